// round 1
// baseline (speedup 1.0000x reference)
#include <cuda_runtime.h>
#include <math.h>
#include <stdint.h>

#define NN_MAX 100000
#define EE_MAX 500000
#define MEMD 128
#define DQKV 384
#define EPS 0.1f
#define GAM 0.1f

// ---------------- scratch (__device__ globals; no allocations allowed) ----------
__device__ float d_h[(size_t)NN_MAX * MEMD];          // 51.2 MB
__device__ float d_qkv[(size_t)NN_MAX * DQKV];        // 153.6 MB
__device__ float d_attr[(size_t)EE_MAX * MEMD];       // 256 MB
__device__ float d_eproj[(size_t)EE_MAX * MEMD];      // 256 MB
__device__ float d_alpha[EE_MAX];                     // 2 MB
__device__ unsigned d_amax[NN_MAX];
__device__ float d_denom[NN_MAX];
__device__ float d_agg[(size_t)NN_MAX * MEMD];        // 51.2 MB
__device__ float d_Wenc_t[256 * 128];
__device__ float d_Wqkv_t[128 * 384];
__device__ float d_bqkv[384];
__device__ float d_We_t[128 * 128];
__device__ float d_Wanti_t[128 * 128];

// monotone float<->uint mapping for atomicMax on floats
__device__ __forceinline__ unsigned fenc(float f) {
    unsigned u = __float_as_uint(f);
    return (u & 0x80000000u) ? ~u : (u | 0x80000000u);
}
__device__ __forceinline__ float fdec(unsigned k) {
    unsigned u = (k & 0x80000000u) ? (k & 0x7FFFFFFFu) : ~k;
    return __uint_as_float(u);
}

// ---------------- weight prep: transposes + concat + antisymmetric build --------
__global__ void prep_kernel(const float* __restrict__ W_enc,
                            const float* __restrict__ Wq, const float* __restrict__ bq,
                            const float* __restrict__ Wk, const float* __restrict__ bk,
                            const float* __restrict__ Wv, const float* __restrict__ bv,
                            const float* __restrict__ We, const float* __restrict__ W_anti) {
    int i = blockIdx.x * blockDim.x + threadIdx.x;
    if (i < 256 * 128) {                       // Wenc_t[k][n] = W_enc[n][k], K=256
        int k = i / 128, n = i % 128;
        d_Wenc_t[i] = W_enc[n * 256 + k];
    }
    if (i < 128 * 384) {                       // Wqkv_t[k][n]
        int k = i / 384, n = i % 384;
        float v;
        if (n < 128) v = Wq[n * 128 + k];
        else if (n < 256) v = Wk[(n - 128) * 128 + k];
        else v = Wv[(n - 256) * 128 + k];
        d_Wqkv_t[i] = v;
    }
    if (i < 384) {
        d_bqkv[i] = (i < 128) ? bq[i] : ((i < 256) ? bk[i - 128] : bv[i - 256]);
    }
    if (i < 128 * 128) {
        int k = i / 128, n = i % 128;
        d_We_t[i] = We[n * 128 + k];
        float a = W_anti[n * 128 + k] - W_anti[k * 128 + n];   // A^T[k][n]
        if (k == n) a -= GAM;
        d_Wanti_t[i] = a;
    }
}

// ---------------- init per-call accumulators ----------------
__global__ void init_kernel(int n_nodes) {
    size_t i = (size_t)blockIdx.x * blockDim.x + threadIdx.x;
    size_t tot = (size_t)n_nodes * MEMD;
    if (i < tot) d_agg[i] = 0.0f;
    if (i < (size_t)n_nodes) {
        d_amax[i] = 0x007FFFFFu;   // fenc(-inf)
        d_denom[i] = 0.0f;
    }
}

// ---------------- generic fp32 tiled GEMM: C = A[MxK] @ B[KxN] (+bias) ----------
// MODE 0: plain (+bias if non-null).  MODE 1: CTAN final epilogue.
template <int MODE>
__global__ __launch_bounds__(256) void sgemm_kernel(
    const float* __restrict__ A, const float* __restrict__ B,
    const float* __restrict__ bias, float* __restrict__ C,
    int M, int N, int K, const float* __restrict__ b_anti) {
    __shared__ float As[8][128];
    __shared__ float Bs[8][128];
    const int t = threadIdx.x;
    const int m0 = blockIdx.y * 128, n0 = blockIdx.x * 128;
    const int lrow = t >> 1, lkp = (t & 1) * 4;   // A loader: row, k-subpart
    const int bkr = t >> 5, bn = (t & 31) * 4;    // B loader: k-row, n
    const int ty = t >> 4, tx = t & 15;

    float c[8][8];
#pragma unroll
    for (int i = 0; i < 8; i++)
#pragma unroll
        for (int j = 0; j < 8; j++) c[i][j] = 0.0f;

    for (int k0 = 0; k0 < K; k0 += 8) {
        float4 a4 = make_float4(0.f, 0.f, 0.f, 0.f);
        int ar = m0 + lrow;
        if (ar < M)
            a4 = *reinterpret_cast<const float4*>(A + (size_t)ar * K + k0 + lkp);
        As[lkp + 0][lrow] = a4.x;
        As[lkp + 1][lrow] = a4.y;
        As[lkp + 2][lrow] = a4.z;
        As[lkp + 3][lrow] = a4.w;
        float4 b4 = *reinterpret_cast<const float4*>(B + (size_t)(k0 + bkr) * N + n0 + bn);
        *reinterpret_cast<float4*>(&Bs[bkr][bn]) = b4;
        __syncthreads();
#pragma unroll
        for (int kk = 0; kk < 8; kk++) {
            float4 ra0 = *reinterpret_cast<const float4*>(&As[kk][ty * 8]);
            float4 ra1 = *reinterpret_cast<const float4*>(&As[kk][ty * 8 + 4]);
            float4 rb0 = *reinterpret_cast<const float4*>(&Bs[kk][tx * 8]);
            float4 rb1 = *reinterpret_cast<const float4*>(&Bs[kk][tx * 8 + 4]);
            float ra[8] = {ra0.x, ra0.y, ra0.z, ra0.w, ra1.x, ra1.y, ra1.z, ra1.w};
            float rb[8] = {rb0.x, rb0.y, rb0.z, rb0.w, rb1.x, rb1.y, rb1.z, rb1.w};
#pragma unroll
            for (int i = 0; i < 8; i++)
#pragma unroll
                for (int j = 0; j < 8; j++) c[i][j] += ra[i] * rb[j];
        }
        __syncthreads();
    }

#pragma unroll
    for (int i = 0; i < 8; i++) {
        int r = m0 + ty * 8 + i;
        if (r >= M) break;
        int nbase = n0 + tx * 8;
        if (MODE == 0) {
            float v[8];
#pragma unroll
            for (int j = 0; j < 8; j++) {
                v[j] = c[i][j];
                if (bias) v[j] += bias[nbase + j];
            }
            float4* cp = reinterpret_cast<float4*>(C + (size_t)r * N + nbase);
            cp[0] = make_float4(v[0], v[1], v[2], v[3]);
            cp[1] = make_float4(v[4], v[5], v[6], v[7]);
        } else {
            float rden = 1.0f / (d_denom[r] + 1e-16f);
            float v[8];
#pragma unroll
            for (int j = 0; j < 8; j++) {
                int n = nbase + j;
                float attn = d_agg[(size_t)r * MEMD + n] * rden;
                float g = tanhf(c[i][j] + attn + b_anti[n]);
                float hv = A[(size_t)r * K + n];   // A is d_h, K == 128
                v[j] = tanhf(hv + EPS * g);
            }
            float4* cp = reinterpret_cast<float4*>(C + (size_t)r * N + nbase);
            cp[0] = make_float4(v[0], v[1], v[2], v[3]);
            cp[1] = make_float4(v[4], v[5], v[6], v[7]);
        }
    }
}

// ---------------- edge_attr = [msg | cos(|lu[src]-t| * w_time + b_time)] --------
__global__ void attr_kernel(const int* __restrict__ src,
                            const float* __restrict__ last_update,
                            const float* __restrict__ tarr,
                            const float* __restrict__ msg,
                            const float* __restrict__ w_time,
                            const float* __restrict__ b_time, int E) {
    size_t i = (size_t)blockIdx.x * blockDim.x + threadIdx.x;
    if (i >= (size_t)E * MEMD) return;
    int col = (int)(i & 127);
    size_t e = i >> 7;
    float v;
    if (col < 64) {
        v = msg[e * 64 + col];
    } else {
        float rel = fabsf(last_update[src[e]] - tarr[e]);
        int j = col - 64;
        v = cosf(rel * w_time[j] + b_time[j]);
    }
    d_attr[i] = v;
}

// ---------------- pass 1: alpha per edge + segment max -------------------------
__global__ void alpha_kernel(const int* __restrict__ src, const int* __restrict__ dst,
                             int E) {
    int w = (int)(((size_t)blockIdx.x * blockDim.x + threadIdx.x) >> 5);
    int lane = threadIdx.x & 31;
    if (w >= E) return;
    int s = src[w], d = dst[w];
    float4 qv = *reinterpret_cast<const float4*>(d_qkv + (size_t)d * DQKV + lane * 4);
    float4 kv = *reinterpret_cast<const float4*>(d_qkv + (size_t)s * DQKV + 128 + lane * 4);
    float4 ev = *reinterpret_cast<const float4*>(d_eproj + (size_t)w * MEMD + lane * 4);
    float p = qv.x * (kv.x + ev.x) + qv.y * (kv.y + ev.y) +
              qv.z * (kv.z + ev.z) + qv.w * (kv.w + ev.w);
#pragma unroll
    for (int o = 16; o; o >>= 1) p += __shfl_xor_sync(0xFFFFFFFFu, p, o);
    if (lane == 0) {
        float a = p * 0.08838834764831845f;   // 1/sqrt(128)
        d_alpha[w] = a;
        atomicMax(&d_amax[d], fenc(a));
    }
}

// ---------------- pass 2: scatter exp-weighted values --------------------------
__global__ void scatter_kernel(const int* __restrict__ src, const int* __restrict__ dst,
                               int E) {
    int w = (int)(((size_t)blockIdx.x * blockDim.x + threadIdx.x) >> 5);
    int lane = threadIdx.x & 31;
    if (w >= E) return;
    int s = src[w], d = dst[w];
    float m = fdec(d_amax[d]);
    float ex = expf(d_alpha[w] - m);
    float4 vv = *reinterpret_cast<const float4*>(d_qkv + (size_t)s * DQKV + 256 + lane * 4);
    float4 ev = *reinterpret_cast<const float4*>(d_eproj + (size_t)w * MEMD + lane * 4);
    float rx = ex * (vv.x + ev.x);
    float ry = ex * (vv.y + ev.y);
    float rz = ex * (vv.z + ev.z);
    float rw = ex * (vv.w + ev.w);
    float* p = d_agg + (size_t)d * MEMD + lane * 4;
    asm volatile("red.global.add.v4.f32 [%0], {%1,%2,%3,%4};"
                 :: "l"(p), "f"(rx), "f"(ry), "f"(rz), "f"(rw)
                 : "memory");
    if (lane == 0) atomicAdd(&d_denom[d], ex);
}

// ---------------- launch ----------------
extern "C" void kernel_launch(void* const* d_in, const int* in_sizes, int n_in,
                              void* d_out, int out_size) {
    const float* x           = (const float*)d_in[0];
    const float* last_update = (const float*)d_in[1];
    const int*   edge_index  = (const int*)d_in[2];
    const float* t           = (const float*)d_in[3];
    const float* msg         = (const float*)d_in[4];
    const float* w_time      = (const float*)d_in[5];
    const float* b_time      = (const float*)d_in[6];
    const float* W_enc       = (const float*)d_in[7];
    const float* b_enc       = (const float*)d_in[8];
    const float* Wq          = (const float*)d_in[9];
    const float* bq          = (const float*)d_in[10];
    const float* Wk          = (const float*)d_in[11];
    const float* bk          = (const float*)d_in[12];
    const float* Wv          = (const float*)d_in[13];
    const float* bv          = (const float*)d_in[14];
    const float* We          = (const float*)d_in[15];
    const float* W_anti      = (const float*)d_in[16];
    const float* b_anti      = (const float*)d_in[17];

    int Nn = in_sizes[1];              // last_update: N
    int Ei = in_sizes[3];              // t: E
    const int* src = edge_index;
    const int* dst = edge_index + Ei;

    float *h_p, *qkv_p, *attr_p, *eproj_p, *Wenc_p, *Wqkv_p, *bqkv_p, *We_p, *Want_p;
    cudaGetSymbolAddress((void**)&h_p, d_h);
    cudaGetSymbolAddress((void**)&qkv_p, d_qkv);
    cudaGetSymbolAddress((void**)&attr_p, d_attr);
    cudaGetSymbolAddress((void**)&eproj_p, d_eproj);
    cudaGetSymbolAddress((void**)&Wenc_p, d_Wenc_t);
    cudaGetSymbolAddress((void**)&Wqkv_p, d_Wqkv_t);
    cudaGetSymbolAddress((void**)&bqkv_p, d_bqkv);
    cudaGetSymbolAddress((void**)&We_p, d_We_t);
    cudaGetSymbolAddress((void**)&Want_p, d_Wanti_t);

    // 1) weight prep + accumulator init
    prep_kernel<<<(128 * 384 + 255) / 256, 256>>>(W_enc, Wq, bq, Wk, bk, Wv, bv, We, W_anti);
    init_kernel<<<(int)(((size_t)Nn * MEMD + 255) / 256), 256>>>(Nn);

    // 2) h = x @ W_enc^T + b_enc        [N,256]x[256,128]
    {
        dim3 g(1, (Nn + 127) / 128);
        sgemm_kernel<0><<<g, 256>>>(x, Wenc_p, b_enc, h_p, Nn, 128, 256, nullptr);
    }
    // 3) QKV = h @ [Wq|Wk|Wv]^T + b     [N,128]x[128,384]
    {
        dim3 g(3, (Nn + 127) / 128);
        sgemm_kernel<0><<<g, 256>>>(h_p, Wqkv_p, bqkv_p, qkv_p, Nn, DQKV, 128, nullptr);
    }
    // 4) edge_attr
    attr_kernel<<<(int)(((size_t)Ei * MEMD + 255) / 256), 256>>>(src, last_update, t, msg,
                                                                 w_time, b_time, Ei);
    // 5) e_proj = edge_attr @ We^T       [E,128]x[128,128]
    {
        dim3 g(1, (Ei + 127) / 128);
        sgemm_kernel<0><<<g, 256>>>(attr_p, We_p, nullptr, eproj_p, Ei, 128, 128, nullptr);
    }
    // 6) alpha + segment max
    alpha_kernel<<<(Ei + 7) / 8, 256>>>(src, dst, Ei);
    // 7) scatter ex * (v + e_proj) and denom
    scatter_kernel<<<(Ei + 7) / 8, 256>>>(src, dst, Ei);
    // 8) final: C = h @ A^T, epilogue tanh(h + eps*tanh(C + agg/den + b_anti))
    {
        dim3 g(1, (Nn + 127) / 128);
        sgemm_kernel<1><<<g, 256>>>(h_p, Want_p, nullptr, (float*)d_out, Nn, 128, 128, b_anti);
    }
}

// round 5
// speedup vs baseline: 1.4382x; 1.4382x over previous
#include <cuda_runtime.h>
#include <cuda_bf16.h>
#include <math.h>
#include <stdint.h>

#define NN_MAX 100000
#define EE_MAX 500000
#define MEMD 128
#define DQKV 384
#define EPS 0.1f
#define GAM 0.1f

// weight-cat offsets (elements) in the bf16 hi/lo weight store, all [N,K] K-major
#define OFF_ENC 0          // [128,256]
#define OFF_QKV 32768      // [384,128]
#define OFF_WE 81920       // [128,128]
#define OFF_ANTI 98304     // [128,128]
#define W_TOTAL 114688

#define LDT 72                          // padded SMEM row pitch in bf16 (144B, conflict-free)
#define TILE_ELEMS (128 * LDT)          // per buffer
#define SMEM_BYTES (4 * TILE_ELEMS * 2) // Ahi, Alo, Bhi, Blo = 73728 B

// ---------------- scratch (__device__ globals) ----------------
__device__ float d_h[(size_t)NN_MAX * MEMD];
__device__ float d_qkv[(size_t)NN_MAX * DQKV];
__device__ float d_eproj[(size_t)EE_MAX * MEMD];
__device__ float d_alpha[EE_MAX];
__device__ unsigned d_amax[NN_MAX];
__device__ float d_denom[NN_MAX];
__device__ float d_agg[(size_t)NN_MAX * MEMD];
__device__ __nv_bfloat16 d_whi[W_TOTAL];
__device__ __nv_bfloat16 d_wlo[W_TOTAL];
__device__ float d_bqkv[DQKV];

// ---------------- PTX helpers (arch-neutral: ldmatrix + mma.sync) -------------
__device__ __forceinline__ uint32_t smem_u32(const void* p) {
    uint32_t a;
    asm("{ .reg .u64 t; cvta.to.shared.u64 t, %1; cvt.u32.u64 %0, t; }" : "=r"(a) : "l"(p));
    return a;
}
__device__ __forceinline__ void ldm_x4(uint32_t* r, uint32_t addr) {
    asm volatile("ldmatrix.sync.aligned.m8n8.x4.shared.b16 {%0,%1,%2,%3}, [%4];"
                 : "=r"(r[0]), "=r"(r[1]), "=r"(r[2]), "=r"(r[3]) : "r"(addr));
}
__device__ __forceinline__ void mma_bf16(float* c, const uint32_t* a, const uint32_t* b) {
    asm volatile(
        "mma.sync.aligned.m16n8k16.row.col.f32.bf16.bf16.f32 "
        "{%0,%1,%2,%3}, {%4,%5,%6,%7}, {%8,%9}, {%0,%1,%2,%3};"
        : "+f"(c[0]), "+f"(c[1]), "+f"(c[2]), "+f"(c[3])
        : "r"(a[0]), "r"(a[1]), "r"(a[2]), "r"(a[3]), "r"(b[0]), "r"(b[1]));
}

// monotone float<->uint mapping for atomicMax on floats
__device__ __forceinline__ unsigned fenc(float f) {
    unsigned u = __float_as_uint(f);
    return (u & 0x80000000u) ? ~u : (u | 0x80000000u);
}
__device__ __forceinline__ float fdec(unsigned k) {
    unsigned u = (k & 0x80000000u) ? (k & 0x7FFFFFFFu) : ~k;
    return __uint_as_float(u);
}

// ---------------- weight prep: bf16 hi/lo split of all B operands -------------
__device__ __forceinline__ void split_store(int idx, float v) {
    __nv_bfloat16 hi = __float2bfloat16(v);
    __nv_bfloat16 lo = __float2bfloat16(v - __bfloat162float(hi));
    d_whi[idx] = hi;
    d_wlo[idx] = lo;
}
__global__ void prep_kernel(const float* __restrict__ W_enc,
                            const float* __restrict__ Wq, const float* __restrict__ bq,
                            const float* __restrict__ Wk, const float* __restrict__ bk,
                            const float* __restrict__ Wv, const float* __restrict__ bv,
                            const float* __restrict__ We, const float* __restrict__ W_anti) {
    int i = blockIdx.x * blockDim.x + threadIdx.x;
    if (i < 32768) {
        split_store(OFF_ENC + i, W_enc[i]);               // [128,256] direct
    } else if (i < 81920) {
        int j = i - 32768;
        int n = j / 128, k = j % 128;
        float v;
        if (n < 128) v = Wq[n * 128 + k];
        else if (n < 256) v = Wk[(n - 128) * 128 + k];
        else v = Wv[(n - 256) * 128 + k];
        split_store(OFF_QKV + j, v);
    } else if (i < 98304) {
        int j = i - 81920;
        split_store(OFF_WE + j, We[j]);                   // [128,128] direct
    } else if (i < W_TOTAL) {
        int j = i - 98304;
        int n = j / 128, k = j % 128;
        float v = W_anti[n * 128 + k] - W_anti[k * 128 + n];
        if (n == k) v -= GAM;
        split_store(OFF_ANTI + j, v);
    }
    if (i < DQKV)
        d_bqkv[i] = (i < 128) ? bq[i] : ((i < 256) ? bk[i - 128] : bv[i - 256]);
}

// ---------------- init per-call accumulators ----------------
__global__ void init_kernel(int n_nodes) {
    size_t i = (size_t)blockIdx.x * blockDim.x + threadIdx.x;
    if (i < (size_t)n_nodes * MEMD) d_agg[i] = 0.0f;
    if (i < (size_t)n_nodes) {
        d_amax[i] = 0x007FFFFFu;  // fenc(-inf)
        d_denom[i] = 0.0f;
    }
}

// ---------------- warp-MMA GEMM: C[128-blk, 128-blk] = A @ W^T, bf16 hi/lo ----
// AMODE 0: A fp32 [M,lda].  AMODE 1: A = [msg | cos-time-enc] built on the fly.
// EPI 0: C = D (+bias).     EPI 1: CTAN final epilogue.
// 8 warps: warp (wm = wid&3, wn = wid>>2) owns rows wm*32..+31, cols wn*64..+63.
template <int AMODE, int EPI>
__global__ void __launch_bounds__(256) mma_gemm(
    const float* __restrict__ A, int lda, int K, int nch,
    const __nv_bfloat16* __restrict__ Bh, const __nv_bfloat16* __restrict__ Bl,
    const float* __restrict__ bias, float* __restrict__ C, int ldc, int M,
    const int* __restrict__ esrc, const float* __restrict__ lu,
    const float* __restrict__ tar, const float* __restrict__ wt,
    const float* __restrict__ bt,
    const float* __restrict__ b_anti, const float* __restrict__ hres) {
    const int t = threadIdx.x;
    const int lane = t & 31, wid = t >> 5;
    const int wm = wid & 3, wn = wid >> 2;
    const size_t m0 = (size_t)blockIdx.y * 128;
    const int col0 = blockIdx.x * 128;
    const __nv_bfloat16* Bhp = Bh + (size_t)col0 * K;
    const __nv_bfloat16* Blp = Bl + (size_t)col0 * K;

    extern __shared__ __nv_bfloat16 smem[];
    uint32_t sbase = smem_u32(smem);
    const uint32_t oAhi = 0;
    const uint32_t oAlo = TILE_ELEMS * 2;
    const uint32_t oBhi = 2 * TILE_ELEMS * 2;
    const uint32_t oBlo = 3 * TILE_ELEMS * 2;

    float acc[2][8][4];
#pragma unroll
    for (int i = 0; i < 2; i++)
#pragma unroll
        for (int j = 0; j < 8; j++)
#pragma unroll
            for (int e = 0; e < 4; e++) acc[i][j][e] = 0.0f;

    const int tr = t >> 1;            // loader row 0..127
    const int tcc = (t & 1) * 32;     // loader 32-col slab
    const size_t row = m0 + tr;
    const bool valid = row < (size_t)M;

    for (int c = 0; c < nch; c++) {
        const int kc = c * 64;
        // ---- stage A (fp32 -> bf16 hi/lo) ----
        float rel = 0.0f;
        if (AMODE == 1 && kc != 0 && valid)
            rel = fabsf(lu[esrc[row]] - tar[row]);
#pragma unroll
        for (int g = 0; g < 8; g++) {
            float4 v = make_float4(0.f, 0.f, 0.f, 0.f);
            if (valid) {
                if (AMODE == 0) {
                    v = *reinterpret_cast<const float4*>(A + row * lda + kc + tcc + g * 4);
                } else if (kc == 0) {
                    v = *reinterpret_cast<const float4*>(A + row * 64 + tcc + g * 4);
                } else {
                    int cb = tcc + g * 4;
                    v.x = cosf(rel * wt[cb + 0] + bt[cb + 0]);
                    v.y = cosf(rel * wt[cb + 1] + bt[cb + 1]);
                    v.z = cosf(rel * wt[cb + 2] + bt[cb + 2]);
                    v.w = cosf(rel * wt[cb + 3] + bt[cb + 3]);
                }
            }
            __nv_bfloat162 h0 = __floats2bfloat162_rn(v.x, v.y);
            __nv_bfloat162 h1 = __floats2bfloat162_rn(v.z, v.w);
            float2 f0 = __bfloat1622float2(h0);
            float2 f1 = __bfloat1622float2(h1);
            __nv_bfloat162 l0 = __floats2bfloat162_rn(v.x - f0.x, v.y - f0.y);
            __nv_bfloat162 l1 = __floats2bfloat162_rn(v.z - f1.x, v.w - f1.y);
            int idx = tr * LDT + tcc + g * 4;
            *reinterpret_cast<uint2*>(smem + idx) =
                make_uint2(*reinterpret_cast<unsigned*>(&h0), *reinterpret_cast<unsigned*>(&h1));
            *reinterpret_cast<uint2*>(smem + TILE_ELEMS + idx) =
                make_uint2(*reinterpret_cast<unsigned*>(&l0), *reinterpret_cast<unsigned*>(&l1));
        }
        // ---- stage B (weights, already bf16 hi/lo) ----
        {
            const __nv_bfloat16* bh = Bhp + (size_t)tr * K + kc + tcc;
            const __nv_bfloat16* bl = Blp + (size_t)tr * K + kc + tcc;
#pragma unroll
            for (int g = 0; g < 4; g++) {
                uint4 uh = *reinterpret_cast<const uint4*>(bh + g * 8);
                uint4 ul = *reinterpret_cast<const uint4*>(bl + g * 8);
                int idx = tr * LDT + tcc + g * 8;
                *reinterpret_cast<uint4*>(smem + 2 * TILE_ELEMS + idx) = uh;
                *reinterpret_cast<uint4*>(smem + 3 * TILE_ELEMS + idx) = ul;
            }
        }
        __syncthreads();
        // ---- compute: 4 k-steps of 16 ----
#pragma unroll
        for (int ks = 0; ks < 4; ks++) {
            const int k0 = ks * 16;
            uint32_t ah[2][4], al[2][4];
#pragma unroll
            for (int mi = 0; mi < 2; mi++) {
                uint32_t ao =
                    ((wm * 32 + mi * 16 + (lane & 15)) * LDT + k0 + ((lane >> 4) << 3)) * 2;
                ldm_x4(ah[mi], sbase + oAhi + ao);
                ldm_x4(al[mi], sbase + oAlo + ao);
            }
            uint32_t bhf[4][4], blf[4][4];
#pragma unroll
            for (int nj = 0; nj < 4; nj++) {
                int bn = wn * 64 + nj * 16 + (lane & 7) + ((lane >> 4) << 3);
                uint32_t bo = (bn * LDT + k0 + (((lane >> 3) & 1) << 3)) * 2;
                ldm_x4(bhf[nj], sbase + oBhi + bo);
                ldm_x4(blf[nj], sbase + oBlo + bo);
            }
#pragma unroll
            for (int mi = 0; mi < 2; mi++)
#pragma unroll
                for (int j = 0; j < 8; j++) {
                    const uint32_t* bh2 = &bhf[j >> 1][(j & 1) * 2];
                    const uint32_t* bl2 = &blf[j >> 1][(j & 1) * 2];
                    mma_bf16(acc[mi][j], ah[mi], bh2);
                    mma_bf16(acc[mi][j], ah[mi], bl2);
                    mma_bf16(acc[mi][j], al[mi], bh2);
                }
        }
        __syncthreads();
    }

    // ---- epilogue: fragment (mi,j): rows wm*32+mi*16+(lane>>2)+{0,8}, cols wn*64+j*8+(lane&3)*2
#pragma unroll
    for (int mi = 0; mi < 2; mi++) {
#pragma unroll
        for (int e = 0; e < 2; e++) {
            size_t r = m0 + wm * 32 + mi * 16 + (lane >> 2) + e * 8;
            if (r >= (size_t)M) continue;
            float rden = 0.0f;
            if (EPI == 1) rden = 1.0f / (d_denom[r] + 1e-16f);
#pragma unroll
            for (int j = 0; j < 8; j++) {
                int n = wn * 64 + j * 8 + (lane & 3) * 2;
                float v0 = acc[mi][j][e * 2 + 0];
                float v1 = acc[mi][j][e * 2 + 1];
                if (EPI == 0) {
                    if (bias) {
                        v0 += bias[col0 + n];
                        v1 += bias[col0 + n + 1];
                    }
                } else {
                    float g0 = tanhf(v0 + d_agg[r * MEMD + n] * rden + b_anti[n]);
                    float g1 = tanhf(v1 + d_agg[r * MEMD + n + 1] * rden + b_anti[n + 1]);
                    v0 = tanhf(hres[r * MEMD + n] + EPS * g0);
                    v1 = tanhf(hres[r * MEMD + n + 1] + EPS * g1);
                }
                *reinterpret_cast<float2*>(C + r * ldc + col0 + n) = make_float2(v0, v1);
            }
        }
    }
}

// ---------------- pass 1: alpha per edge + segment max -------------------------
__global__ void alpha_kernel(const int* __restrict__ src, const int* __restrict__ dst,
                             int E) {
    int w = (int)(((size_t)blockIdx.x * blockDim.x + threadIdx.x) >> 5);
    int lane = threadIdx.x & 31;
    if (w >= E) return;
    int s = src[w], d = dst[w];
    float4 qv = *reinterpret_cast<const float4*>(d_qkv + (size_t)d * DQKV + lane * 4);
    float4 kv = *reinterpret_cast<const float4*>(d_qkv + (size_t)s * DQKV + 128 + lane * 4);
    float4 ev = *reinterpret_cast<const float4*>(d_eproj + (size_t)w * MEMD + lane * 4);
    float p = qv.x * (kv.x + ev.x) + qv.y * (kv.y + ev.y) +
              qv.z * (kv.z + ev.z) + qv.w * (kv.w + ev.w);
#pragma unroll
    for (int o = 16; o; o >>= 1) p += __shfl_xor_sync(0xFFFFFFFFu, p, o);
    if (lane == 0) {
        float a = p * 0.08838834764831845f;  // 1/sqrt(128)
        d_alpha[w] = a;
        atomicMax(&d_amax[d], fenc(a));
    }
}

// ---------------- pass 2: scatter exp-weighted values --------------------------
__global__ void scatter_kernel(const int* __restrict__ src, const int* __restrict__ dst,
                               int E) {
    int w = (int)(((size_t)blockIdx.x * blockDim.x + threadIdx.x) >> 5);
    int lane = threadIdx.x & 31;
    if (w >= E) return;
    int s = src[w], d = dst[w];
    float m = fdec(d_amax[d]);
    float ex = expf(d_alpha[w] - m);
    float4 vv = *reinterpret_cast<const float4*>(d_qkv + (size_t)s * DQKV + 256 + lane * 4);
    float4 ev = *reinterpret_cast<const float4*>(d_eproj + (size_t)w * MEMD + lane * 4);
    float rx = ex * (vv.x + ev.x);
    float ry = ex * (vv.y + ev.y);
    float rz = ex * (vv.z + ev.z);
    float rw = ex * (vv.w + ev.w);
    float* p = d_agg + (size_t)d * MEMD + lane * 4;
    asm volatile("red.global.add.v4.f32 [%0], {%1,%2,%3,%4};"
                 :: "l"(p), "f"(rx), "f"(ry), "f"(rz), "f"(rw)
                 : "memory");
    if (lane == 0) atomicAdd(&d_denom[d], ex);
}

// ---------------- launch ----------------
extern "C" void kernel_launch(void* const* d_in, const int* in_sizes, int n_in,
                              void* d_out, int out_size) {
    const float* x           = (const float*)d_in[0];
    const float* last_update = (const float*)d_in[1];
    const int*   edge_index  = (const int*)d_in[2];
    const float* t           = (const float*)d_in[3];
    const float* msg         = (const float*)d_in[4];
    const float* w_time      = (const float*)d_in[5];
    const float* b_time      = (const float*)d_in[6];
    const float* W_enc       = (const float*)d_in[7];
    const float* b_enc       = (const float*)d_in[8];
    const float* Wq          = (const float*)d_in[9];
    const float* bq          = (const float*)d_in[10];
    const float* Wk          = (const float*)d_in[11];
    const float* bk          = (const float*)d_in[12];
    const float* Wv          = (const float*)d_in[13];
    const float* bv          = (const float*)d_in[14];
    const float* We          = (const float*)d_in[15];
    const float* W_anti      = (const float*)d_in[16];
    const float* b_anti      = (const float*)d_in[17];

    int Nn = in_sizes[1];
    int Ei = in_sizes[3];
    const int* src = edge_index;
    const int* dst = edge_index + Ei;

    float *h_p, *qkv_p, *eproj_p, *bqkv_p;
    __nv_bfloat16 *whi_p, *wlo_p;
    cudaGetSymbolAddress((void**)&h_p, d_h);
    cudaGetSymbolAddress((void**)&qkv_p, d_qkv);
    cudaGetSymbolAddress((void**)&eproj_p, d_eproj);
    cudaGetSymbolAddress((void**)&bqkv_p, d_bqkv);
    cudaGetSymbolAddress((void**)&whi_p, d_whi);
    cudaGetSymbolAddress((void**)&wlo_p, d_wlo);

    cudaFuncSetAttribute(mma_gemm<0, 0>, cudaFuncAttributeMaxDynamicSharedMemorySize, SMEM_BYTES);
    cudaFuncSetAttribute(mma_gemm<1, 0>, cudaFuncAttributeMaxDynamicSharedMemorySize, SMEM_BYTES);
    cudaFuncSetAttribute(mma_gemm<0, 1>, cudaFuncAttributeMaxDynamicSharedMemorySize, SMEM_BYTES);

    int nblk = (Nn + 127) / 128;
    int eblk = (Ei + 127) / 128;

    prep_kernel<<<(W_TOTAL + 255) / 256, 256>>>(W_enc, Wq, bq, Wk, bk, Wv, bv, We, W_anti);
    init_kernel<<<(int)(((size_t)Nn * MEMD + 255) / 256), 256>>>(Nn);

    // h = x @ W_enc^T + b_enc        [N,256]x[256,128]
    mma_gemm<0, 0><<<dim3(1, nblk), 256, SMEM_BYTES>>>(
        x, 256, 256, 4, whi_p + OFF_ENC, wlo_p + OFF_ENC, b_enc, h_p, 128, Nn,
        nullptr, nullptr, nullptr, nullptr, nullptr, nullptr, nullptr);
    // QKV = h @ [Wq|Wk|Wv]^T + b     [N,128]x[128,384]
    mma_gemm<0, 0><<<dim3(3, nblk), 256, SMEM_BYTES>>>(
        h_p, 128, 128, 2, whi_p + OFF_QKV, wlo_p + OFF_QKV, bqkv_p, qkv_p, DQKV, Nn,
        nullptr, nullptr, nullptr, nullptr, nullptr, nullptr, nullptr);
    // e_proj = [msg | time_enc] @ We^T  (edge_attr built in-kernel)
    mma_gemm<1, 0><<<dim3(1, eblk), 256, SMEM_BYTES>>>(
        msg, 64, 128, 2, whi_p + OFF_WE, wlo_p + OFF_WE, nullptr, eproj_p, 128, Ei,
        src, last_update, t, w_time, b_time, nullptr, nullptr);
    // attention passes
    alpha_kernel<<<(Ei + 7) / 8, 256>>>(src, dst, Ei);
    scatter_kernel<<<(Ei + 7) / 8, 256>>>(src, dst, Ei);
    // final: D = h @ A^T, epilogue tanh(h + eps*tanh(D + agg/den + b_anti))
    mma_gemm<0, 1><<<dim3(1, nblk), 256, SMEM_BYTES>>>(
        h_p, 128, 128, 2, whi_p + OFF_ANTI, wlo_p + OFF_ANTI, nullptr, (float*)d_out, 128, Nn,
        nullptr, nullptr, nullptr, nullptr, nullptr, b_anti, h_p);
}

// round 7
// speedup vs baseline: 1.8507x; 1.2868x over previous
#include <cuda_runtime.h>
#include <cuda_bf16.h>
#include <math.h>
#include <stdint.h>

#define NN_MAX 100000
#define EE_MAX 500000
#define MEMD 128
#define DQKV 384
#define EPS 0.1f
#define GAM 0.1f

// weight-cat offsets (elements) in the bf16 hi/lo weight store, all [N,K] K-major
#define OFF_ENC 0          // [128,256]
#define OFF_QKV 32768      // [384,128]
#define OFF_WE 81920       // [128,128]
#define OFF_ANTI 98304     // [128,128]
#define W_TOTAL 114688

#define LDT 72                          // padded SMEM row pitch in bf16 (144B, conflict-free)
#define TILE_ELEMS (128 * LDT)          // per buffer
#define SMEM_BYTES (4 * TILE_ELEMS * 2) // Ahi, Alo, Bhi, Blo = 73728 B

// ---------------- scratch (__device__ globals) ----------------
__device__ float d_h[(size_t)NN_MAX * MEMD];
__device__ float d_qkv[(size_t)NN_MAX * DQKV];
__device__ float d_eproj[(size_t)EE_MAX * MEMD];
__device__ float d_denom[NN_MAX];
__device__ float d_agg[(size_t)NN_MAX * MEMD];
__device__ __nv_bfloat16 d_whi[W_TOTAL];
__device__ __nv_bfloat16 d_wlo[W_TOTAL];
__device__ float d_bqkv[DQKV];

// ---------------- PTX helpers (arch-neutral: ldmatrix + mma.sync + cp.async) --
__device__ __forceinline__ uint32_t smem_u32(const void* p) {
    uint32_t a;
    asm("{ .reg .u64 t; cvta.to.shared.u64 t, %1; cvt.u32.u64 %0, t; }" : "=r"(a) : "l"(p));
    return a;
}
__device__ __forceinline__ void ldm_x4(uint32_t* r, uint32_t addr) {
    asm volatile("ldmatrix.sync.aligned.m8n8.x4.shared.b16 {%0,%1,%2,%3}, [%4];"
                 : "=r"(r[0]), "=r"(r[1]), "=r"(r[2]), "=r"(r[3]) : "r"(addr));
}
__device__ __forceinline__ void mma_bf16(float* c, const uint32_t* a, const uint32_t* b) {
    asm volatile(
        "mma.sync.aligned.m16n8k16.row.col.f32.bf16.bf16.f32 "
        "{%0,%1,%2,%3}, {%4,%5,%6,%7}, {%8,%9}, {%0,%1,%2,%3};"
        : "+f"(c[0]), "+f"(c[1]), "+f"(c[2]), "+f"(c[3])
        : "r"(a[0]), "r"(a[1]), "r"(a[2]), "r"(a[3]), "r"(b[0]), "r"(b[1]));
}
__device__ __forceinline__ void cp16(uint32_t saddr, const void* gaddr) {
    asm volatile("cp.async.ca.shared.global [%0], [%1], 16;" :: "r"(saddr), "l"(gaddr));
}
__device__ __forceinline__ void cp_commit_wait() {
    asm volatile("cp.async.commit_group;");
    asm volatile("cp.async.wait_group 0;");
}

// ---------------- weight prep: bf16 hi/lo split of all B operands -------------
__device__ __forceinline__ void split_store(int idx, float v) {
    __nv_bfloat16 hi = __float2bfloat16(v);
    __nv_bfloat16 lo = __float2bfloat16(v - __bfloat162float(hi));
    d_whi[idx] = hi;
    d_wlo[idx] = lo;
}
__global__ void prep_kernel(const float* __restrict__ W_enc,
                            const float* __restrict__ Wq, const float* __restrict__ bq,
                            const float* __restrict__ Wk, const float* __restrict__ bk,
                            const float* __restrict__ Wv, const float* __restrict__ bv,
                            const float* __restrict__ We, const float* __restrict__ W_anti) {
    int i = blockIdx.x * blockDim.x + threadIdx.x;
    if (i < 32768) {
        split_store(OFF_ENC + i, W_enc[i]);               // [128,256] direct
    } else if (i < 81920) {
        int j = i - 32768;
        int n = j / 128, k = j % 128;
        float v;
        if (n < 128) v = Wq[n * 128 + k];
        else if (n < 256) v = Wk[(n - 128) * 128 + k];
        else v = Wv[(n - 256) * 128 + k];
        split_store(OFF_QKV + j, v);
    } else if (i < 98304) {
        int j = i - 81920;
        split_store(OFF_WE + j, We[j]);                   // [128,128] direct
    } else if (i < W_TOTAL) {
        int j = i - 98304;
        int n = j / 128, k = j % 128;
        float v = W_anti[n * 128 + k] - W_anti[k * 128 + n];
        if (n == k) v -= GAM;
        split_store(OFF_ANTI + j, v);
    }
    if (i < DQKV)
        d_bqkv[i] = (i < 128) ? bq[i] : ((i < 256) ? bk[i - 128] : bv[i - 256]);
}

// ---------------- init per-call accumulators ----------------
__global__ void init_kernel(int n_nodes) {
    size_t i = (size_t)blockIdx.x * blockDim.x + threadIdx.x;
    if (i < (size_t)n_nodes * MEMD) d_agg[i] = 0.0f;
    if (i < (size_t)n_nodes) d_denom[i] = 0.0f;
}

// ---------------- warp-MMA GEMM: C[128-blk, 128-blk] = A @ W^T, bf16 hi/lo ----
// AMODE 0: A fp32 [M,lda].  AMODE 1: A = [msg | cos-time-enc] built on the fly.
// EPI 0: C = D (+bias).     EPI 1: CTAN final epilogue.
// 8 warps: warp (wm = wid&3, wn = wid>>2) owns rows wm*32..+31, cols wn*64..+63.
template <int AMODE, int EPI>
__global__ void __launch_bounds__(256, 2) mma_gemm(
    const float* __restrict__ A, int lda, int K, int nch,
    const __nv_bfloat16* __restrict__ Bh, const __nv_bfloat16* __restrict__ Bl,
    const float* __restrict__ bias, float* __restrict__ C, int ldc, int M,
    const int* __restrict__ esrc, const float* __restrict__ lu,
    const float* __restrict__ tar, const float* __restrict__ wt,
    const float* __restrict__ bt,
    const float* __restrict__ b_anti, const float* __restrict__ hres) {
    const int t = threadIdx.x;
    const int lane = t & 31, wid = t >> 5;
    const int wm = wid & 3, wn = wid >> 2;
    const size_t m0 = (size_t)blockIdx.y * 128;
    const int col0 = blockIdx.x * 128;
    const __nv_bfloat16* Bhp = Bh + (size_t)col0 * K;
    const __nv_bfloat16* Blp = Bl + (size_t)col0 * K;

    extern __shared__ __nv_bfloat16 smem[];
    uint32_t sbase = smem_u32(smem);
    const uint32_t oAhi = 0;
    const uint32_t oAlo = TILE_ELEMS * 2;
    const uint32_t oBhi = 2 * TILE_ELEMS * 2;
    const uint32_t oBlo = 3 * TILE_ELEMS * 2;

    float acc[2][8][4];
#pragma unroll
    for (int i = 0; i < 2; i++)
#pragma unroll
        for (int j = 0; j < 8; j++)
#pragma unroll
            for (int e = 0; e < 4; e++) acc[i][j][e] = 0.0f;

    const int tr = t >> 1;            // loader row 0..127
    const int tcc = (t & 1) * 32;     // loader 32-col slab
    const size_t row = m0 + tr;
    const bool valid = row < (size_t)M;

    for (int c = 0; c < nch; c++) {
        const int kc = c * 64;
        // ---- stage B via cp.async first (overlaps with A conversion below) ----
        {
            const __nv_bfloat16* bh = Bhp + (size_t)tr * K + kc + tcc;
            const __nv_bfloat16* bl = Blp + (size_t)tr * K + kc + tcc;
#pragma unroll
            for (int g = 0; g < 4; g++) {
                uint32_t so = (tr * LDT + tcc + g * 8) * 2;
                cp16(sbase + oBhi + so, bh + g * 8);
                cp16(sbase + oBlo + so, bl + g * 8);
            }
        }
        // ---- stage A (fp32 -> bf16 hi/lo) ----
        float rel = 0.0f;
        if (AMODE == 1 && kc != 0 && valid)
            rel = fabsf(lu[esrc[row]] - tar[row]);
#pragma unroll
        for (int g = 0; g < 8; g++) {
            float4 v = make_float4(0.f, 0.f, 0.f, 0.f);
            if (valid) {
                if (AMODE == 0) {
                    v = *reinterpret_cast<const float4*>(A + row * lda + kc + tcc + g * 4);
                } else if (kc == 0) {
                    v = *reinterpret_cast<const float4*>(A + row * 64 + tcc + g * 4);
                } else {
                    int cb = tcc + g * 4;
                    v.x = cosf(rel * wt[cb + 0] + bt[cb + 0]);
                    v.y = cosf(rel * wt[cb + 1] + bt[cb + 1]);
                    v.z = cosf(rel * wt[cb + 2] + bt[cb + 2]);
                    v.w = cosf(rel * wt[cb + 3] + bt[cb + 3]);
                }
            }
            __nv_bfloat162 h0 = __floats2bfloat162_rn(v.x, v.y);
            __nv_bfloat162 h1 = __floats2bfloat162_rn(v.z, v.w);
            float2 f0 = __bfloat1622float2(h0);
            float2 f1 = __bfloat1622float2(h1);
            __nv_bfloat162 l0 = __floats2bfloat162_rn(v.x - f0.x, v.y - f0.y);
            __nv_bfloat162 l1 = __floats2bfloat162_rn(v.z - f1.x, v.w - f1.y);
            int idx = tr * LDT + tcc + g * 4;
            *reinterpret_cast<uint2*>(smem + idx) =
                make_uint2(*reinterpret_cast<unsigned*>(&h0), *reinterpret_cast<unsigned*>(&h1));
            *reinterpret_cast<uint2*>(smem + TILE_ELEMS + idx) =
                make_uint2(*reinterpret_cast<unsigned*>(&l0), *reinterpret_cast<unsigned*>(&l1));
        }
        cp_commit_wait();
        __syncthreads();
        // ---- compute: 4 k-steps of 16 ----
#pragma unroll
        for (int ks = 0; ks < 4; ks++) {
            const int k0 = ks * 16;
            uint32_t ah[2][4], al[2][4];
#pragma unroll
            for (int mi = 0; mi < 2; mi++) {
                uint32_t ao =
                    ((wm * 32 + mi * 16 + (lane & 15)) * LDT + k0 + ((lane >> 4) << 3)) * 2;
                ldm_x4(ah[mi], sbase + oAhi + ao);
                ldm_x4(al[mi], sbase + oAlo + ao);
            }
            uint32_t bhf[4][4], blf[4][4];
#pragma unroll
            for (int nj = 0; nj < 4; nj++) {
                int bn = wn * 64 + nj * 16 + (lane & 7) + ((lane >> 4) << 3);
                uint32_t bo = (bn * LDT + k0 + (((lane >> 3) & 1) << 3)) * 2;
                ldm_x4(bhf[nj], sbase + oBhi + bo);
                ldm_x4(blf[nj], sbase + oBlo + bo);
            }
#pragma unroll
            for (int mi = 0; mi < 2; mi++)
#pragma unroll
                for (int j = 0; j < 8; j++) {
                    const uint32_t* bh2 = &bhf[j >> 1][(j & 1) * 2];
                    const uint32_t* bl2 = &blf[j >> 1][(j & 1) * 2];
                    mma_bf16(acc[mi][j], ah[mi], bh2);
                    mma_bf16(acc[mi][j], ah[mi], bl2);
                    mma_bf16(acc[mi][j], al[mi], bh2);
                }
        }
        __syncthreads();
    }

    // ---- epilogue: fragment (mi,j): rows wm*32+mi*16+(lane>>2)+{0,8}, cols wn*64+j*8+(lane&3)*2
#pragma unroll
    for (int mi = 0; mi < 2; mi++) {
#pragma unroll
        for (int e = 0; e < 2; e++) {
            size_t r = m0 + wm * 32 + mi * 16 + (lane >> 2) + e * 8;
            if (r >= (size_t)M) continue;
            float rden = 0.0f;
            if (EPI == 1) rden = 1.0f / (d_denom[r] + 1e-16f);
#pragma unroll
            for (int j = 0; j < 8; j++) {
                int n = wn * 64 + j * 8 + (lane & 3) * 2;
                float v0 = acc[mi][j][e * 2 + 0];
                float v1 = acc[mi][j][e * 2 + 1];
                if (EPI == 0) {
                    if (bias) {
                        v0 += bias[col0 + n];
                        v1 += bias[col0 + n + 1];
                    }
                } else {
                    float g0 = tanhf(v0 + d_agg[r * MEMD + n] * rden + b_anti[n]);
                    float g1 = tanhf(v1 + d_agg[r * MEMD + n + 1] * rden + b_anti[n + 1]);
                    v0 = tanhf(hres[r * MEMD + n] + EPS * g0);
                    v1 = tanhf(hres[r * MEMD + n + 1] + EPS * g1);
                }
                *reinterpret_cast<float2*>(C + r * ldc + col0 + n) = make_float2(v0, v1);
            }
        }
    }
}

// ---------------- fused edge pass: alpha -> exp -> scatter (no max-shift) ------
// softmax is shift-invariant; alpha = q.k/sqrt(128) is O(+-6) here so exp() is safe.
__global__ void edge_kernel(const int* __restrict__ src, const int* __restrict__ dst,
                            int E) {
    int w = (int)(((size_t)blockIdx.x * blockDim.x + threadIdx.x) >> 5);
    int lane = threadIdx.x & 31;
    if (w >= E) return;
    int s = src[w], d = dst[w];
    float4 qv = *reinterpret_cast<const float4*>(d_qkv + (size_t)d * DQKV + lane * 4);
    float4 kv = *reinterpret_cast<const float4*>(d_qkv + (size_t)s * DQKV + 128 + lane * 4);
    float4 vv = *reinterpret_cast<const float4*>(d_qkv + (size_t)s * DQKV + 256 + lane * 4);
    float4 ev = *reinterpret_cast<const float4*>(d_eproj + (size_t)w * MEMD + lane * 4);
    float p = qv.x * (kv.x + ev.x) + qv.y * (kv.y + ev.y) +
              qv.z * (kv.z + ev.z) + qv.w * (kv.w + ev.w);
#pragma unroll
    for (int o = 16; o; o >>= 1) p += __shfl_xor_sync(0xFFFFFFFFu, p, o);
    float ex = expf(p * 0.08838834764831845f);  // 1/sqrt(128)
    float rx = ex * (vv.x + ev.x);
    float ry = ex * (vv.y + ev.y);
    float rz = ex * (vv.z + ev.z);
    float rw = ex * (vv.w + ev.w);
    float* pa = d_agg + (size_t)d * MEMD + lane * 4;
    asm volatile("red.global.add.v4.f32 [%0], {%1,%2,%3,%4};"
                 :: "l"(pa), "f"(rx), "f"(ry), "f"(rz), "f"(rw)
                 : "memory");
    if (lane == 0) atomicAdd(&d_denom[d], ex);
}

// ---------------- launch ----------------
extern "C" void kernel_launch(void* const* d_in, const int* in_sizes, int n_in,
                              void* d_out, int out_size) {
    const float* x           = (const float*)d_in[0];
    const float* last_update = (const float*)d_in[1];
    const int*   edge_index  = (const int*)d_in[2];
    const float* t           = (const float*)d_in[3];
    const float* msg         = (const float*)d_in[4];
    const float* w_time      = (const float*)d_in[5];
    const float* b_time      = (const float*)d_in[6];
    const float* W_enc       = (const float*)d_in[7];
    const float* b_enc       = (const float*)d_in[8];
    const float* Wq          = (const float*)d_in[9];
    const float* bq          = (const float*)d_in[10];
    const float* Wk          = (const float*)d_in[11];
    const float* bk          = (const float*)d_in[12];
    const float* Wv          = (const float*)d_in[13];
    const float* bv          = (const float*)d_in[14];
    const float* We          = (const float*)d_in[15];
    const float* W_anti      = (const float*)d_in[16];
    const float* b_anti      = (const float*)d_in[17];

    int Nn = in_sizes[1];
    int Ei = in_sizes[3];
    const int* src = edge_index;
    const int* dst = edge_index + Ei;

    float *h_p, *qkv_p, *eproj_p, *bqkv_p;
    __nv_bfloat16 *whi_p, *wlo_p;
    cudaGetSymbolAddress((void**)&h_p, d_h);
    cudaGetSymbolAddress((void**)&qkv_p, d_qkv);
    cudaGetSymbolAddress((void**)&eproj_p, d_eproj);
    cudaGetSymbolAddress((void**)&bqkv_p, d_bqkv);
    cudaGetSymbolAddress((void**)&whi_p, d_whi);
    cudaGetSymbolAddress((void**)&wlo_p, d_wlo);

    cudaFuncSetAttribute(mma_gemm<0, 0>, cudaFuncAttributeMaxDynamicSharedMemorySize, SMEM_BYTES);
    cudaFuncSetAttribute(mma_gemm<1, 0>, cudaFuncAttributeMaxDynamicSharedMemorySize, SMEM_BYTES);
    cudaFuncSetAttribute(mma_gemm<0, 1>, cudaFuncAttributeMaxDynamicSharedMemorySize, SMEM_BYTES);

    int nblk = (Nn + 127) / 128;
    int eblk = (Ei + 127) / 128;

    prep_kernel<<<(W_TOTAL + 255) / 256, 256>>>(W_enc, Wq, bq, Wk, bk, Wv, bv, We, W_anti);
    init_kernel<<<(int)(((size_t)Nn * MEMD + 255) / 256), 256>>>(Nn);

    // h = x @ W_enc^T + b_enc        [N,256]x[256,128]
    mma_gemm<0, 0><<<dim3(1, nblk), 256, SMEM_BYTES>>>(
        x, 256, 256, 4, whi_p + OFF_ENC, wlo_p + OFF_ENC, b_enc, h_p, 128, Nn,
        nullptr, nullptr, nullptr, nullptr, nullptr, nullptr, nullptr);
    // QKV = h @ [Wq|Wk|Wv]^T + b     [N,128]x[128,384]
    mma_gemm<0, 0><<<dim3(3, nblk), 256, SMEM_BYTES>>>(
        h_p, 128, 128, 2, whi_p + OFF_QKV, wlo_p + OFF_QKV, bqkv_p, qkv_p, DQKV, Nn,
        nullptr, nullptr, nullptr, nullptr, nullptr, nullptr, nullptr);
    // e_proj = [msg | time_enc] @ We^T  (edge_attr built in-kernel)
    mma_gemm<1, 0><<<dim3(1, eblk), 256, SMEM_BYTES>>>(
        msg, 64, 128, 2, whi_p + OFF_WE, wlo_p + OFF_WE, nullptr, eproj_p, 128, Ei,
        src, last_update, t, w_time, b_time, nullptr, nullptr);
    // fused attention scatter (alpha + exp + aggregate)
    edge_kernel<<<(Ei + 7) / 8, 256>>>(src, dst, Ei);
    // final: D = h @ A^T, epilogue tanh(h + eps*tanh(D + agg/den + b_anti))
    mma_gemm<0, 1><<<dim3(1, nblk), 256, SMEM_BYTES>>>(
        h_p, 128, 128, 2, whi_p + OFF_ANTI, wlo_p + OFF_ANTI, nullptr, (float*)d_out, 128, Nn,
        nullptr, nullptr, nullptr, nullptr, nullptr, b_anti, h_p);
}

// round 8
// speedup vs baseline: 1.9796x; 1.0696x over previous
#include <cuda_runtime.h>
#include <cuda_bf16.h>
#include <math.h>
#include <stdint.h>

#define NN_MAX 100000
#define EE_MAX 500000
#define MEMD 128
#define DQKV 384
#define EPS 0.1f
#define GAM 0.1f

// weight-cat offsets (elements) in the bf16 hi/lo weight store, all [N,K] K-major
#define OFF_ENC 0          // [128,256]
#define OFF_QKV 32768      // [384,128]
#define OFF_WE 81920       // [128,128]
#define OFF_ANTI 98304     // [128,128]
#define W_TOTAL 114688

#define LDT 72                          // padded SMEM row pitch in bf16 (144B)
#define TILE_ELEMS (128 * LDT)          // per buffer
#define SMEM_BYTES (4 * TILE_ELEMS * 2) // Ahi, Alo, Bhi, Blo = 73728 B
#define LDF 132                         // fp32 pitch for edge-tile dump (128x132x4=67584B)

// ---------------- scratch (__device__ globals) ----------------
__device__ float d_h[(size_t)NN_MAX * MEMD];
__device__ __nv_bfloat16 d_hhi[(size_t)NN_MAX * MEMD];
__device__ __nv_bfloat16 d_hlo[(size_t)NN_MAX * MEMD];
__device__ float d_qkv[(size_t)NN_MAX * DQKV];
__device__ float d_denom[NN_MAX];
__device__ float d_agg[(size_t)NN_MAX * MEMD];
__device__ __nv_bfloat16 d_whi[W_TOTAL];
__device__ __nv_bfloat16 d_wlo[W_TOTAL];
__device__ float d_bqkv[DQKV];

// ---------------- PTX helpers --------------------------------------------------
__device__ __forceinline__ uint32_t smem_u32(const void* p) {
    uint32_t a;
    asm("{ .reg .u64 t; cvta.to.shared.u64 t, %1; cvt.u32.u64 %0, t; }" : "=r"(a) : "l"(p));
    return a;
}
__device__ __forceinline__ void ldm_x4(uint32_t* r, uint32_t addr) {
    asm volatile("ldmatrix.sync.aligned.m8n8.x4.shared.b16 {%0,%1,%2,%3}, [%4];"
                 : "=r"(r[0]), "=r"(r[1]), "=r"(r[2]), "=r"(r[3]) : "r"(addr));
}
__device__ __forceinline__ void mma_bf16(float* c, const uint32_t* a, const uint32_t* b) {
    asm volatile(
        "mma.sync.aligned.m16n8k16.row.col.f32.bf16.bf16.f32 "
        "{%0,%1,%2,%3}, {%4,%5,%6,%7}, {%8,%9}, {%0,%1,%2,%3};"
        : "+f"(c[0]), "+f"(c[1]), "+f"(c[2]), "+f"(c[3])
        : "r"(a[0]), "r"(a[1]), "r"(a[2]), "r"(a[3]), "r"(b[0]), "r"(b[1]));
}
__device__ __forceinline__ void cp16(uint32_t saddr, const void* gaddr) {
    asm volatile("cp.async.ca.shared.global [%0], [%1], 16;" :: "r"(saddr), "l"(gaddr));
}
__device__ __forceinline__ void cp16z(uint32_t saddr, const void* gaddr, int srcsz) {
    asm volatile("cp.async.ca.shared.global [%0], [%1], 16, %2;"
                 :: "r"(saddr), "l"(gaddr), "r"(srcsz));
}
__device__ __forceinline__ void cp_commit_wait() {
    asm volatile("cp.async.commit_group;");
    asm volatile("cp.async.wait_group 0;");
}

// ---------------- weight prep: bf16 hi/lo split of all B operands -------------
__device__ __forceinline__ void split_store(int idx, float v) {
    __nv_bfloat16 hi = __float2bfloat16(v);
    __nv_bfloat16 lo = __float2bfloat16(v - __bfloat162float(hi));
    d_whi[idx] = hi;
    d_wlo[idx] = lo;
}
__global__ void prep_kernel(const float* __restrict__ W_enc,
                            const float* __restrict__ Wq, const float* __restrict__ bq,
                            const float* __restrict__ Wk, const float* __restrict__ bk,
                            const float* __restrict__ Wv, const float* __restrict__ bv,
                            const float* __restrict__ We, const float* __restrict__ W_anti) {
    int i = blockIdx.x * blockDim.x + threadIdx.x;
    if (i < 32768) {
        split_store(OFF_ENC + i, W_enc[i]);               // [128,256] direct
    } else if (i < 81920) {
        int j = i - 32768;
        int n = j / 128, k = j % 128;
        float v;
        if (n < 128) v = Wq[n * 128 + k];
        else if (n < 256) v = Wk[(n - 128) * 128 + k];
        else v = Wv[(n - 256) * 128 + k];
        split_store(OFF_QKV + j, v);
    } else if (i < 98304) {
        int j = i - 81920;
        split_store(OFF_WE + j, We[j]);                   // [128,128] direct
    } else if (i < W_TOTAL) {
        int j = i - 98304;
        int n = j / 128, k = j % 128;
        float v = W_anti[n * 128 + k] - W_anti[k * 128 + n];
        if (n == k) v -= GAM;
        split_store(OFF_ANTI + j, v);
    }
    if (i < DQKV)
        d_bqkv[i] = (i < 128) ? bq[i] : ((i < 256) ? bk[i - 128] : bv[i - 256]);
}

// ---------------- init per-call accumulators ----------------
__global__ void init_kernel(int n_nodes) {
    size_t i = (size_t)blockIdx.x * blockDim.x + threadIdx.x;
    if (i < (size_t)n_nodes * MEMD) d_agg[i] = 0.0f;
    if (i < (size_t)n_nodes) d_denom[i] = 0.0f;
}

// ---------------- warp-MMA GEMM, bf16 hi/lo, fused variants --------------------
// AMODE 0: A fp32 [M,lda], convert in-kernel.   (enc: A = x, K=256)
// AMODE 1: A = [msg | cos-time-enc] built on the fly.  (edge GEMM)
// AMODE 2: A pre-split bf16 hi/lo (Ah/Al, K=128), staged via cp.async.
// EPI 0: C = D + bias.
// EPI 1: CTAN final epilogue (tanh(h + eps*tanh(D + agg/den + b_anti))).
// EPI 2: enc epilogue: C=h fp32, plus bf16 hi/lo split into Chi/Clo.
// EPI 3: fused attention: dump tile to smem, gather qkv, exp, scatter to agg/denom.
template <int AMODE, int EPI>
__global__ void __launch_bounds__(256, 2) mma_gemm(
    const float* __restrict__ A, int lda, int K, int nch,
    const __nv_bfloat16* __restrict__ Ah, const __nv_bfloat16* __restrict__ Al,
    const __nv_bfloat16* __restrict__ Bh, const __nv_bfloat16* __restrict__ Bl,
    const float* __restrict__ bias, float* __restrict__ C, int ldc, int M,
    const int* __restrict__ esrc, const int* __restrict__ edst,
    const float* __restrict__ lu, const float* __restrict__ tar,
    const float* __restrict__ wt, const float* __restrict__ bt,
    const float* __restrict__ b_anti, const float* __restrict__ hres,
    __nv_bfloat16* __restrict__ Chi, __nv_bfloat16* __restrict__ Clo) {
    const int t = threadIdx.x;
    const int lane = t & 31, wid = t >> 5;
    const int wm = wid & 3, wn = wid >> 2;
    const size_t m0 = (size_t)blockIdx.y * 128;
    const int col0 = blockIdx.x * 128;
    const __nv_bfloat16* Bhp = Bh + (size_t)col0 * K;
    const __nv_bfloat16* Blp = Bl + (size_t)col0 * K;

    extern __shared__ __nv_bfloat16 smem[];
    uint32_t sbase = smem_u32(smem);
    const uint32_t oAhi = 0;
    const uint32_t oAlo = TILE_ELEMS * 2;
    const uint32_t oBhi = 2 * TILE_ELEMS * 2;
    const uint32_t oBlo = 3 * TILE_ELEMS * 2;

    float acc[2][8][4];
#pragma unroll
    for (int i = 0; i < 2; i++)
#pragma unroll
        for (int j = 0; j < 8; j++)
#pragma unroll
            for (int e = 0; e < 4; e++) acc[i][j][e] = 0.0f;

    const int tr = t >> 1;            // loader row 0..127
    const int tcc = (t & 1) * 32;     // loader 32-col slab
    const size_t row = m0 + tr;
    const bool valid = row < (size_t)M;

    for (int c = 0; c < nch; c++) {
        const int kc = c * 64;
        // ---- stage B via cp.async ----
        {
            const __nv_bfloat16* bh = Bhp + (size_t)tr * K + kc + tcc;
            const __nv_bfloat16* bl = Blp + (size_t)tr * K + kc + tcc;
#pragma unroll
            for (int g = 0; g < 4; g++) {
                uint32_t so = (tr * LDT + tcc + g * 8) * 2;
                cp16(sbase + oBhi + so, bh + g * 8);
                cp16(sbase + oBlo + so, bl + g * 8);
            }
        }
        // ---- stage A ----
        if (AMODE == 2) {
            const __nv_bfloat16* ah = Ah + row * 128 + kc + tcc;
            const __nv_bfloat16* al = Al + row * 128 + kc + tcc;
            int sz = valid ? 16 : 0;
#pragma unroll
            for (int g = 0; g < 4; g++) {
                uint32_t so = (tr * LDT + tcc + g * 8) * 2;
                cp16z(sbase + oAhi + so, ah + g * 8, sz);
                cp16z(sbase + oAlo + so, al + g * 8, sz);
            }
        } else {
            float rel = 0.0f;
            if (AMODE == 1 && kc != 0 && valid)
                rel = fabsf(lu[esrc[row]] - tar[row]);
#pragma unroll
            for (int g = 0; g < 8; g++) {
                float4 v = make_float4(0.f, 0.f, 0.f, 0.f);
                if (valid) {
                    if (AMODE == 0) {
                        v = *reinterpret_cast<const float4*>(A + row * lda + kc + tcc + g * 4);
                    } else if (kc == 0) {
                        v = *reinterpret_cast<const float4*>(A + row * 64 + tcc + g * 4);
                    } else {
                        int cb = tcc + g * 4;
                        v.x = cosf(rel * wt[cb + 0] + bt[cb + 0]);
                        v.y = cosf(rel * wt[cb + 1] + bt[cb + 1]);
                        v.z = cosf(rel * wt[cb + 2] + bt[cb + 2]);
                        v.w = cosf(rel * wt[cb + 3] + bt[cb + 3]);
                    }
                }
                __nv_bfloat162 h0 = __floats2bfloat162_rn(v.x, v.y);
                __nv_bfloat162 h1 = __floats2bfloat162_rn(v.z, v.w);
                float2 f0 = __bfloat1622float2(h0);
                float2 f1 = __bfloat1622float2(h1);
                __nv_bfloat162 l0 = __floats2bfloat162_rn(v.x - f0.x, v.y - f0.y);
                __nv_bfloat162 l1 = __floats2bfloat162_rn(v.z - f1.x, v.w - f1.y);
                int idx = tr * LDT + tcc + g * 4;
                *reinterpret_cast<uint2*>(smem + idx) = make_uint2(
                    *reinterpret_cast<unsigned*>(&h0), *reinterpret_cast<unsigned*>(&h1));
                *reinterpret_cast<uint2*>(smem + TILE_ELEMS + idx) = make_uint2(
                    *reinterpret_cast<unsigned*>(&l0), *reinterpret_cast<unsigned*>(&l1));
            }
        }
        cp_commit_wait();
        __syncthreads();
        // ---- compute: 4 k-steps of 16 ----
#pragma unroll
        for (int ks = 0; ks < 4; ks++) {
            const int k0 = ks * 16;
            uint32_t ah[2][4], al[2][4];
#pragma unroll
            for (int mi = 0; mi < 2; mi++) {
                uint32_t ao =
                    ((wm * 32 + mi * 16 + (lane & 15)) * LDT + k0 + ((lane >> 4) << 3)) * 2;
                ldm_x4(ah[mi], sbase + oAhi + ao);
                ldm_x4(al[mi], sbase + oAlo + ao);
            }
            uint32_t bhf[4][4], blf[4][4];
#pragma unroll
            for (int nj = 0; nj < 4; nj++) {
                int bn = wn * 64 + nj * 16 + (lane & 7) + ((lane >> 4) << 3);
                uint32_t bo = (bn * LDT + k0 + (((lane >> 3) & 1) << 3)) * 2;
                ldm_x4(bhf[nj], sbase + oBhi + bo);
                ldm_x4(blf[nj], sbase + oBlo + bo);
            }
#pragma unroll
            for (int mi = 0; mi < 2; mi++)
#pragma unroll
                for (int j = 0; j < 8; j++) {
                    const uint32_t* bh2 = &bhf[j >> 1][(j & 1) * 2];
                    const uint32_t* bl2 = &blf[j >> 1][(j & 1) * 2];
                    mma_bf16(acc[mi][j], ah[mi], bh2);
                    mma_bf16(acc[mi][j], ah[mi], bl2);
                    mma_bf16(acc[mi][j], al[mi], bh2);
                }
        }
        __syncthreads();
    }

    if (EPI == 3) {
        // ---- fused attention epilogue ----
        float* sf = reinterpret_cast<float*>(smem);
#pragma unroll
        for (int mi = 0; mi < 2; mi++)
#pragma unroll
            for (int e = 0; e < 2; e++) {
                int rl = wm * 32 + mi * 16 + (lane >> 2) + e * 8;
#pragma unroll
                for (int j = 0; j < 8; j++) {
                    int n = wn * 64 + j * 8 + (lane & 3) * 2;
                    *reinterpret_cast<float2*>(sf + rl * LDF + n) =
                        make_float2(acc[mi][j][e * 2 + 0], acc[mi][j][e * 2 + 1]);
                }
            }
        __syncthreads();
        for (int i = 0; i < 16; i++) {
            int el = wid * 16 + i;
            size_t e = m0 + el;
            if (e >= (size_t)M) break;
            int s = esrc[e], d = edst[e];
            float4 qv = *reinterpret_cast<const float4*>(d_qkv + (size_t)d * DQKV + lane * 4);
            float4 kv =
                *reinterpret_cast<const float4*>(d_qkv + (size_t)s * DQKV + 128 + lane * 4);
            float4 vv =
                *reinterpret_cast<const float4*>(d_qkv + (size_t)s * DQKV + 256 + lane * 4);
            float4 ev = *reinterpret_cast<const float4*>(sf + el * LDF + lane * 4);
            float p = qv.x * (kv.x + ev.x) + qv.y * (kv.y + ev.y) +
                      qv.z * (kv.z + ev.z) + qv.w * (kv.w + ev.w);
#pragma unroll
            for (int o = 16; o; o >>= 1) p += __shfl_xor_sync(0xFFFFFFFFu, p, o);
            float ex = expf(p * 0.08838834764831845f);  // 1/sqrt(128); shift-free softmax
            float rx = ex * (vv.x + ev.x);
            float ry = ex * (vv.y + ev.y);
            float rz = ex * (vv.z + ev.z);
            float rw = ex * (vv.w + ev.w);
            float* pa = d_agg + (size_t)d * MEMD + lane * 4;
            asm volatile("red.global.add.v4.f32 [%0], {%1,%2,%3,%4};"
                         :: "l"(pa), "f"(rx), "f"(ry), "f"(rz), "f"(rw)
                         : "memory");
            if (lane == 0) atomicAdd(&d_denom[d], ex);
        }
        return;
    }

    // ---- standard epilogues ----
#pragma unroll
    for (int mi = 0; mi < 2; mi++) {
#pragma unroll
        for (int e = 0; e < 2; e++) {
            size_t r = m0 + wm * 32 + mi * 16 + (lane >> 2) + e * 8;
            if (r >= (size_t)M) continue;
            float rden = 0.0f;
            if (EPI == 1) rden = 1.0f / (d_denom[r] + 1e-16f);
#pragma unroll
            for (int j = 0; j < 8; j++) {
                int n = wn * 64 + j * 8 + (lane & 3) * 2;
                float v0 = acc[mi][j][e * 2 + 0];
                float v1 = acc[mi][j][e * 2 + 1];
                if (EPI == 0 || EPI == 2) {
                    if (bias) {
                        v0 += bias[col0 + n];
                        v1 += bias[col0 + n + 1];
                    }
                } else {
                    float g0 = tanhf(v0 + d_agg[r * MEMD + n] * rden + b_anti[n]);
                    float g1 = tanhf(v1 + d_agg[r * MEMD + n + 1] * rden + b_anti[n + 1]);
                    v0 = tanhf(hres[r * MEMD + n] + EPS * g0);
                    v1 = tanhf(hres[r * MEMD + n + 1] + EPS * g1);
                }
                *reinterpret_cast<float2*>(C + r * ldc + col0 + n) = make_float2(v0, v1);
                if (EPI == 2) {
                    __nv_bfloat162 hi2 = __floats2bfloat162_rn(v0, v1);
                    float2 hf = __bfloat1622float2(hi2);
                    __nv_bfloat162 lo2 = __floats2bfloat162_rn(v0 - hf.x, v1 - hf.y);
                    *reinterpret_cast<unsigned*>(Chi + r * MEMD + col0 + n) =
                        *reinterpret_cast<unsigned*>(&hi2);
                    *reinterpret_cast<unsigned*>(Clo + r * MEMD + col0 + n) =
                        *reinterpret_cast<unsigned*>(&lo2);
                }
            }
        }
    }
}

// ---------------- launch ----------------
extern "C" void kernel_launch(void* const* d_in, const int* in_sizes, int n_in,
                              void* d_out, int out_size) {
    const float* x           = (const float*)d_in[0];
    const float* last_update = (const float*)d_in[1];
    const int*   edge_index  = (const int*)d_in[2];
    const float* t           = (const float*)d_in[3];
    const float* msg         = (const float*)d_in[4];
    const float* w_time      = (const float*)d_in[5];
    const float* b_time      = (const float*)d_in[6];
    const float* W_enc       = (const float*)d_in[7];
    const float* b_enc       = (const float*)d_in[8];
    const float* Wq          = (const float*)d_in[9];
    const float* bq          = (const float*)d_in[10];
    const float* Wk          = (const float*)d_in[11];
    const float* bk          = (const float*)d_in[12];
    const float* Wv          = (const float*)d_in[13];
    const float* bv          = (const float*)d_in[14];
    const float* We          = (const float*)d_in[15];
    const float* W_anti      = (const float*)d_in[16];
    const float* b_anti      = (const float*)d_in[17];

    int Nn = in_sizes[1];
    int Ei = in_sizes[3];
    const int* src = edge_index;
    const int* dst = edge_index + Ei;

    float *h_p, *qkv_p, *bqkv_p;
    __nv_bfloat16 *whi_p, *wlo_p, *hhi_p, *hlo_p;
    cudaGetSymbolAddress((void**)&h_p, d_h);
    cudaGetSymbolAddress((void**)&qkv_p, d_qkv);
    cudaGetSymbolAddress((void**)&bqkv_p, d_bqkv);
    cudaGetSymbolAddress((void**)&whi_p, d_whi);
    cudaGetSymbolAddress((void**)&wlo_p, d_wlo);
    cudaGetSymbolAddress((void**)&hhi_p, d_hhi);
    cudaGetSymbolAddress((void**)&hlo_p, d_hlo);

    cudaFuncSetAttribute(mma_gemm<0, 2>, cudaFuncAttributeMaxDynamicSharedMemorySize, SMEM_BYTES);
    cudaFuncSetAttribute(mma_gemm<2, 0>, cudaFuncAttributeMaxDynamicSharedMemorySize, SMEM_BYTES);
    cudaFuncSetAttribute(mma_gemm<1, 3>, cudaFuncAttributeMaxDynamicSharedMemorySize, SMEM_BYTES);
    cudaFuncSetAttribute(mma_gemm<2, 1>, cudaFuncAttributeMaxDynamicSharedMemorySize, SMEM_BYTES);

    int nblk = (Nn + 127) / 128;
    int eblk = (Ei + 127) / 128;

    prep_kernel<<<(W_TOTAL + 255) / 256, 256>>>(W_enc, Wq, bq, Wk, bk, Wv, bv, We, W_anti);
    init_kernel<<<(int)(((size_t)Nn * MEMD + 255) / 256), 256>>>(Nn);

    // enc: h = x @ W_enc^T + b_enc; also emit bf16 hi/lo split of h
    mma_gemm<0, 2><<<dim3(1, nblk), 256, SMEM_BYTES>>>(
        x, 256, 256, 4, nullptr, nullptr, whi_p + OFF_ENC, wlo_p + OFF_ENC, b_enc,
        h_p, 128, Nn, nullptr, nullptr, nullptr, nullptr, nullptr, nullptr,
        nullptr, nullptr, hhi_p, hlo_p);
    // QKV = h @ [Wq|Wk|Wv]^T + b   (A pre-split, cp.async staged)
    mma_gemm<2, 0><<<dim3(3, nblk), 256, SMEM_BYTES>>>(
        nullptr, 0, 128, 2, hhi_p, hlo_p, whi_p + OFF_QKV, wlo_p + OFF_QKV, bqkv_p,
        qkv_p, DQKV, Nn, nullptr, nullptr, nullptr, nullptr, nullptr, nullptr,
        nullptr, nullptr, nullptr, nullptr);
    // fused: e_proj tile GEMM + attention gather/exp/scatter (no e_proj in gmem)
    mma_gemm<1, 3><<<dim3(1, eblk), 256, SMEM_BYTES>>>(
        msg, 64, 128, 2, nullptr, nullptr, whi_p + OFF_WE, wlo_p + OFF_WE, nullptr,
        nullptr, 0, Ei, src, dst, last_update, t, w_time, b_time,
        nullptr, nullptr, nullptr, nullptr);
    // final: D = h @ A^T, epilogue tanh(h + eps*tanh(D + agg/den + b_anti))
    mma_gemm<2, 1><<<dim3(1, nblk), 256, SMEM_BYTES>>>(
        nullptr, 0, 128, 2, hhi_p, hlo_p, whi_p + OFF_ANTI, wlo_p + OFF_ANTI, nullptr,
        (float*)d_out, 128, Nn, nullptr, nullptr, nullptr, nullptr, nullptr, nullptr,
        b_anti, h_p, nullptr, nullptr);
}

// round 9
// speedup vs baseline: 2.3525x; 1.1884x over previous
#include <cuda_runtime.h>
#include <cuda_bf16.h>
#include <math.h>
#include <stdint.h>

#define NN_MAX 100000
#define EE_MAX 500000
#define MEMD 128
#define EPS 0.1f
#define GAM 0.1f

// weight-cat offsets (elements) in the bf16 hi/lo weight store, all [N,K] K-major
#define OFF_ENC 0          // [128,256]  W_enc
#define OFF_QQ 32768       // [256,128]  [M1|M2] rows: 0..127 -> qk', 128..255 -> qW
#define OFF_FIN 65536      // [128,384]  [Aanti | Wv | We]
#define W_TOTAL 114688

#define LDT 72                          // padded SMEM row pitch in bf16 (144B)
#define TILE_ELEMS (128 * LDT)          // per buffer
#define SMEM_BYTES (4 * TILE_ELEMS * 2) // Ahi, Alo, Bhi, Blo = 73728 B

// ---------------- scratch (__device__ globals) ----------------
__device__ float d_h[(size_t)NN_MAX * MEMD];
__device__ __nv_bfloat16 d_hhi[(size_t)NN_MAX * MEMD];
__device__ __nv_bfloat16 d_hlo[(size_t)NN_MAX * MEMD];
__device__ float d_qq[(size_t)NN_MAX * 256];     // [qk' | qW]
__device__ float d_sq[NN_MAX];
__device__ float d_denom[NN_MAX];
__device__ float d_aggc[(size_t)NN_MAX * 256];   // [sum w*h | sum w*attr]
__device__ __nv_bfloat16 d_whi[W_TOTAL];
__device__ __nv_bfloat16 d_wlo[W_TOTAL];
__device__ float d_bqq[256];                     // [c1|c2]
__device__ float d_bfin[128];                    // b_anti + bv
__device__ float d_w3[128];
__device__ float d_c3;

// ---------------- PTX helpers --------------------------------------------------
__device__ __forceinline__ uint32_t smem_u32(const void* p) {
    uint32_t a;
    asm("{ .reg .u64 t; cvta.to.shared.u64 t, %1; cvt.u32.u64 %0, t; }" : "=r"(a) : "l"(p));
    return a;
}
__device__ __forceinline__ void ldm_x4(uint32_t* r, uint32_t addr) {
    asm volatile("ldmatrix.sync.aligned.m8n8.x4.shared.b16 {%0,%1,%2,%3}, [%4];"
                 : "=r"(r[0]), "=r"(r[1]), "=r"(r[2]), "=r"(r[3]) : "r"(addr));
}
__device__ __forceinline__ void mma_bf16(float* c, const uint32_t* a, const uint32_t* b) {
    asm volatile(
        "mma.sync.aligned.m16n8k16.row.col.f32.bf16.bf16.f32 "
        "{%0,%1,%2,%3}, {%4,%5,%6,%7}, {%8,%9}, {%0,%1,%2,%3};"
        : "+f"(c[0]), "+f"(c[1]), "+f"(c[2]), "+f"(c[3])
        : "r"(a[0]), "r"(a[1]), "r"(a[2]), "r"(a[3]), "r"(b[0]), "r"(b[1]));
}
__device__ __forceinline__ void cp16(uint32_t saddr, const void* gaddr) {
    asm volatile("cp.async.ca.shared.global [%0], [%1], 16;" :: "r"(saddr), "l"(gaddr));
}
__device__ __forceinline__ void cp16z(uint32_t saddr, const void* gaddr, int srcsz) {
    asm volatile("cp.async.ca.shared.global [%0], [%1], 16, %2;"
                 :: "r"(saddr), "l"(gaddr), "r"(srcsz));
}
__device__ __forceinline__ void cp_commit_wait() {
    asm volatile("cp.async.commit_group;");
    asm volatile("cp.async.wait_group 0;");
}

// ---------------- weight prep: composed matrices + bf16 hi/lo split -----------
__device__ __forceinline__ void split_store(int idx, float v) {
    __nv_bfloat16 hi = __float2bfloat16(v);
    __nv_bfloat16 lo = __float2bfloat16(v - __bfloat162float(hi));
    d_whi[idx] = hi;
    d_wlo[idx] = lo;
}
__global__ void prep_kernel(const float* __restrict__ W_enc,
                            const float* __restrict__ Wq, const float* __restrict__ bq,
                            const float* __restrict__ Wk, const float* __restrict__ bk,
                            const float* __restrict__ Wv, const float* __restrict__ bv,
                            const float* __restrict__ We, const float* __restrict__ W_anti,
                            const float* __restrict__ b_anti) {
    int i = blockIdx.x * blockDim.x + threadIdx.x;
    if (i < 32768) {
        split_store(OFF_ENC + i, W_enc[i]);               // [128,256] direct
    } else if (i < 65536) {
        int j = i - 32768;
        int jo = j / 128, k = j % 128;                    // out col jo, K index k
        float s = 0.0f;
        if (jo < 128) {
            for (int m = 0; m < 128; m++) s += Wk[m * 128 + jo] * Wq[m * 128 + k];
        } else {
            int j2 = jo - 128;
            for (int m = 0; m < 128; m++) s += We[m * 128 + j2] * Wq[m * 128 + k];
        }
        split_store(OFF_QQ + j, s);
    } else if (i < 114688) {
        int j = i - 65536;
        int jo = j / 384, k = j % 384;
        float v;
        if (k < 128) {
            v = W_anti[jo * 128 + k] - W_anti[k * 128 + jo];
            if (jo == k) v -= GAM;
        } else if (k < 256) {
            v = Wv[jo * 128 + (k - 128)];
        } else {
            v = We[jo * 128 + (k - 256)];
        }
        split_store(OFF_FIN + j, v);
    } else if (i < 114944) {
        int j = i - 114688;                               // c1|c2
        float s = 0.0f;
        if (j < 128) {
            for (int m = 0; m < 128; m++) s += bq[m] * Wk[m * 128 + j];
        } else {
            int j2 = j - 128;
            for (int m = 0; m < 128; m++) s += bq[m] * We[m * 128 + j2];
        }
        d_bqq[j] = s;
    } else if (i < 115072) {
        int j = i - 114944;
        d_bfin[j] = b_anti[j] + bv[j];
    } else if (i < 115200) {
        int j = i - 115072;
        float s = 0.0f;
        for (int m = 0; m < 128; m++) s += bk[m] * Wq[m * 128 + j];
        d_w3[j] = s;
    } else if (i == 115200) {
        float s = 0.0f;
        for (int m = 0; m < 128; m++) s += bq[m] * bk[m];
        d_c3 = s;
    }
}

// ---------------- init per-call accumulators ----------------
__global__ void init_kernel(int n_nodes) {
    size_t i = (size_t)blockIdx.x * blockDim.x + threadIdx.x;
    if (i < (size_t)n_nodes * 256) d_aggc[i] = 0.0f;
    if (i < (size_t)n_nodes) d_denom[i] = 0.0f;
}

// ---------------- sq[n] = h[n].w3 + c3 (warp per node) -------------------------
__global__ void sq_kernel(int Nn) {
    int n = (int)(((size_t)blockIdx.x * blockDim.x + threadIdx.x) >> 5);
    int lane = threadIdx.x & 31;
    if (n >= Nn) return;
    float4 hv = *reinterpret_cast<const float4*>(d_h + (size_t)n * MEMD + lane * 4);
    float4 wv = *reinterpret_cast<const float4*>(d_w3 + lane * 4);
    float p = hv.x * wv.x + hv.y * wv.y + hv.z * wv.z + hv.w * wv.w;
#pragma unroll
    for (int o = 16; o; o >>= 1) p += __shfl_xor_sync(0xFFFFFFFFu, p, o);
    if (lane == 0) d_sq[n] = p + d_c3;
}

// ---------------- warp-MMA GEMM, bf16 hi/lo ------------------------------------
// AMODE 0: A fp32 [M,lda], convert in-kernel (enc).
// AMODE 2: A pre-split bf16 hi/lo (Ah/Al, K=128), staged via cp.async.
// AMODE 3: final: chunks 0-1 from Ah/Al (h), chunks 2-5 from d_aggc * 1/denom.
// EPI 0: C = D + bias.   EPI 1: out = tanh(h + eps*tanh(D + bfin)).
// EPI 2: enc: C=h fp32 + bf16 hi/lo split into Chi/Clo.
template <int AMODE, int EPI>
__global__ void __launch_bounds__(256, 2) mma_gemm(
    const float* __restrict__ A, int lda, int K, int nch,
    const __nv_bfloat16* __restrict__ Ah, const __nv_bfloat16* __restrict__ Al,
    const __nv_bfloat16* __restrict__ Bh, const __nv_bfloat16* __restrict__ Bl,
    const float* __restrict__ bias, float* __restrict__ C, int ldc, int M,
    const float* __restrict__ hres,
    __nv_bfloat16* __restrict__ Chi, __nv_bfloat16* __restrict__ Clo) {
    const int t = threadIdx.x;
    const int lane = t & 31, wid = t >> 5;
    const int wm = wid & 3, wn = wid >> 2;
    const size_t m0 = (size_t)blockIdx.y * 128;
    const int col0 = blockIdx.x * 128;
    const __nv_bfloat16* Bhp = Bh + (size_t)col0 * K;
    const __nv_bfloat16* Blp = Bl + (size_t)col0 * K;

    extern __shared__ __nv_bfloat16 smem[];
    uint32_t sbase = smem_u32(smem);
    const uint32_t oAhi = 0;
    const uint32_t oAlo = TILE_ELEMS * 2;
    const uint32_t oBhi = 2 * TILE_ELEMS * 2;
    const uint32_t oBlo = 3 * TILE_ELEMS * 2;

    float acc[2][8][4];
#pragma unroll
    for (int i = 0; i < 2; i++)
#pragma unroll
        for (int j = 0; j < 8; j++)
#pragma unroll
            for (int e = 0; e < 4; e++) acc[i][j][e] = 0.0f;

    const int tr = t >> 1;            // loader row 0..127
    const int tcc = (t & 1) * 32;     // loader 32-col slab
    const size_t row = m0 + tr;
    const bool valid = row < (size_t)M;

    for (int c = 0; c < nch; c++) {
        const int kc = c * 64;
        // ---- stage B via cp.async ----
        {
            const __nv_bfloat16* bh = Bhp + (size_t)tr * K + kc + tcc;
            const __nv_bfloat16* bl = Blp + (size_t)tr * K + kc + tcc;
#pragma unroll
            for (int g = 0; g < 4; g++) {
                uint32_t so = (tr * LDT + tcc + g * 8) * 2;
                cp16(sbase + oBhi + so, bh + g * 8);
                cp16(sbase + oBlo + so, bl + g * 8);
            }
        }
        // ---- stage A ----
        if (AMODE == 2 || (AMODE == 3 && c < 2)) {
            const __nv_bfloat16* ah = Ah + row * 128 + kc + tcc;
            const __nv_bfloat16* al = Al + row * 128 + kc + tcc;
            int sz = valid ? 16 : 0;
#pragma unroll
            for (int g = 0; g < 4; g++) {
                uint32_t so = (tr * LDT + tcc + g * 8) * 2;
                cp16z(sbase + oAhi + so, ah + g * 8, sz);
                cp16z(sbase + oAlo + so, al + g * 8, sz);
            }
        } else {
            float rden = 0.0f;
            if (AMODE == 3 && valid) rden = 1.0f / (d_denom[row] + 1e-16f);
#pragma unroll
            for (int g = 0; g < 8; g++) {
                float4 v = make_float4(0.f, 0.f, 0.f, 0.f);
                if (valid) {
                    if (AMODE == 0) {
                        v = *reinterpret_cast<const float4*>(A + row * lda + kc + tcc + g * 4);
                    } else {  // AMODE 3, c >= 2: normalized aggregates
                        v = *reinterpret_cast<const float4*>(
                            d_aggc + row * 256 + (kc - 128) + tcc + g * 4);
                        v.x *= rden; v.y *= rden; v.z *= rden; v.w *= rden;
                    }
                }
                __nv_bfloat162 h0 = __floats2bfloat162_rn(v.x, v.y);
                __nv_bfloat162 h1 = __floats2bfloat162_rn(v.z, v.w);
                float2 f0 = __bfloat1622float2(h0);
                float2 f1 = __bfloat1622float2(h1);
                __nv_bfloat162 l0 = __floats2bfloat162_rn(v.x - f0.x, v.y - f0.y);
                __nv_bfloat162 l1 = __floats2bfloat162_rn(v.z - f1.x, v.w - f1.y);
                int idx = tr * LDT + tcc + g * 4;
                *reinterpret_cast<uint2*>(smem + idx) = make_uint2(
                    *reinterpret_cast<unsigned*>(&h0), *reinterpret_cast<unsigned*>(&h1));
                *reinterpret_cast<uint2*>(smem + TILE_ELEMS + idx) = make_uint2(
                    *reinterpret_cast<unsigned*>(&l0), *reinterpret_cast<unsigned*>(&l1));
            }
        }
        cp_commit_wait();
        __syncthreads();
        // ---- compute: 4 k-steps of 16 ----
#pragma unroll
        for (int ks = 0; ks < 4; ks++) {
            const int k0 = ks * 16;
            uint32_t ah[2][4], al[2][4];
#pragma unroll
            for (int mi = 0; mi < 2; mi++) {
                uint32_t ao =
                    ((wm * 32 + mi * 16 + (lane & 15)) * LDT + k0 + ((lane >> 4) << 3)) * 2;
                ldm_x4(ah[mi], sbase + oAhi + ao);
                ldm_x4(al[mi], sbase + oAlo + ao);
            }
            uint32_t bhf[4][4], blf[4][4];
#pragma unroll
            for (int nj = 0; nj < 4; nj++) {
                int bn = wn * 64 + nj * 16 + (lane & 7) + ((lane >> 4) << 3);
                uint32_t bo = (bn * LDT + k0 + (((lane >> 3) & 1) << 3)) * 2;
                ldm_x4(bhf[nj], sbase + oBhi + bo);
                ldm_x4(blf[nj], sbase + oBlo + bo);
            }
#pragma unroll
            for (int mi = 0; mi < 2; mi++)
#pragma unroll
                for (int j = 0; j < 8; j++) {
                    const uint32_t* bh2 = &bhf[j >> 1][(j & 1) * 2];
                    const uint32_t* bl2 = &blf[j >> 1][(j & 1) * 2];
                    mma_bf16(acc[mi][j], ah[mi], bh2);
                    mma_bf16(acc[mi][j], ah[mi], bl2);
                    mma_bf16(acc[mi][j], al[mi], bh2);
                }
        }
        __syncthreads();
    }

    // ---- epilogues ----
#pragma unroll
    for (int mi = 0; mi < 2; mi++) {
#pragma unroll
        for (int e = 0; e < 2; e++) {
            size_t r = m0 + wm * 32 + mi * 16 + (lane >> 2) + e * 8;
            if (r >= (size_t)M) continue;
#pragma unroll
            for (int j = 0; j < 8; j++) {
                int n = wn * 64 + j * 8 + (lane & 3) * 2;
                float v0 = acc[mi][j][e * 2 + 0];
                float v1 = acc[mi][j][e * 2 + 1];
                if (EPI == 0 || EPI == 2) {
                    if (bias) {
                        v0 += bias[col0 + n];
                        v1 += bias[col0 + n + 1];
                    }
                } else {
                    float g0 = tanhf(v0 + bias[n]);
                    float g1 = tanhf(v1 + bias[n + 1]);
                    v0 = tanhf(hres[r * MEMD + n] + EPS * g0);
                    v1 = tanhf(hres[r * MEMD + n + 1] + EPS * g1);
                }
                *reinterpret_cast<float2*>(C + r * ldc + col0 + n) = make_float2(v0, v1);
                if (EPI == 2) {
                    __nv_bfloat162 hi2 = __floats2bfloat162_rn(v0, v1);
                    float2 hf = __bfloat1622float2(hi2);
                    __nv_bfloat162 lo2 = __floats2bfloat162_rn(v0 - hf.x, v1 - hf.y);
                    *reinterpret_cast<unsigned*>(Chi + r * MEMD + col0 + n) =
                        *reinterpret_cast<unsigned*>(&hi2);
                    *reinterpret_cast<unsigned*>(Clo + r * MEMD + col0 + n) =
                        *reinterpret_cast<unsigned*>(&lo2);
                }
            }
        }
    }
}

// ---------------- edge pass: alpha -> exp -> scatter w*h, w*attr ---------------
// alpha = qk'[dst].h[src] + qW[dst].attr + sq[dst]; softmax shift-free (alpha O(+-6)).
__global__ void edge_kernel(const int* __restrict__ src, const int* __restrict__ dst,
                            const float* __restrict__ msg,
                            const float* __restrict__ lu, const float* __restrict__ tar,
                            const float* __restrict__ wt, const float* __restrict__ bt,
                            int E) {
    int w = (int)(((size_t)blockIdx.x * blockDim.x + threadIdx.x) >> 5);
    int lane = threadIdx.x & 31;
    if (w >= E) return;
    int s = src[w], d = dst[w];
    float4 qk = *reinterpret_cast<const float4*>(d_qq + (size_t)d * 256 + lane * 4);
    float4 qw = *reinterpret_cast<const float4*>(d_qq + (size_t)d * 256 + 128 + lane * 4);
    float4 hs = *reinterpret_cast<const float4*>(d_h + (size_t)s * MEMD + lane * 4);
    float4 at;
    if (lane < 16) {
        at = *reinterpret_cast<const float4*>(msg + (size_t)w * 64 + lane * 4);
    } else {
        float rel = fabsf(lu[s] - tar[w]);
        int j = lane * 4 - 64;
        at.x = __cosf(fmaf(rel, wt[j + 0], bt[j + 0]));
        at.y = __cosf(fmaf(rel, wt[j + 1], bt[j + 1]));
        at.z = __cosf(fmaf(rel, wt[j + 2], bt[j + 2]));
        at.w = __cosf(fmaf(rel, wt[j + 3], bt[j + 3]));
    }
    float p = qk.x * hs.x + qk.y * hs.y + qk.z * hs.z + qk.w * hs.w +
              qw.x * at.x + qw.y * at.y + qw.z * at.z + qw.w * at.w;
#pragma unroll
    for (int o = 16; o; o >>= 1) p += __shfl_xor_sync(0xFFFFFFFFu, p, o);
    float ex = __expf((p + d_sq[d]) * 0.08838834764831845f);  // 1/sqrt(128)
    float* pa = d_aggc + (size_t)d * 256;
    asm volatile("red.global.add.v4.f32 [%0], {%1,%2,%3,%4};"
                 :: "l"(pa + lane * 4), "f"(ex * hs.x), "f"(ex * hs.y),
                    "f"(ex * hs.z), "f"(ex * hs.w) : "memory");
    asm volatile("red.global.add.v4.f32 [%0], {%1,%2,%3,%4};"
                 :: "l"(pa + 128 + lane * 4), "f"(ex * at.x), "f"(ex * at.y),
                    "f"(ex * at.z), "f"(ex * at.w) : "memory");
    if (lane == 0) atomicAdd(&d_denom[d], ex);
}

// ---------------- launch ----------------
extern "C" void kernel_launch(void* const* d_in, const int* in_sizes, int n_in,
                              void* d_out, int out_size) {
    const float* x           = (const float*)d_in[0];
    const float* last_update = (const float*)d_in[1];
    const int*   edge_index  = (const int*)d_in[2];
    const float* t           = (const float*)d_in[3];
    const float* msg         = (const float*)d_in[4];
    const float* w_time      = (const float*)d_in[5];
    const float* b_time      = (const float*)d_in[6];
    const float* W_enc       = (const float*)d_in[7];
    const float* b_enc       = (const float*)d_in[8];
    const float* Wq          = (const float*)d_in[9];
    const float* bq          = (const float*)d_in[10];
    const float* Wk          = (const float*)d_in[11];
    const float* bk          = (const float*)d_in[12];
    const float* Wv          = (const float*)d_in[13];
    const float* bv          = (const float*)d_in[14];
    const float* We          = (const float*)d_in[15];
    const float* W_anti      = (const float*)d_in[16];
    const float* b_anti      = (const float*)d_in[17];

    int Nn = in_sizes[1];
    int Ei = in_sizes[3];
    const int* src = edge_index;
    const int* dst = edge_index + Ei;

    float *h_p, *qq_p, *bqq_p, *bfin_p;
    __nv_bfloat16 *whi_p, *wlo_p, *hhi_p, *hlo_p;
    cudaGetSymbolAddress((void**)&h_p, d_h);
    cudaGetSymbolAddress((void**)&qq_p, d_qq);
    cudaGetSymbolAddress((void**)&bqq_p, d_bqq);
    cudaGetSymbolAddress((void**)&bfin_p, d_bfin);
    cudaGetSymbolAddress((void**)&whi_p, d_whi);
    cudaGetSymbolAddress((void**)&wlo_p, d_wlo);
    cudaGetSymbolAddress((void**)&hhi_p, d_hhi);
    cudaGetSymbolAddress((void**)&hlo_p, d_hlo);

    cudaFuncSetAttribute(mma_gemm<0, 2>, cudaFuncAttributeMaxDynamicSharedMemorySize, SMEM_BYTES);
    cudaFuncSetAttribute(mma_gemm<2, 0>, cudaFuncAttributeMaxDynamicSharedMemorySize, SMEM_BYTES);
    cudaFuncSetAttribute(mma_gemm<3, 1>, cudaFuncAttributeMaxDynamicSharedMemorySize, SMEM_BYTES);

    int nblk = (Nn + 127) / 128;

    prep_kernel<<<(115201 + 255) / 256, 256>>>(W_enc, Wq, bq, Wk, bk, Wv, bv, We,
                                               W_anti, b_anti);
    init_kernel<<<(int)(((size_t)Nn * 256 + 255) / 256), 256>>>(Nn);

    // enc: h = x @ W_enc^T + b_enc; also emit bf16 hi/lo split of h
    mma_gemm<0, 2><<<dim3(1, nblk), 256, SMEM_BYTES>>>(
        x, 256, 256, 4, nullptr, nullptr, whi_p + OFF_ENC, wlo_p + OFF_ENC, b_enc,
        h_p, 128, Nn, nullptr, hhi_p, hlo_p);
    // qq = h @ [M1|M2]^T + [c1|c2]   -> d_qq [N,256]
    mma_gemm<2, 0><<<dim3(2, nblk), 256, SMEM_BYTES>>>(
        nullptr, 0, 128, 2, hhi_p, hlo_p, whi_p + OFF_QQ, wlo_p + OFF_QQ, bqq_p,
        qq_p, 256, Nn, nullptr, nullptr, nullptr);
    // sq = h.w3 + c3
    sq_kernel<<<(Nn * 32 + 255) / 256, 256>>>(Nn);
    // edge pass: alpha/exp/scatter
    edge_kernel<<<(Ei + 7) / 8, 256>>>(src, dst, msg, last_update, t, w_time, b_time, Ei);
    // final: out = tanh(h + eps*tanh([h|ah|aa]@[A|Wv|We]^T + b_anti + bv))
    mma_gemm<3, 1><<<dim3(1, nblk), 256, SMEM_BYTES>>>(
        nullptr, 0, 384, 6, hhi_p, hlo_p, whi_p + OFF_FIN, wlo_p + OFF_FIN, bfin_p,
        (float*)d_out, 128, Nn, h_p, nullptr, nullptr);
}

// round 12
// speedup vs baseline: 2.5689x; 1.0920x over previous
#include <cuda_runtime.h>
#include <cuda_bf16.h>
#include <math.h>
#include <stdint.h>

#define NN_MAX 100000
#define EE_MAX 500000
#define MEMD 128
#define EPS 0.1f
#define GAM 0.1f

// weight-cat offsets (elements) in the bf16 hi/lo weight store, all [N,K] K-major
#define OFF_ENC 0          // [128,256]  W_enc
#define OFF_QQ 32768       // [256,128]  [M1|M2]: qk' rows 0..127, qW rows 128..255
#define OFF_FIN 65536      // [128,384]  [Aanti | Wv | We]
#define W_TOTAL 114688

#define LDT 72                          // padded SMEM row pitch in bf16 (144B)
#define TILE_ELEMS (128 * LDT)          // per buffer
#define SMEM_BYTES (4 * TILE_ELEMS * 2) // Ahi, Alo, Bhi, Blo = 73728 B

// ---------------- scratch (__device__ globals) ----------------
__device__ float d_h[(size_t)NN_MAX * MEMD];
__device__ __nv_bfloat16 d_hhi[(size_t)NN_MAX * MEMD];
__device__ __nv_bfloat16 d_hlo[(size_t)NN_MAX * MEMD];
__device__ __nv_bfloat16 d_qqb[(size_t)NN_MAX * 256];   // [qk' | qW] bf16
__device__ float d_denom[NN_MAX];
__device__ float d_aggc[(size_t)NN_MAX * 256];          // [sum w*h | sum w*attr]
__device__ __nv_bfloat16 d_whi[W_TOTAL];
__device__ __nv_bfloat16 d_wlo[W_TOTAL];
__device__ float d_bqq[256];                            // [c1|c2]
__device__ float d_bfin[128];                           // b_anti + bv

// ---------------- PTX helpers --------------------------------------------------
__device__ __forceinline__ uint32_t smem_u32(const void* p) {
    uint32_t a;
    asm("{ .reg .u64 t; cvta.to.shared.u64 t, %1; cvt.u32.u64 %0, t; }" : "=r"(a) : "l"(p));
    return a;
}
__device__ __forceinline__ void ldm_x4(uint32_t* r, uint32_t addr) {
    asm volatile("ldmatrix.sync.aligned.m8n8.x4.shared.b16 {%0,%1,%2,%3}, [%4];"
                 : "=r"(r[0]), "=r"(r[1]), "=r"(r[2]), "=r"(r[3]) : "r"(addr));
}
__device__ __forceinline__ void mma_bf16(float* c, const uint32_t* a, const uint32_t* b) {
    asm volatile(
        "mma.sync.aligned.m16n8k16.row.col.f32.bf16.bf16.f32 "
        "{%0,%1,%2,%3}, {%4,%5,%6,%7}, {%8,%9}, {%0,%1,%2,%3};"
        : "+f"(c[0]), "+f"(c[1]), "+f"(c[2]), "+f"(c[3])
        : "r"(a[0]), "r"(a[1]), "r"(a[2]), "r"(a[3]), "r"(b[0]), "r"(b[1]));
}
__device__ __forceinline__ void cp16(uint32_t saddr, const void* gaddr) {
    asm volatile("cp.async.ca.shared.global [%0], [%1], 16;" :: "r"(saddr), "l"(gaddr));
}
__device__ __forceinline__ void cp16z(uint32_t saddr, const void* gaddr, int srcsz) {
    asm volatile("cp.async.ca.shared.global [%0], [%1], 16, %2;"
                 :: "r"(saddr), "l"(gaddr), "r"(srcsz));
}
__device__ __forceinline__ void cp_commit_wait() {
    asm volatile("cp.async.commit_group;");
    asm volatile("cp.async.wait_group 0;");
}

// ---------------- weight prep: composed matrices + bf16 hi/lo split -----------
__device__ __forceinline__ void split_store(int idx, float v) {
    __nv_bfloat16 hi = __float2bfloat16(v);
    __nv_bfloat16 lo = __float2bfloat16(v - __bfloat162float(hi));
    d_whi[idx] = hi;
    d_wlo[idx] = lo;
}
__global__ void prep_kernel(const float* __restrict__ W_enc,
                            const float* __restrict__ Wq, const float* __restrict__ bq,
                            const float* __restrict__ Wk, const float* __restrict__ bk,
                            const float* __restrict__ Wv, const float* __restrict__ bv,
                            const float* __restrict__ We, const float* __restrict__ W_anti,
                            const float* __restrict__ b_anti) {
    int i = blockIdx.x * blockDim.x + threadIdx.x;
    if (i < 32768) {
        split_store(OFF_ENC + i, W_enc[i]);               // [128,256] direct
    } else if (i < 65536) {
        int j = i - 32768;
        int jo = j / 128, k = j % 128;                    // out col jo, K index k
        float s = 0.0f;
        if (jo < 128) {
            for (int m = 0; m < 128; m++) s += Wk[m * 128 + jo] * Wq[m * 128 + k];
        } else {
            int j2 = jo - 128;
            for (int m = 0; m < 128; m++) s += We[m * 128 + j2] * Wq[m * 128 + k];
        }
        split_store(OFF_QQ + j, s);
    } else if (i < 114688) {
        int j = i - 65536;
        int jo = j / 384, k = j % 384;
        float v;
        if (k < 128) {
            v = W_anti[jo * 128 + k] - W_anti[k * 128 + jo];
            if (jo == k) v -= GAM;
        } else if (k < 256) {
            v = Wv[jo * 128 + (k - 128)];
        } else {
            v = We[jo * 128 + (k - 256)];
        }
        split_store(OFF_FIN + j, v);
    } else if (i < 114944) {
        int j = i - 114688;                               // c1|c2
        float s = 0.0f;
        if (j < 128) {
            for (int m = 0; m < 128; m++) s += bq[m] * Wk[m * 128 + j];
        } else {
            int j2 = j - 128;
            for (int m = 0; m < 128; m++) s += bq[m] * We[m * 128 + j2];
        }
        d_bqq[j] = s;
    } else if (i < 115072) {
        int j = i - 114944;
        d_bfin[j] = b_anti[j] + bv[j];
    }
    // NOTE: the per-dst scalar (q.bk) term of alpha cancels in segment softmax - dropped.
}

// ---------------- init per-call accumulators ----------------
__global__ void init_kernel(int n_nodes) {
    size_t i = (size_t)blockIdx.x * blockDim.x + threadIdx.x;
    if (i < (size_t)n_nodes * 256) d_aggc[i] = 0.0f;
    if (i < (size_t)n_nodes) d_denom[i] = 0.0f;
}

// ---------------- warp-MMA GEMM, bf16 hi/lo ------------------------------------
// AMODE 0: A fp32 [M,lda], convert in-kernel (enc).
// AMODE 2: A pre-split bf16 hi/lo (Ah/Al, K=128), staged via cp.async.
// AMODE 3: final: chunks 0-1 from Ah/Al (h), chunks 2-5 from d_aggc * 1/denom.
// EPI 1: out = tanh(h + eps*tanh(D + bfin)).
// EPI 2: enc: C=h fp32 + bf16 hi/lo split into Chi/Clo.
// EPI 4: qq: bf16 output into Chi only (+bias).
template <int AMODE, int EPI>
__global__ void __launch_bounds__(256, 2) mma_gemm(
    const float* __restrict__ A, int lda, int K, int nch,
    const __nv_bfloat16* __restrict__ Ah, const __nv_bfloat16* __restrict__ Al,
    const __nv_bfloat16* __restrict__ Bh, const __nv_bfloat16* __restrict__ Bl,
    const float* __restrict__ bias, float* __restrict__ C, int ldc, int M,
    const float* __restrict__ hres,
    __nv_bfloat16* __restrict__ Chi, __nv_bfloat16* __restrict__ Clo) {
    const int t = threadIdx.x;
    const int lane = t & 31, wid = t >> 5;
    const int wm = wid & 3, wn = wid >> 2;
    const size_t m0 = (size_t)blockIdx.y * 128;
    const int col0 = blockIdx.x * 128;
    const __nv_bfloat16* Bhp = Bh + (size_t)col0 * K;
    const __nv_bfloat16* Blp = Bl + (size_t)col0 * K;

    extern __shared__ __nv_bfloat16 smem[];
    uint32_t sbase = smem_u32(smem);
    const uint32_t oAhi = 0;
    const uint32_t oAlo = TILE_ELEMS * 2;
    const uint32_t oBhi = 2 * TILE_ELEMS * 2;
    const uint32_t oBlo = 3 * TILE_ELEMS * 2;

    float acc[2][8][4];
#pragma unroll
    for (int i = 0; i < 2; i++)
#pragma unroll
        for (int j = 0; j < 8; j++)
#pragma unroll
            for (int e = 0; e < 4; e++) acc[i][j][e] = 0.0f;

    const int tr = t >> 1;            // loader row 0..127
    const int tcc = (t & 1) * 32;     // loader 32-col slab
    const size_t row = m0 + tr;
    const bool valid = row < (size_t)M;

    for (int c = 0; c < nch; c++) {
        const int kc = c * 64;
        // ---- stage B via cp.async ----
        {
            const __nv_bfloat16* bh = Bhp + (size_t)tr * K + kc + tcc;
            const __nv_bfloat16* bl = Blp + (size_t)tr * K + kc + tcc;
#pragma unroll
            for (int g = 0; g < 4; g++) {
                uint32_t so = (tr * LDT + tcc + g * 8) * 2;
                cp16(sbase + oBhi + so, bh + g * 8);
                cp16(sbase + oBlo + so, bl + g * 8);
            }
        }
        // ---- stage A ----
        if (AMODE == 2 || (AMODE == 3 && c < 2)) {
            const __nv_bfloat16* ah = Ah + row * 128 + kc + tcc;
            const __nv_bfloat16* al = Al + row * 128 + kc + tcc;
            int sz = valid ? 16 : 0;
#pragma unroll
            for (int g = 0; g < 4; g++) {
                uint32_t so = (tr * LDT + tcc + g * 8) * 2;
                cp16z(sbase + oAhi + so, ah + g * 8, sz);
                cp16z(sbase + oAlo + so, al + g * 8, sz);
            }
        } else {
            float rden = 0.0f;
            if (AMODE == 3 && valid) rden = 1.0f / (d_denom[row] + 1e-16f);
#pragma unroll
            for (int g = 0; g < 8; g++) {
                float4 v = make_float4(0.f, 0.f, 0.f, 0.f);
                if (valid) {
                    if (AMODE == 0) {
                        v = *reinterpret_cast<const float4*>(A + row * lda + kc + tcc + g * 4);
                    } else {  // AMODE 3, c >= 2: normalized aggregates
                        v = *reinterpret_cast<const float4*>(
                            d_aggc + row * 256 + (kc - 128) + tcc + g * 4);
                        v.x *= rden; v.y *= rden; v.z *= rden; v.w *= rden;
                    }
                }
                __nv_bfloat162 h0 = __floats2bfloat162_rn(v.x, v.y);
                __nv_bfloat162 h1 = __floats2bfloat162_rn(v.z, v.w);
                float2 f0 = __bfloat1622float2(h0);
                float2 f1 = __bfloat1622float2(h1);
                __nv_bfloat162 l0 = __floats2bfloat162_rn(v.x - f0.x, v.y - f0.y);
                __nv_bfloat162 l1 = __floats2bfloat162_rn(v.z - f1.x, v.w - f1.y);
                int idx = tr * LDT + tcc + g * 4;
                *reinterpret_cast<uint2*>(smem + idx) = make_uint2(
                    *reinterpret_cast<unsigned*>(&h0), *reinterpret_cast<unsigned*>(&h1));
                *reinterpret_cast<uint2*>(smem + TILE_ELEMS + idx) = make_uint2(
                    *reinterpret_cast<unsigned*>(&l0), *reinterpret_cast<unsigned*>(&l1));
            }
        }
        cp_commit_wait();
        __syncthreads();
        // ---- compute: 4 k-steps of 16 ----
#pragma unroll
        for (int ks = 0; ks < 4; ks++) {
            const int k0 = ks * 16;
            uint32_t ah[2][4], al[2][4];
#pragma unroll
            for (int mi = 0; mi < 2; mi++) {
                uint32_t ao =
                    ((wm * 32 + mi * 16 + (lane & 15)) * LDT + k0 + ((lane >> 4) << 3)) * 2;
                ldm_x4(ah[mi], sbase + oAhi + ao);
                ldm_x4(al[mi], sbase + oAlo + ao);
            }
            uint32_t bhf[4][4], blf[4][4];
#pragma unroll
            for (int nj = 0; nj < 4; nj++) {
                int bn = wn * 64 + nj * 16 + (lane & 7) + ((lane >> 4) << 3);
                uint32_t bo = (bn * LDT + k0 + (((lane >> 3) & 1) << 3)) * 2;
                ldm_x4(bhf[nj], sbase + oBhi + bo);
                ldm_x4(blf[nj], sbase + oBlo + bo);
            }
#pragma unroll
            for (int mi = 0; mi < 2; mi++)
#pragma unroll
                for (int j = 0; j < 8; j++) {
                    const uint32_t* bh2 = &bhf[j >> 1][(j & 1) * 2];
                    const uint32_t* bl2 = &blf[j >> 1][(j & 1) * 2];
                    mma_bf16(acc[mi][j], ah[mi], bh2);
                    mma_bf16(acc[mi][j], ah[mi], bl2);
                    mma_bf16(acc[mi][j], al[mi], bh2);
                }
        }
        __syncthreads();
    }

    // ---- epilogues ----
#pragma unroll
    for (int mi = 0; mi < 2; mi++) {
#pragma unroll
        for (int e = 0; e < 2; e++) {
            size_t r = m0 + wm * 32 + mi * 16 + (lane >> 2) + e * 8;
            if (r >= (size_t)M) continue;
#pragma unroll
            for (int j = 0; j < 8; j++) {
                int n = wn * 64 + j * 8 + (lane & 3) * 2;
                float v0 = acc[mi][j][e * 2 + 0];
                float v1 = acc[mi][j][e * 2 + 1];
                if (EPI == 2 || EPI == 4) {
                    if (bias) {
                        v0 += bias[col0 + n];
                        v1 += bias[col0 + n + 1];
                    }
                } else {
                    float g0 = tanhf(v0 + bias[n]);
                    float g1 = tanhf(v1 + bias[n + 1]);
                    v0 = tanhf(hres[r * MEMD + n] + EPS * g0);
                    v1 = tanhf(hres[r * MEMD + n + 1] + EPS * g1);
                }
                if (EPI != 4)
                    *reinterpret_cast<float2*>(C + r * ldc + col0 + n) = make_float2(v0, v1);
                if (EPI == 2) {
                    __nv_bfloat162 hi2 = __floats2bfloat162_rn(v0, v1);
                    float2 hf = __bfloat1622float2(hi2);
                    __nv_bfloat162 lo2 = __floats2bfloat162_rn(v0 - hf.x, v1 - hf.y);
                    *reinterpret_cast<unsigned*>(Chi + r * MEMD + col0 + n) =
                        *reinterpret_cast<unsigned*>(&hi2);
                    *reinterpret_cast<unsigned*>(Clo + r * MEMD + col0 + n) =
                        *reinterpret_cast<unsigned*>(&lo2);
                } else if (EPI == 4) {
                    __nv_bfloat162 hi2 = __floats2bfloat162_rn(v0, v1);
                    *reinterpret_cast<unsigned*>(Chi + r * ldc + col0 + n) =
                        *reinterpret_cast<unsigned*>(&hi2);
                }
            }
        }
    }
}

// ---------------- edge pass: alpha -> exp -> scatter w*h, w*attr ---------------
// alpha = qk'[dst].h[src] + qW[dst].attr (per-dst scalar terms cancel in softmax).
__global__ void edge_kernel(const int* __restrict__ src, const int* __restrict__ dst,
                            const float* __restrict__ msg,
                            const float* __restrict__ lu, const float* __restrict__ tar,
                            const float* __restrict__ wt, const float* __restrict__ bt,
                            int E) {
    int w = (int)(((size_t)blockIdx.x * blockDim.x + threadIdx.x) >> 5);
    int lane = threadIdx.x & 31;
    if (w >= E) return;
    int s = src[w], d = dst[w];
    uint2 qk2 = *reinterpret_cast<const uint2*>(d_qqb + (size_t)d * 256 + lane * 4);
    uint2 qw2 = *reinterpret_cast<const uint2*>(d_qqb + (size_t)d * 256 + 128 + lane * 4);
    uint2 hs2 = *reinterpret_cast<const uint2*>(d_hhi + (size_t)s * MEMD + lane * 4);
    float2 qka = __bfloat1622float2(*reinterpret_cast<__nv_bfloat162*>(&qk2.x));
    float2 qkb = __bfloat1622float2(*reinterpret_cast<__nv_bfloat162*>(&qk2.y));
    float2 qwa = __bfloat1622float2(*reinterpret_cast<__nv_bfloat162*>(&qw2.x));
    float2 qwb = __bfloat1622float2(*reinterpret_cast<__nv_bfloat162*>(&qw2.y));
    float2 hsa = __bfloat1622float2(*reinterpret_cast<__nv_bfloat162*>(&hs2.x));
    float2 hsb = __bfloat1622float2(*reinterpret_cast<__nv_bfloat162*>(&hs2.y));
    float4 at;
    if (lane < 16) {
        at = *reinterpret_cast<const float4*>(msg + (size_t)w * 64 + lane * 4);
    } else {
        float rel = fabsf(lu[s] - tar[w]);
        int j = lane * 4 - 64;
        at.x = __cosf(fmaf(rel, wt[j + 0], bt[j + 0]));
        at.y = __cosf(fmaf(rel, wt[j + 1], bt[j + 1]));
        at.z = __cosf(fmaf(rel, wt[j + 2], bt[j + 2]));
        at.w = __cosf(fmaf(rel, wt[j + 3], bt[j + 3]));
    }
    float p = qka.x * hsa.x + qka.y * hsa.y + qkb.x * hsb.x + qkb.y * hsb.y +
              qwa.x * at.x + qwa.y * at.y + qwb.x * at.z + qwb.y * at.w;
#pragma unroll
    for (int o = 16; o; o >>= 1) p += __shfl_xor_sync(0xFFFFFFFFu, p, o);
    float ex = __expf(p * 0.08838834764831845f);  // 1/sqrt(128); shift-free softmax
    float* pa = d_aggc + (size_t)d * 256;
    asm volatile("red.global.add.v4.f32 [%0], {%1,%2,%3,%4};"
                 :: "l"(pa + lane * 4), "f"(ex * hsa.x), "f"(ex * hsa.y),
                    "f"(ex * hsb.x), "f"(ex * hsb.y) : "memory");
    asm volatile("red.global.add.v4.f32 [%0], {%1,%2,%3,%4};"
                 :: "l"(pa + 128 + lane * 4), "f"(ex * at.x), "f"(ex * at.y),
                    "f"(ex * at.z), "f"(ex * at.w) : "memory");
    if (lane == 0) atomicAdd(&d_denom[d], ex);
}

// ---------------- launch ----------------
extern "C" void kernel_launch(void* const* d_in, const int* in_sizes, int n_in,
                              void* d_out, int out_size) {
    const float* x           = (const float*)d_in[0];
    const float* last_update = (const float*)d_in[1];
    const int*   edge_index  = (const int*)d_in[2];
    const float* t           = (const float*)d_in[3];
    const float* msg         = (const float*)d_in[4];
    const float* w_time      = (const float*)d_in[5];
    const float* b_time      = (const float*)d_in[6];
    const float* W_enc       = (const float*)d_in[7];
    const float* b_enc       = (const float*)d_in[8];
    const float* Wq          = (const float*)d_in[9];
    const float* bq          = (const float*)d_in[10];
    const float* Wk          = (const float*)d_in[11];
    const float* bk          = (const float*)d_in[12];
    const float* Wv          = (const float*)d_in[13];
    const float* bv          = (const float*)d_in[14];
    const float* We          = (const float*)d_in[15];
    const float* W_anti      = (const float*)d_in[16];
    const float* b_anti      = (const float*)d_in[17];

    int Nn = in_sizes[1];
    int Ei = in_sizes[3];
    const int* src = edge_index;
    const int* dst = edge_index + Ei;

    float *h_p, *bqq_p, *bfin_p;
    __nv_bfloat16 *whi_p, *wlo_p, *hhi_p, *hlo_p, *qqb_p;
    cudaGetSymbolAddress((void**)&h_p, d_h);
    cudaGetSymbolAddress((void**)&bqq_p, d_bqq);
    cudaGetSymbolAddress((void**)&bfin_p, d_bfin);
    cudaGetSymbolAddress((void**)&whi_p, d_whi);
    cudaGetSymbolAddress((void**)&wlo_p, d_wlo);
    cudaGetSymbolAddress((void**)&hhi_p, d_hhi);
    cudaGetSymbolAddress((void**)&hlo_p, d_hlo);
    cudaGetSymbolAddress((void**)&qqb_p, d_qqb);

    cudaFuncSetAttribute(mma_gemm<0, 2>, cudaFuncAttributeMaxDynamicSharedMemorySize, SMEM_BYTES);
    cudaFuncSetAttribute(mma_gemm<2, 4>, cudaFuncAttributeMaxDynamicSharedMemorySize, SMEM_BYTES);
    cudaFuncSetAttribute(mma_gemm<3, 1>, cudaFuncAttributeMaxDynamicSharedMemorySize, SMEM_BYTES);

    int nblk = (Nn + 127) / 128;

    prep_kernel<<<(115072 + 255) / 256, 256>>>(W_enc, Wq, bq, Wk, bk, Wv, bv, We,
                                               W_anti, b_anti);
    init_kernel<<<(int)(((size_t)Nn * 256 + 255) / 256), 256>>>(Nn);

    // enc: h = x @ W_enc^T + b_enc; also emit bf16 hi/lo split of h
    mma_gemm<0, 2><<<dim3(1, nblk), 256, SMEM_BYTES>>>(
        x, 256, 256, 4, nullptr, nullptr, whi_p + OFF_ENC, wlo_p + OFF_ENC, b_enc,
        h_p, 128, Nn, nullptr, hhi_p, hlo_p);
    // qq = h @ [M1|M2]^T + [c1|c2]  -> d_qqb [N,256] bf16
    mma_gemm<2, 4><<<dim3(2, nblk), 256, SMEM_BYTES>>>(
        nullptr, 0, 128, 2, hhi_p, hlo_p, whi_p + OFF_QQ, wlo_p + OFF_QQ, bqq_p,
        nullptr, 256, Nn, nullptr, qqb_p, nullptr);
    // edge pass: alpha/exp/scatter
    edge_kernel<<<(Ei + 7) / 8, 256>>>(src, dst, msg, last_update, t, w_time, b_time, Ei);
    // final: out = tanh(h + eps*tanh([h|ah|aa]@[A|Wv|We]^T + b_anti + bv))
    mma_gemm<3, 1><<<dim3(1, nblk), 256, SMEM_BYTES>>>(
        nullptr, 0, 384, 6, hhi_p, hlo_p, whi_p + OFF_FIN, wlo_p + OFF_FIN, bfin_p,
        (float*)d_out, 128, Nn, h_p, nullptr, nullptr);
}

// round 14
// speedup vs baseline: 2.9582x; 1.1515x over previous
#include <cuda_runtime.h>
#include <cuda_bf16.h>
#include <cuda_fp16.h>
#include <math.h>
#include <stdint.h>

#define NN_MAX 100000
#define EE_MAX 500000
#define MEMD 128
#define EPS 0.1f
#define GAM 0.1f

// weight-cat offsets (elements) in the bf16 hi/lo weight store, all [N,K] K-major
#define OFF_ENC 0          // [128,256]  W_enc
#define OFF_QQ 32768       // [256,128]  [M1|M2]: qk' rows 0..127, qW rows 128..255
#define OFF_FIN 65536      // [128,384]  [Aanti | Wv | We]
#define W_TOTAL 114688

#define LDT 72                          // padded SMEM row pitch in bf16 (144B)
#define TILE_ELEMS (128 * LDT)          // per buffer
#define SMEM_BYTES (4 * TILE_ELEMS * 2) // Ahi, Alo, Bhi, Blo = 73728 B

// ---------------- scratch (__device__ globals) ----------------
__device__ __nv_bfloat16 d_hhi[(size_t)NN_MAX * MEMD];
__device__ __nv_bfloat16 d_hlo[(size_t)NN_MAX * MEMD];
__device__ __nv_bfloat16 d_qqb[(size_t)NN_MAX * 256];   // [qk' | qW] bf16
__device__ float d_denom[NN_MAX];
__device__ __half d_aggh[(size_t)NN_MAX * 256];         // [sum w*h | sum w*attr] fp16
__device__ __nv_bfloat16 d_whi[W_TOTAL];
__device__ __nv_bfloat16 d_wlo[W_TOTAL];
__device__ float d_bqq[256];                            // [c1|c2]
__device__ float d_bfin[128];                           // b_anti + bv

// ---------------- PTX helpers --------------------------------------------------
__device__ __forceinline__ uint32_t smem_u32(const void* p) {
    uint32_t a;
    asm("{ .reg .u64 t; cvta.to.shared.u64 t, %1; cvt.u32.u64 %0, t; }" : "=r"(a) : "l"(p));
    return a;
}
__device__ __forceinline__ void ldm_x4(uint32_t* r, uint32_t addr) {
    asm volatile("ldmatrix.sync.aligned.m8n8.x4.shared.b16 {%0,%1,%2,%3}, [%4];"
                 : "=r"(r[0]), "=r"(r[1]), "=r"(r[2]), "=r"(r[3]) : "r"(addr));
}
__device__ __forceinline__ void mma_bf16(float* c, const uint32_t* a, const uint32_t* b) {
    asm volatile(
        "mma.sync.aligned.m16n8k16.row.col.f32.bf16.bf16.f32 "
        "{%0,%1,%2,%3}, {%4,%5,%6,%7}, {%8,%9}, {%0,%1,%2,%3};"
        : "+f"(c[0]), "+f"(c[1]), "+f"(c[2]), "+f"(c[3])
        : "r"(a[0]), "r"(a[1]), "r"(a[2]), "r"(a[3]), "r"(b[0]), "r"(b[1]));
}
__device__ __forceinline__ void cp16(uint32_t saddr, const void* gaddr) {
    asm volatile("cp.async.ca.shared.global [%0], [%1], 16;" :: "r"(saddr), "l"(gaddr));
}
__device__ __forceinline__ void cp16z(uint32_t saddr, const void* gaddr, int srcsz) {
    asm volatile("cp.async.ca.shared.global [%0], [%1], 16, %2;"
                 :: "r"(saddr), "l"(gaddr), "r"(srcsz));
}
__device__ __forceinline__ void cp_commit_wait() {
    asm volatile("cp.async.commit_group;");
    asm volatile("cp.async.wait_group 0;");
}

// ---------------- weight prep: composed matrices + bf16 hi/lo split -----------
__device__ __forceinline__ void split_store(int idx, float v) {
    __nv_bfloat16 hi = __float2bfloat16(v);
    __nv_bfloat16 lo = __float2bfloat16(v - __bfloat162float(hi));
    d_whi[idx] = hi;
    d_wlo[idx] = lo;
}
__global__ void prep_kernel(const float* __restrict__ W_enc,
                            const float* __restrict__ Wq, const float* __restrict__ bq,
                            const float* __restrict__ Wk, const float* __restrict__ bk,
                            const float* __restrict__ Wv, const float* __restrict__ bv,
                            const float* __restrict__ We, const float* __restrict__ W_anti,
                            const float* __restrict__ b_anti) {
    int i = blockIdx.x * blockDim.x + threadIdx.x;
    if (i < 32768) {
        split_store(OFF_ENC + i, W_enc[i]);               // [128,256] direct
    } else if (i < 65536) {
        int j = i - 32768;
        int jo = j / 128, k = j % 128;                    // out col jo, K index k
        float s = 0.0f;
        if (jo < 128) {
            for (int m = 0; m < 128; m++) s += Wk[m * 128 + jo] * Wq[m * 128 + k];
        } else {
            int j2 = jo - 128;
            for (int m = 0; m < 128; m++) s += We[m * 128 + j2] * Wq[m * 128 + k];
        }
        split_store(OFF_QQ + j, s);
    } else if (i < 114688) {
        int j = i - 65536;
        int jo = j / 384, k = j % 384;
        float v;
        if (k < 128) {
            v = W_anti[jo * 128 + k] - W_anti[k * 128 + jo];
            if (jo == k) v -= GAM;
        } else if (k < 256) {
            v = Wv[jo * 128 + (k - 128)];
        } else {
            v = We[jo * 128 + (k - 256)];
        }
        split_store(OFF_FIN + j, v);
    } else if (i < 114944) {
        int j = i - 114688;                               // c1|c2
        float s = 0.0f;
        if (j < 128) {
            for (int m = 0; m < 128; m++) s += bq[m] * Wk[m * 128 + j];
        } else {
            int j2 = j - 128;
            for (int m = 0; m < 128; m++) s += bq[m] * We[m * 128 + j2];
        }
        d_bqq[j] = s;
    } else if (i < 115072) {
        int j = i - 114944;
        d_bfin[j] = b_anti[j] + bv[j];
    }
    // per-dst scalar alpha terms cancel in segment softmax - dropped.
}

// ---------------- init per-call accumulators ----------------
__global__ void init_kernel(int n_nodes) {
    size_t i = (size_t)blockIdx.x * blockDim.x + threadIdx.x;
    if (i < (size_t)n_nodes * 128)
        reinterpret_cast<unsigned*>(d_aggh)[i] = 0u;      // 256 halves per node
    if (i < (size_t)n_nodes) d_denom[i] = 0.0f;
}

// ---------------- warp-MMA GEMM, bf16 hi/lo ------------------------------------
// AMODE 0: A fp32 [M,lda], convert in-kernel (enc).
// AMODE 2: A pre-split bf16 hi/lo (Ah/Al, K=128), staged via cp.async.
// AMODE 3: final: chunks 0-1 from Ah/Al (h); chunks 2-5 from fp16 d_aggh * 1/denom.
// EPI 1: out = tanh((Ah+Al) + eps*tanh(D + bfin)).
// EPI 2: enc: bf16 hi/lo split into Chi/Clo (no fp32 output).
// EPI 4: qq: bf16 output into Chi only (+bias).
// NMMA: 3 = full hi/lo A, 2 = Ahi only (AMODE3: h-chunks always 3, agg-chunks 2).
template <int AMODE, int EPI, int NMMA>
__global__ void __launch_bounds__(256, 2) mma_gemm(
    const float* __restrict__ A, int lda, int K, int nch,
    const __nv_bfloat16* __restrict__ Ah, const __nv_bfloat16* __restrict__ Al,
    const __nv_bfloat16* __restrict__ Bh, const __nv_bfloat16* __restrict__ Bl,
    const float* __restrict__ bias, float* __restrict__ C, int ldc, int M,
    __nv_bfloat16* __restrict__ Chi, __nv_bfloat16* __restrict__ Clo) {
    const int t = threadIdx.x;
    const int lane = t & 31, wid = t >> 5;
    const int wm = wid & 3, wn = wid >> 2;
    const size_t m0 = (size_t)blockIdx.y * 128;
    const int col0 = blockIdx.x * 128;
    const __nv_bfloat16* Bhp = Bh + (size_t)col0 * K;
    const __nv_bfloat16* Blp = Bl + (size_t)col0 * K;

    extern __shared__ __nv_bfloat16 smem[];
    uint32_t sbase = smem_u32(smem);
    const uint32_t oAhi = 0;
    const uint32_t oAlo = TILE_ELEMS * 2;
    const uint32_t oBhi = 2 * TILE_ELEMS * 2;
    const uint32_t oBlo = 3 * TILE_ELEMS * 2;

    float acc[2][8][4];
#pragma unroll
    for (int i = 0; i < 2; i++)
#pragma unroll
        for (int j = 0; j < 8; j++)
#pragma unroll
            for (int e = 0; e < 4; e++) acc[i][j][e] = 0.0f;

    const int tr = t >> 1;            // loader row 0..127
    const int tcc = (t & 1) * 32;     // loader 32-col slab
    const size_t row = m0 + tr;
    const bool valid = row < (size_t)M;

    for (int c = 0; c < nch; c++) {
        const int kc = c * 64;
        const bool uselo = (NMMA == 3) && (AMODE != 3 || c < 2);
        // ---- stage B via cp.async ----
        {
            const __nv_bfloat16* bh = Bhp + (size_t)tr * K + kc + tcc;
            const __nv_bfloat16* bl = Blp + (size_t)tr * K + kc + tcc;
#pragma unroll
            for (int g = 0; g < 4; g++) {
                uint32_t so = (tr * LDT + tcc + g * 8) * 2;
                cp16(sbase + oBhi + so, bh + g * 8);
                cp16(sbase + oBlo + so, bl + g * 8);
            }
        }
        // ---- stage A ----
        if (AMODE == 2 || (AMODE == 3 && c < 2)) {
            const __nv_bfloat16* ah = Ah + row * 128 + kc + tcc;
            const __nv_bfloat16* al = Al + row * 128 + kc + tcc;
            int sz = valid ? 16 : 0;
#pragma unroll
            for (int g = 0; g < 4; g++) {
                uint32_t so = (tr * LDT + tcc + g * 8) * 2;
                cp16z(sbase + oAhi + so, ah + g * 8, sz);
                if (uselo) cp16z(sbase + oAlo + so, al + g * 8, sz);
            }
        } else if (AMODE == 0) {
#pragma unroll
            for (int g = 0; g < 8; g++) {
                float4 v = make_float4(0.f, 0.f, 0.f, 0.f);
                if (valid)
                    v = *reinterpret_cast<const float4*>(A + row * lda + kc + tcc + g * 4);
                __nv_bfloat162 h0 = __floats2bfloat162_rn(v.x, v.y);
                __nv_bfloat162 h1 = __floats2bfloat162_rn(v.z, v.w);
                float2 f0 = __bfloat1622float2(h0);
                float2 f1 = __bfloat1622float2(h1);
                __nv_bfloat162 l0 = __floats2bfloat162_rn(v.x - f0.x, v.y - f0.y);
                __nv_bfloat162 l1 = __floats2bfloat162_rn(v.z - f1.x, v.w - f1.y);
                int idx = tr * LDT + tcc + g * 4;
                *reinterpret_cast<uint2*>(smem + idx) = make_uint2(
                    *reinterpret_cast<unsigned*>(&h0), *reinterpret_cast<unsigned*>(&h1));
                *reinterpret_cast<uint2*>(smem + TILE_ELEMS + idx) = make_uint2(
                    *reinterpret_cast<unsigned*>(&l0), *reinterpret_cast<unsigned*>(&l1));
            }
        } else {  // AMODE 3, c >= 2: normalized fp16 aggregates, hi only
            float rden = 0.0f;
            if (valid) rden = 1.0f / (d_denom[row] + 1e-16f);
#pragma unroll
            for (int g = 0; g < 8; g++) {
                float4 v = make_float4(0.f, 0.f, 0.f, 0.f);
                if (valid) {
                    uint2 u = *reinterpret_cast<const uint2*>(
                        d_aggh + row * 256 + (kc - 128) + tcc + g * 4);
                    float2 f0 = __half22float2(*reinterpret_cast<__half2*>(&u.x));
                    float2 f1 = __half22float2(*reinterpret_cast<__half2*>(&u.y));
                    v = make_float4(f0.x * rden, f0.y * rden, f1.x * rden, f1.y * rden);
                }
                __nv_bfloat162 h0 = __floats2bfloat162_rn(v.x, v.y);
                __nv_bfloat162 h1 = __floats2bfloat162_rn(v.z, v.w);
                int idx = tr * LDT + tcc + g * 4;
                *reinterpret_cast<uint2*>(smem + idx) = make_uint2(
                    *reinterpret_cast<unsigned*>(&h0), *reinterpret_cast<unsigned*>(&h1));
            }
        }
        cp_commit_wait();
        __syncthreads();
        // ---- compute: 4 k-steps of 16 ----
#pragma unroll
        for (int ks = 0; ks < 4; ks++) {
            const int k0 = ks * 16;
            uint32_t ah[2][4], al[2][4];
#pragma unroll
            for (int mi = 0; mi < 2; mi++) {
                uint32_t ao =
                    ((wm * 32 + mi * 16 + (lane & 15)) * LDT + k0 + ((lane >> 4) << 3)) * 2;
                ldm_x4(ah[mi], sbase + oAhi + ao);
                if (uselo) ldm_x4(al[mi], sbase + oAlo + ao);
            }
            uint32_t bhf[4][4], blf[4][4];
#pragma unroll
            for (int nj = 0; nj < 4; nj++) {
                int bn = wn * 64 + nj * 16 + (lane & 7) + ((lane >> 4) << 3);
                uint32_t bo = (bn * LDT + k0 + (((lane >> 3) & 1) << 3)) * 2;
                ldm_x4(bhf[nj], sbase + oBhi + bo);
                ldm_x4(blf[nj], sbase + oBlo + bo);
            }
#pragma unroll
            for (int mi = 0; mi < 2; mi++)
#pragma unroll
                for (int j = 0; j < 8; j++) {
                    const uint32_t* bh2 = &bhf[j >> 1][(j & 1) * 2];
                    const uint32_t* bl2 = &blf[j >> 1][(j & 1) * 2];
                    mma_bf16(acc[mi][j], ah[mi], bh2);
                    mma_bf16(acc[mi][j], ah[mi], bl2);
                    if (uselo) mma_bf16(acc[mi][j], al[mi], bh2);
                }
        }
        __syncthreads();
    }

    // ---- epilogues ----
#pragma unroll
    for (int mi = 0; mi < 2; mi++) {
#pragma unroll
        for (int e = 0; e < 2; e++) {
            size_t r = m0 + wm * 32 + mi * 16 + (lane >> 2) + e * 8;
            if (r >= (size_t)M) continue;
#pragma unroll
            for (int j = 0; j < 8; j++) {
                int n = wn * 64 + j * 8 + (lane & 3) * 2;
                float v0 = acc[mi][j][e * 2 + 0];
                float v1 = acc[mi][j][e * 2 + 1];
                if (EPI == 2 || EPI == 4) {
                    if (bias) {
                        v0 += bias[col0 + n];
                        v1 += bias[col0 + n + 1];
                    }
                } else {  // EPI 1: reconstruct h from hi/lo, fused CTAN epilogue
                    float2 hi = __bfloat1622float2(
                        *reinterpret_cast<const __nv_bfloat162*>(Ah + r * MEMD + n));
                    float2 lo = __bfloat1622float2(
                        *reinterpret_cast<const __nv_bfloat162*>(Al + r * MEMD + n));
                    float g0 = tanhf(v0 + bias[n]);
                    float g1 = tanhf(v1 + bias[n + 1]);
                    v0 = tanhf(hi.x + lo.x + EPS * g0);
                    v1 = tanhf(hi.y + lo.y + EPS * g1);
                }
                if (EPI == 1)
                    *reinterpret_cast<float2*>(C + r * ldc + col0 + n) = make_float2(v0, v1);
                if (EPI == 2) {
                    __nv_bfloat162 hi2 = __floats2bfloat162_rn(v0, v1);
                    float2 hf = __bfloat1622float2(hi2);
                    __nv_bfloat162 lo2 = __floats2bfloat162_rn(v0 - hf.x, v1 - hf.y);
                    *reinterpret_cast<unsigned*>(Chi + r * MEMD + col0 + n) =
                        *reinterpret_cast<unsigned*>(&hi2);
                    *reinterpret_cast<unsigned*>(Clo + r * MEMD + col0 + n) =
                        *reinterpret_cast<unsigned*>(&lo2);
                } else if (EPI == 4) {
                    __nv_bfloat162 hi2 = __floats2bfloat162_rn(v0, v1);
                    *reinterpret_cast<unsigned*>(Chi + r * ldc + col0 + n) =
                        *reinterpret_cast<unsigned*>(&hi2);
                }
            }
        }
    }
}

// ---------------- edge pass: alpha -> exp -> single fp16 vector scatter --------
// lane i owns elements [8i,8i+8) of the 256-wide [h | msg | timefeat] row.
// alpha = qq[dst].row; scatter ex*row as one red.v4.f16x2; ex scaled 2^-4
// (cancels in agg/denom). Per-dst scalar alpha terms cancel in softmax.
__global__ void edge_kernel(const int* __restrict__ src, const int* __restrict__ dst,
                            const float* __restrict__ msg,
                            const float* __restrict__ lu, const float* __restrict__ tar,
                            const float* __restrict__ wt, const float* __restrict__ bt,
                            int E) {
    int w = (int)(((size_t)blockIdx.x * blockDim.x + threadIdx.x) >> 5);
    int lane = threadIdx.x & 31;
    if (w >= E) return;
    int s = src[w], d = dst[w];
    uint4 qq4 = *reinterpret_cast<const uint4*>(d_qqb + (size_t)d * 256 + lane * 8);
    float q[8];
    {
        const __nv_bfloat162* qp = reinterpret_cast<const __nv_bfloat162*>(&qq4);
#pragma unroll
        for (int k = 0; k < 4; k++) {
            float2 f = __bfloat1622float2(qp[k]);
            q[2 * k] = f.x;
            q[2 * k + 1] = f.y;
        }
    }
    float o[8];
    if (lane < 16) {
        uint4 h4 = *reinterpret_cast<const uint4*>(d_hhi + (size_t)s * MEMD + lane * 8);
        const __nv_bfloat162* hp = reinterpret_cast<const __nv_bfloat162*>(&h4);
#pragma unroll
        for (int k = 0; k < 4; k++) {
            float2 f = __bfloat1622float2(hp[k]);
            o[2 * k] = f.x;
            o[2 * k + 1] = f.y;
        }
    } else if (lane < 24) {
        const float4* mp =
            reinterpret_cast<const float4*>(msg + (size_t)w * 64 + (lane - 16) * 8);
        float4 a = mp[0], b = mp[1];
        o[0] = a.x; o[1] = a.y; o[2] = a.z; o[3] = a.w;
        o[4] = b.x; o[5] = b.y; o[6] = b.z; o[7] = b.w;
    } else {
        float rel = fabsf(lu[s] - tar[w]);
        int j = (lane - 24) * 8;
#pragma unroll
        for (int k = 0; k < 8; k++)
            o[k] = __cosf(fmaf(rel, wt[j + k], bt[j + k]));
    }
    float p = 0.0f;
#pragma unroll
    for (int k = 0; k < 8; k++) p += q[k] * o[k];
#pragma unroll
    for (int off = 16; off; off >>= 1) p += __shfl_xor_sync(0xFFFFFFFFu, p, off);
    float ex = __expf(p * 0.08838834764831845f) * 0.0625f;  // 1/sqrt(128); 2^-4 scale
    __half2 p0 = __floats2half2_rn(ex * o[0], ex * o[1]);
    __half2 p1 = __floats2half2_rn(ex * o[2], ex * o[3]);
    __half2 p2 = __floats2half2_rn(ex * o[4], ex * o[5]);
    __half2 p3 = __floats2half2_rn(ex * o[6], ex * o[7]);
    __half* pa = d_aggh + (size_t)d * 256 + lane * 8;
    asm volatile("red.global.add.noftz.v4.f16x2 [%0], {%1,%2,%3,%4};"
                 :: "l"(pa), "r"(*reinterpret_cast<unsigned*>(&p0)),
                    "r"(*reinterpret_cast<unsigned*>(&p1)),
                    "r"(*reinterpret_cast<unsigned*>(&p2)),
                    "r"(*reinterpret_cast<unsigned*>(&p3))
                 : "memory");
    if (lane == 0) atomicAdd(&d_denom[d], ex);
}

// ---------------- launch ----------------
extern "C" void kernel_launch(void* const* d_in, const int* in_sizes, int n_in,
                              void* d_out, int out_size) {
    const float* x           = (const float*)d_in[0];
    const float* last_update = (const float*)d_in[1];
    const int*   edge_index  = (const int*)d_in[2];
    const float* t           = (const float*)d_in[3];
    const float* msg         = (const float*)d_in[4];
    const float* w_time      = (const float*)d_in[5];
    const float* b_time      = (const float*)d_in[6];
    const float* W_enc       = (const float*)d_in[7];
    const float* b_enc       = (const float*)d_in[8];
    const float* Wq          = (const float*)d_in[9];
    const float* bq          = (const float*)d_in[10];
    const float* Wk          = (const float*)d_in[11];
    const float* bk          = (const float*)d_in[12];
    const float* Wv          = (const float*)d_in[13];
    const float* bv          = (const float*)d_in[14];
    const float* We          = (const float*)d_in[15];
    const float* W_anti      = (const float*)d_in[16];
    const float* b_anti      = (const float*)d_in[17];

    int Nn = in_sizes[1];
    int Ei = in_sizes[3];
    const int* src = edge_index;
    const int* dst = edge_index + Ei;

    float *bqq_p, *bfin_p;
    __nv_bfloat16 *whi_p, *wlo_p, *hhi_p, *hlo_p, *qqb_p;
    cudaGetSymbolAddress((void**)&bqq_p, d_bqq);
    cudaGetSymbolAddress((void**)&bfin_p, d_bfin);
    cudaGetSymbolAddress((void**)&whi_p, d_whi);
    cudaGetSymbolAddress((void**)&wlo_p, d_wlo);
    cudaGetSymbolAddress((void**)&hhi_p, d_hhi);
    cudaGetSymbolAddress((void**)&hlo_p, d_hlo);
    cudaGetSymbolAddress((void**)&qqb_p, d_qqb);

    cudaFuncSetAttribute(mma_gemm<0, 2, 3>, cudaFuncAttributeMaxDynamicSharedMemorySize,
                         SMEM_BYTES);
    cudaFuncSetAttribute(mma_gemm<2, 4, 2>, cudaFuncAttributeMaxDynamicSharedMemorySize,
                         SMEM_BYTES);
    cudaFuncSetAttribute(mma_gemm<3, 1, 3>, cudaFuncAttributeMaxDynamicSharedMemorySize,
                         SMEM_BYTES);

    int nblk = (Nn + 127) / 128;

    prep_kernel<<<(115072 + 255) / 256, 256>>>(W_enc, Wq, bq, Wk, bk, Wv, bv, We,
                                               W_anti, b_anti);
    init_kernel<<<(int)(((size_t)Nn * 128 + 255) / 256), 256>>>(Nn);

    // enc: h = x @ W_enc^T + b_enc -> bf16 hi/lo only
    mma_gemm<0, 2, 3><<<dim3(1, nblk), 256, SMEM_BYTES>>>(
        x, 256, 256, 4, nullptr, nullptr, whi_p + OFF_ENC, wlo_p + OFF_ENC, b_enc,
        nullptr, 0, Nn, hhi_p, hlo_p);
    // qq = h @ [M1|M2]^T + [c1|c2]  -> d_qqb [N,256] bf16 (2-MMA path)
    mma_gemm<2, 4, 2><<<dim3(2, nblk), 256, SMEM_BYTES>>>(
        nullptr, 0, 128, 2, hhi_p, hlo_p, whi_p + OFF_QQ, wlo_p + OFF_QQ, bqq_p,
        nullptr, 256, Nn, qqb_p, nullptr);
    // edge pass: alpha/exp/fp16 vector scatter
    edge_kernel<<<(Ei + 7) / 8, 256>>>(src, dst, msg, last_update, t, w_time, b_time, Ei);
    // final: out = tanh(h + eps*tanh([h|ah|aa]@[A|Wv|We]^T + b_anti + bv))
    mma_gemm<3, 1, 3><<<dim3(1, nblk), 256, SMEM_BYTES>>>(
        nullptr, 0, 384, 6, hhi_p, hlo_p, whi_p + OFF_FIN, wlo_p + OFF_FIN, bfin_p,
        (float*)d_out, 128, Nn, nullptr, nullptr);
}

// round 16
// speedup vs baseline: 3.0129x; 1.0185x over previous
#include <cuda_runtime.h>
#include <cuda_bf16.h>
#include <cuda_fp16.h>
#include <math.h>
#include <stdint.h>

#define NN_MAX 100000
#define EE_MAX 500000
#define MEMD 128
#define EPS 0.1f
#define GAM 0.1f

// weight-cat offsets (elements) in the bf16 hi/lo weight store, all [N,K] K-major
#define OFF_ENC 0          // [128,256]  W_enc
#define OFF_QQ 32768       // [256,128]  [M1|M2]: qk' rows 0..127, qW rows 128..255
#define OFF_FIN 65536      // [128,384]  [Aanti | Wv | We]
#define W_TOTAL 114688

#define LDT 72                          // padded SMEM row pitch in bf16 (144B)
#define TILE_ELEMS (128 * LDT)          // per buffer
#define SMEM_BYTES (4 * TILE_ELEMS * 2) // Ahi, Alo, Bhi, Blo = 73728 B

// ---------------- scratch (__device__ globals) ----------------
__device__ __nv_bfloat16 d_hhi[(size_t)NN_MAX * MEMD];
__device__ __nv_bfloat16 d_hlo[(size_t)NN_MAX * MEMD];
__device__ __nv_bfloat16 d_qqb[(size_t)NN_MAX * 256];   // [qk' | qW] bf16
__device__ float d_denom[NN_MAX];
__device__ __half d_aggh[(size_t)NN_MAX * 256];         // [sum w*h | sum w*attr] fp16
__device__ __nv_bfloat16 d_whi[W_TOTAL];
__device__ __nv_bfloat16 d_wlo[W_TOTAL];
__device__ float d_bqq[256];                            // [c1|c2]
__device__ float d_bfin[128];                           // b_anti + bv

// ---------------- PTX helpers --------------------------------------------------
__device__ __forceinline__ uint32_t smem_u32(const void* p) {
    uint32_t a;
    asm("{ .reg .u64 t; cvta.to.shared.u64 t, %1; cvt.u32.u64 %0, t; }" : "=r"(a) : "l"(p));
    return a;
}
__device__ __forceinline__ void ldm_x4(uint32_t* r, uint32_t addr) {
    asm volatile("ldmatrix.sync.aligned.m8n8.x4.shared.b16 {%0,%1,%2,%3}, [%4];"
                 : "=r"(r[0]), "=r"(r[1]), "=r"(r[2]), "=r"(r[3]) : "r"(addr));
}
__device__ __forceinline__ void mma_bf16(float* c, const uint32_t* a, const uint32_t* b) {
    asm volatile(
        "mma.sync.aligned.m16n8k16.row.col.f32.bf16.bf16.f32 "
        "{%0,%1,%2,%3}, {%4,%5,%6,%7}, {%8,%9}, {%0,%1,%2,%3};"
        : "+f"(c[0]), "+f"(c[1]), "+f"(c[2]), "+f"(c[3])
        : "r"(a[0]), "r"(a[1]), "r"(a[2]), "r"(a[3]), "r"(b[0]), "r"(b[1]));
}
__device__ __forceinline__ void cp16(uint32_t saddr, const void* gaddr) {
    asm volatile("cp.async.ca.shared.global [%0], [%1], 16;" :: "r"(saddr), "l"(gaddr));
}
__device__ __forceinline__ void cp16z(uint32_t saddr, const void* gaddr, int srcsz) {
    asm volatile("cp.async.ca.shared.global [%0], [%1], 16, %2;"
                 :: "r"(saddr), "l"(gaddr), "r"(srcsz));
}
__device__ __forceinline__ void cp_commit_wait() {
    asm volatile("cp.async.commit_group;");
    asm volatile("cp.async.wait_group 0;");
}
__device__ __forceinline__ float tanh_fast(float x) {
    float r;
    asm("tanh.approx.f32 %0, %1;" : "=f"(r) : "f"(x));
    return r;
}

// ---------------- weight prep + per-call accumulator init (merged) -------------
__device__ __forceinline__ void split_store(int idx, float v) {
    __nv_bfloat16 hi = __float2bfloat16(v);
    __nv_bfloat16 lo = __float2bfloat16(v - __bfloat162float(hi));
    d_whi[idx] = hi;
    d_wlo[idx] = lo;
}
__global__ void prep_kernel(const float* __restrict__ W_enc,
                            const float* __restrict__ Wq, const float* __restrict__ bq,
                            const float* __restrict__ Wk, const float* __restrict__ bk,
                            const float* __restrict__ Wv, const float* __restrict__ bv,
                            const float* __restrict__ We, const float* __restrict__ W_anti,
                            const float* __restrict__ b_anti, int n_nodes) {
    size_t i = (size_t)blockIdx.x * blockDim.x + threadIdx.x;
    // per-call accumulator init
    if (i < (size_t)n_nodes * 128)
        reinterpret_cast<unsigned*>(d_aggh)[i] = 0u;      // 256 halves per node
    if (i < (size_t)n_nodes) d_denom[i] = 0.0f;
    // weight composition (graph replays recompute; deterministic)
    if (i < 32768) {
        split_store(OFF_ENC + (int)i, W_enc[i]);          // [128,256] direct
    } else if (i < 65536) {
        int j = (int)i - 32768;
        int jo = j / 128, k = j % 128;                    // out col jo, K index k
        float s = 0.0f;
        if (jo < 128) {
            for (int m = 0; m < 128; m++) s += Wk[m * 128 + jo] * Wq[m * 128 + k];
        } else {
            int j2 = jo - 128;
            for (int m = 0; m < 128; m++) s += We[m * 128 + j2] * Wq[m * 128 + k];
        }
        split_store(OFF_QQ + j, s);
    } else if (i < 114688) {
        int j = (int)i - 65536;
        int jo = j / 384, k = j % 384;
        float v;
        if (k < 128) {
            v = W_anti[jo * 128 + k] - W_anti[k * 128 + jo];
            if (jo == k) v -= GAM;
        } else if (k < 256) {
            v = Wv[jo * 128 + (k - 128)];
        } else {
            v = We[jo * 128 + (k - 256)];
        }
        split_store(OFF_FIN + j, v);
    } else if (i < 114944) {
        int j = (int)i - 114688;                          // c1|c2
        float s = 0.0f;
        if (j < 128) {
            for (int m = 0; m < 128; m++) s += bq[m] * Wk[m * 128 + j];
        } else {
            int j2 = j - 128;
            for (int m = 0; m < 128; m++) s += bq[m] * We[m * 128 + j2];
        }
        d_bqq[j] = s;
    } else if (i < 115072) {
        int j = (int)i - 114944;
        d_bfin[j] = b_anti[j] + bv[j];
    }
    // per-dst scalar alpha terms cancel in segment softmax - dropped.
}

// ---------------- fused enc + qq kernel ----------------------------------------
// Phase 1: h = x @ W_enc^T + b_enc (K=256, 3-MMA hi/lo). Writes hhi/hlo to gmem
//          and stages h-hi into the A smem buffers.
// Phase 2: qq = h @ [M1|M2]^T + [c1|c2] (K=128, 2-MMA, A-hi from smem),
//          two 128-col output halves sequentially, acc reused. bf16 out to qqb.
__global__ void __launch_bounds__(256, 2) enc_qq_kernel(
    const float* __restrict__ x, int M,
    const __nv_bfloat16* __restrict__ Wh, const __nv_bfloat16* __restrict__ Wl,
    const float* __restrict__ b_enc) {
    const int t = threadIdx.x;
    const int lane = t & 31, wid = t >> 5;
    const int wm = wid & 3, wn = wid >> 2;
    const size_t m0 = (size_t)blockIdx.y * 128;

    extern __shared__ __nv_bfloat16 smem[];
    uint32_t sbase = smem_u32(smem);
    const uint32_t oAhi = 0;
    const uint32_t oAlo = TILE_ELEMS * 2;
    const uint32_t oBhi = 2 * TILE_ELEMS * 2;
    const uint32_t oBlo = 3 * TILE_ELEMS * 2;

    float acc[2][8][4];
#pragma unroll
    for (int i = 0; i < 2; i++)
#pragma unroll
        for (int j = 0; j < 8; j++)
#pragma unroll
            for (int e = 0; e < 4; e++) acc[i][j][e] = 0.0f;

    const int tr = t >> 1;
    const int tcc = (t & 1) * 32;
    const size_t row = m0 + tr;
    const bool valid = row < (size_t)M;

    // ---- Phase 1 mainloop: K=256, 4 chunks ----
    const __nv_bfloat16* Bhp = Wh + OFF_ENC;   // [128,256]
    const __nv_bfloat16* Blp = Wl + OFF_ENC;
    for (int c = 0; c < 4; c++) {
        const int kc = c * 64;
        {
            const __nv_bfloat16* bh = Bhp + (size_t)tr * 256 + kc + tcc;
            const __nv_bfloat16* bl = Blp + (size_t)tr * 256 + kc + tcc;
#pragma unroll
            for (int g = 0; g < 4; g++) {
                uint32_t so = (tr * LDT + tcc + g * 8) * 2;
                cp16(sbase + oBhi + so, bh + g * 8);
                cp16(sbase + oBlo + so, bl + g * 8);
            }
        }
#pragma unroll
        for (int g = 0; g < 8; g++) {
            float4 v = make_float4(0.f, 0.f, 0.f, 0.f);
            if (valid)
                v = *reinterpret_cast<const float4*>(x + row * 256 + kc + tcc + g * 4);
            __nv_bfloat162 h0 = __floats2bfloat162_rn(v.x, v.y);
            __nv_bfloat162 h1 = __floats2bfloat162_rn(v.z, v.w);
            float2 f0 = __bfloat1622float2(h0);
            float2 f1 = __bfloat1622float2(h1);
            __nv_bfloat162 l0 = __floats2bfloat162_rn(v.x - f0.x, v.y - f0.y);
            __nv_bfloat162 l1 = __floats2bfloat162_rn(v.z - f1.x, v.w - f1.y);
            int idx = tr * LDT + tcc + g * 4;
            *reinterpret_cast<uint2*>(smem + idx) = make_uint2(
                *reinterpret_cast<unsigned*>(&h0), *reinterpret_cast<unsigned*>(&h1));
            *reinterpret_cast<uint2*>(smem + TILE_ELEMS + idx) = make_uint2(
                *reinterpret_cast<unsigned*>(&l0), *reinterpret_cast<unsigned*>(&l1));
        }
        cp_commit_wait();
        __syncthreads();
#pragma unroll
        for (int ks = 0; ks < 4; ks++) {
            const int k0 = ks * 16;
            uint32_t ah[2][4], al[2][4];
#pragma unroll
            for (int mi = 0; mi < 2; mi++) {
                uint32_t ao =
                    ((wm * 32 + mi * 16 + (lane & 15)) * LDT + k0 + ((lane >> 4) << 3)) * 2;
                ldm_x4(ah[mi], sbase + oAhi + ao);
                ldm_x4(al[mi], sbase + oAlo + ao);
            }
            uint32_t bhf[4][4], blf[4][4];
#pragma unroll
            for (int nj = 0; nj < 4; nj++) {
                int bn = wn * 64 + nj * 16 + (lane & 7) + ((lane >> 4) << 3);
                uint32_t bo = (bn * LDT + k0 + (((lane >> 3) & 1) << 3)) * 2;
                ldm_x4(bhf[nj], sbase + oBhi + bo);
                ldm_x4(blf[nj], sbase + oBlo + bo);
            }
#pragma unroll
            for (int mi = 0; mi < 2; mi++)
#pragma unroll
                for (int j = 0; j < 8; j++) {
                    const uint32_t* bh2 = &bhf[j >> 1][(j & 1) * 2];
                    const uint32_t* bl2 = &blf[j >> 1][(j & 1) * 2];
                    mma_bf16(acc[mi][j], ah[mi], bh2);
                    mma_bf16(acc[mi][j], ah[mi], bl2);
                    mma_bf16(acc[mi][j], al[mi], bh2);
                }
        }
        __syncthreads();
    }

    // ---- Phase 1 epilogue: h -> gmem hi/lo, h-hi -> A smem buffers ----
    // h cols [0,64) -> oAhi buffer, cols [64,128) -> oAlo buffer (qq K staging).
#pragma unroll
    for (int mi = 0; mi < 2; mi++) {
#pragma unroll
        for (int e = 0; e < 2; e++) {
            int rl = wm * 32 + mi * 16 + (lane >> 2) + e * 8;
            size_t r = m0 + rl;
#pragma unroll
            for (int j = 0; j < 8; j++) {
                int n = wn * 64 + j * 8 + (lane & 3) * 2;
                float v0 = acc[mi][j][e * 2 + 0] + b_enc[n];
                float v1 = acc[mi][j][e * 2 + 1] + b_enc[n + 1];
                __nv_bfloat162 hi2 = __floats2bfloat162_rn(v0, v1);
                float2 hf = __bfloat1622float2(hi2);
                __nv_bfloat162 lo2 = __floats2bfloat162_rn(v0 - hf.x, v1 - hf.y);
                if (r < (size_t)M) {
                    *reinterpret_cast<unsigned*>(d_hhi + r * MEMD + n) =
                        *reinterpret_cast<unsigned*>(&hi2);
                    *reinterpret_cast<unsigned*>(d_hlo + r * MEMD + n) =
                        *reinterpret_cast<unsigned*>(&lo2);
                }
                int idx = wn * TILE_ELEMS + rl * LDT + (n - wn * 64);
                *reinterpret_cast<unsigned*>(smem + idx) = *reinterpret_cast<unsigned*>(&hi2);
            }
        }
    }
    __syncthreads();

    // ---- Phase 2: qq, two output col-halves, K=128 (A-hi in smem) ----
    for (int ch = 0; ch < 2; ch++) {
        const int colq = ch * 128;
        const __nv_bfloat16* Bqh = Wh + OFF_QQ + (size_t)colq * 128;
        const __nv_bfloat16* Bql = Wl + OFF_QQ + (size_t)colq * 128;
#pragma unroll
        for (int i = 0; i < 2; i++)
#pragma unroll
            for (int j = 0; j < 8; j++)
#pragma unroll
                for (int e = 0; e < 4; e++) acc[i][j][e] = 0.0f;
        for (int c = 0; c < 2; c++) {
            const int kc = c * 64;
            {
                const __nv_bfloat16* bh = Bqh + (size_t)tr * 128 + kc + tcc;
                const __nv_bfloat16* bl = Bql + (size_t)tr * 128 + kc + tcc;
#pragma unroll
                for (int g = 0; g < 4; g++) {
                    uint32_t so = (tr * LDT + tcc + g * 8) * 2;
                    cp16(sbase + oBhi + so, bh + g * 8);
                    cp16(sbase + oBlo + so, bl + g * 8);
                }
            }
            cp_commit_wait();
            __syncthreads();
            const uint32_t oA = (c == 0) ? oAhi : oAlo;
#pragma unroll
            for (int ks = 0; ks < 4; ks++) {
                const int k0 = ks * 16;
                uint32_t ah[2][4];
#pragma unroll
                for (int mi = 0; mi < 2; mi++) {
                    uint32_t ao =
                        ((wm * 32 + mi * 16 + (lane & 15)) * LDT + k0 + ((lane >> 4) << 3)) * 2;
                    ldm_x4(ah[mi], sbase + oA + ao);
                }
                uint32_t bhf[4][4], blf[4][4];
#pragma unroll
                for (int nj = 0; nj < 4; nj++) {
                    int bn = wn * 64 + nj * 16 + (lane & 7) + ((lane >> 4) << 3);
                    uint32_t bo = (bn * LDT + k0 + (((lane >> 3) & 1) << 3)) * 2;
                    ldm_x4(bhf[nj], sbase + oBhi + bo);
                    ldm_x4(blf[nj], sbase + oBlo + bo);
                }
#pragma unroll
                for (int mi = 0; mi < 2; mi++)
#pragma unroll
                    for (int j = 0; j < 8; j++) {
                        mma_bf16(acc[mi][j], ah[mi], &bhf[j >> 1][(j & 1) * 2]);
                        mma_bf16(acc[mi][j], ah[mi], &blf[j >> 1][(j & 1) * 2]);
                    }
            }
            __syncthreads();
        }
        // qq epilogue: bf16 out
#pragma unroll
        for (int mi = 0; mi < 2; mi++) {
#pragma unroll
            for (int e = 0; e < 2; e++) {
                size_t r = m0 + wm * 32 + mi * 16 + (lane >> 2) + e * 8;
                if (r >= (size_t)M) continue;
#pragma unroll
                for (int j = 0; j < 8; j++) {
                    int n = wn * 64 + j * 8 + (lane & 3) * 2;
                    float v0 = acc[mi][j][e * 2 + 0] + d_bqq[colq + n];
                    float v1 = acc[mi][j][e * 2 + 1] + d_bqq[colq + n + 1];
                    __nv_bfloat162 hi2 = __floats2bfloat162_rn(v0, v1);
                    *reinterpret_cast<unsigned*>(d_qqb + r * 256 + colq + n) =
                        *reinterpret_cast<unsigned*>(&hi2);
                }
            }
        }
    }
}

// ---------------- final GEMM: out = tanh(h + eps*tanh([h|agg]@W^T + bfin)) -----
// chunks 0-1: A = h hi/lo (3-MMA); chunks 2-5: A = fp16 agg * 1/denom (2-MMA).
__global__ void __launch_bounds__(256, 2) final_gemm(
    int M, const __nv_bfloat16* __restrict__ Wh, const __nv_bfloat16* __restrict__ Wl,
    float* __restrict__ Cout) {
    const int t = threadIdx.x;
    const int lane = t & 31, wid = t >> 5;
    const int wm = wid & 3, wn = wid >> 2;
    const size_t m0 = (size_t)blockIdx.y * 128;
    const __nv_bfloat16* Bhp = Wh + OFF_FIN;
    const __nv_bfloat16* Blp = Wl + OFF_FIN;

    extern __shared__ __nv_bfloat16 smem[];
    uint32_t sbase = smem_u32(smem);
    const uint32_t oAhi = 0;
    const uint32_t oAlo = TILE_ELEMS * 2;
    const uint32_t oBhi = 2 * TILE_ELEMS * 2;
    const uint32_t oBlo = 3 * TILE_ELEMS * 2;

    float acc[2][8][4];
#pragma unroll
    for (int i = 0; i < 2; i++)
#pragma unroll
        for (int j = 0; j < 8; j++)
#pragma unroll
            for (int e = 0; e < 4; e++) acc[i][j][e] = 0.0f;

    const int tr = t >> 1;
    const int tcc = (t & 1) * 32;
    const size_t row = m0 + tr;
    const bool valid = row < (size_t)M;

    for (int c = 0; c < 6; c++) {
        const int kc = c * 64;
        const bool hchunk = (c < 2);
        {
            const __nv_bfloat16* bh = Bhp + (size_t)tr * 384 + kc + tcc;
            const __nv_bfloat16* bl = Blp + (size_t)tr * 384 + kc + tcc;
#pragma unroll
            for (int g = 0; g < 4; g++) {
                uint32_t so = (tr * LDT + tcc + g * 8) * 2;
                cp16(sbase + oBhi + so, bh + g * 8);
                cp16(sbase + oBlo + so, bl + g * 8);
            }
        }
        if (hchunk) {
            const __nv_bfloat16* ah = d_hhi + row * 128 + kc + tcc;
            const __nv_bfloat16* al = d_hlo + row * 128 + kc + tcc;
            int sz = valid ? 16 : 0;
#pragma unroll
            for (int g = 0; g < 4; g++) {
                uint32_t so = (tr * LDT + tcc + g * 8) * 2;
                cp16z(sbase + oAhi + so, ah + g * 8, sz);
                cp16z(sbase + oAlo + so, al + g * 8, sz);
            }
        } else {
            float rden = 0.0f;
            if (valid) rden = 1.0f / (d_denom[row] + 1e-16f);
#pragma unroll
            for (int g = 0; g < 8; g++) {
                float4 v = make_float4(0.f, 0.f, 0.f, 0.f);
                if (valid) {
                    uint2 u = *reinterpret_cast<const uint2*>(
                        d_aggh + row * 256 + (kc - 128) + tcc + g * 4);
                    float2 f0 = __half22float2(*reinterpret_cast<__half2*>(&u.x));
                    float2 f1 = __half22float2(*reinterpret_cast<__half2*>(&u.y));
                    v = make_float4(f0.x * rden, f0.y * rden, f1.x * rden, f1.y * rden);
                }
                __nv_bfloat162 h0 = __floats2bfloat162_rn(v.x, v.y);
                __nv_bfloat162 h1 = __floats2bfloat162_rn(v.z, v.w);
                int idx = tr * LDT + tcc + g * 4;
                *reinterpret_cast<uint2*>(smem + idx) = make_uint2(
                    *reinterpret_cast<unsigned*>(&h0), *reinterpret_cast<unsigned*>(&h1));
            }
        }
        cp_commit_wait();
        __syncthreads();
#pragma unroll
        for (int ks = 0; ks < 4; ks++) {
            const int k0 = ks * 16;
            uint32_t ah[2][4], al[2][4];
#pragma unroll
            for (int mi = 0; mi < 2; mi++) {
                uint32_t ao =
                    ((wm * 32 + mi * 16 + (lane & 15)) * LDT + k0 + ((lane >> 4) << 3)) * 2;
                ldm_x4(ah[mi], sbase + oAhi + ao);
                if (hchunk) ldm_x4(al[mi], sbase + oAlo + ao);
            }
            uint32_t bhf[4][4], blf[4][4];
#pragma unroll
            for (int nj = 0; nj < 4; nj++) {
                int bn = wn * 64 + nj * 16 + (lane & 7) + ((lane >> 4) << 3);
                uint32_t bo = (bn * LDT + k0 + (((lane >> 3) & 1) << 3)) * 2;
                ldm_x4(bhf[nj], sbase + oBhi + bo);
                ldm_x4(blf[nj], sbase + oBlo + bo);
            }
#pragma unroll
            for (int mi = 0; mi < 2; mi++)
#pragma unroll
                for (int j = 0; j < 8; j++) {
                    const uint32_t* bh2 = &bhf[j >> 1][(j & 1) * 2];
                    const uint32_t* bl2 = &blf[j >> 1][(j & 1) * 2];
                    mma_bf16(acc[mi][j], ah[mi], bh2);
                    mma_bf16(acc[mi][j], ah[mi], bl2);
                    if (hchunk) mma_bf16(acc[mi][j], al[mi], bh2);
                }
        }
        __syncthreads();
    }

    // ---- CTAN epilogue ----
#pragma unroll
    for (int mi = 0; mi < 2; mi++) {
#pragma unroll
        for (int e = 0; e < 2; e++) {
            size_t r = m0 + wm * 32 + mi * 16 + (lane >> 2) + e * 8;
            if (r >= (size_t)M) continue;
#pragma unroll
            for (int j = 0; j < 8; j++) {
                int n = wn * 64 + j * 8 + (lane & 3) * 2;
                float2 hi = __bfloat1622float2(
                    *reinterpret_cast<const __nv_bfloat162*>(d_hhi + r * MEMD + n));
                float2 lo = __bfloat1622float2(
                    *reinterpret_cast<const __nv_bfloat162*>(d_hlo + r * MEMD + n));
                float g0 = tanh_fast(acc[mi][j][e * 2 + 0] + d_bfin[n]);
                float g1 = tanh_fast(acc[mi][j][e * 2 + 1] + d_bfin[n + 1]);
                float v0 = tanhf(hi.x + lo.x + EPS * g0);
                float v1 = tanhf(hi.y + lo.y + EPS * g1);
                *reinterpret_cast<float2*>(Cout + r * MEMD + n) = make_float2(v0, v1);
            }
        }
    }
}

// ---------------- edge pass: alpha -> exp -> single fp16 vector scatter --------
// lane i owns elements [8i,8i+8) of the 256-wide [h | msg | timefeat] row.
// alpha = qq[dst].row; scatter ex*row as one red.v4.f16x2; ex scaled 2^-4
// (cancels in agg/denom). Per-dst scalar alpha terms cancel in softmax.
__global__ void edge_kernel(const int* __restrict__ src, const int* __restrict__ dst,
                            const float* __restrict__ msg,
                            const float* __restrict__ lu, const float* __restrict__ tar,
                            const float* __restrict__ wt, const float* __restrict__ bt,
                            int E) {
    int w = (int)(((size_t)blockIdx.x * blockDim.x + threadIdx.x) >> 5);
    int lane = threadIdx.x & 31;
    if (w >= E) return;
    int s = src[w], d = dst[w];
    uint4 qq4 = *reinterpret_cast<const uint4*>(d_qqb + (size_t)d * 256 + lane * 8);
    float q[8];
    {
        const __nv_bfloat162* qp = reinterpret_cast<const __nv_bfloat162*>(&qq4);
#pragma unroll
        for (int k = 0; k < 4; k++) {
            float2 f = __bfloat1622float2(qp[k]);
            q[2 * k] = f.x;
            q[2 * k + 1] = f.y;
        }
    }
    float o[8];
    if (lane < 16) {
        uint4 h4 = *reinterpret_cast<const uint4*>(d_hhi + (size_t)s * MEMD + lane * 8);
        const __nv_bfloat162* hp = reinterpret_cast<const __nv_bfloat162*>(&h4);
#pragma unroll
        for (int k = 0; k < 4; k++) {
            float2 f = __bfloat1622float2(hp[k]);
            o[2 * k] = f.x;
            o[2 * k + 1] = f.y;
        }
    } else if (lane < 24) {
        const float4* mp =
            reinterpret_cast<const float4*>(msg + (size_t)w * 64 + (lane - 16) * 8);
        float4 a = mp[0], b = mp[1];
        o[0] = a.x; o[1] = a.y; o[2] = a.z; o[3] = a.w;
        o[4] = b.x; o[5] = b.y; o[6] = b.z; o[7] = b.w;
    } else {
        float rel = fabsf(lu[s] - tar[w]);
        int j = (lane - 24) * 8;
#pragma unroll
        for (int k = 0; k < 8; k++)
            o[k] = __cosf(fmaf(rel, wt[j + k], bt[j + k]));
    }
    float p = 0.0f;
#pragma unroll
    for (int k = 0; k < 8; k++) p += q[k] * o[k];
#pragma unroll
    for (int off = 16; off; off >>= 1) p += __shfl_xor_sync(0xFFFFFFFFu, p, off);
    float ex = __expf(p * 0.08838834764831845f) * 0.0625f;  // 1/sqrt(128); 2^-4 scale
    __half2 p0 = __floats2half2_rn(ex * o[0], ex * o[1]);
    __half2 p1 = __floats2half2_rn(ex * o[2], ex * o[3]);
    __half2 p2 = __floats2half2_rn(ex * o[4], ex * o[5]);
    __half2 p3 = __floats2half2_rn(ex * o[6], ex * o[7]);
    __half* pa = d_aggh + (size_t)d * 256 + lane * 8;
    asm volatile("red.global.add.noftz.v4.f16x2 [%0], {%1,%2,%3,%4};"
                 :: "l"(pa), "r"(*reinterpret_cast<unsigned*>(&p0)),
                    "r"(*reinterpret_cast<unsigned*>(&p1)),
                    "r"(*reinterpret_cast<unsigned*>(&p2)),
                    "r"(*reinterpret_cast<unsigned*>(&p3))
                 : "memory");
    if (lane == 0) atomicAdd(&d_denom[d], ex);
}

// ---------------- launch ----------------
extern "C" void kernel_launch(void* const* d_in, const int* in_sizes, int n_in,
                              void* d_out, int out_size) {
    const float* x           = (const float*)d_in[0];
    const float* last_update = (const float*)d_in[1];
    const int*   edge_index  = (const int*)d_in[2];
    const float* t           = (const float*)d_in[3];
    const float* msg         = (const float*)d_in[4];
    const float* w_time      = (const float*)d_in[5];
    const float* b_time      = (const float*)d_in[6];
    const float* W_enc       = (const float*)d_in[7];
    const float* b_enc       = (const float*)d_in[8];
    const float* Wq          = (const float*)d_in[9];
    const float* bq          = (const float*)d_in[10];
    const float* Wk          = (const float*)d_in[11];
    const float* bk          = (const float*)d_in[12];
    const float* Wv          = (const float*)d_in[13];
    const float* bv          = (const float*)d_in[14];
    const float* We          = (const float*)d_in[15];
    const float* W_anti      = (const float*)d_in[16];
    const float* b_anti      = (const float*)d_in[17];

    int Nn = in_sizes[1];
    int Ei = in_sizes[3];
    const int* src = edge_index;
    const int* dst = edge_index + Ei;

    __nv_bfloat16 *whi_p, *wlo_p;
    cudaGetSymbolAddress((void**)&whi_p, d_whi);
    cudaGetSymbolAddress((void**)&wlo_p, d_wlo);

    cudaFuncSetAttribute(enc_qq_kernel, cudaFuncAttributeMaxDynamicSharedMemorySize,
                         SMEM_BYTES);
    cudaFuncSetAttribute(final_gemm, cudaFuncAttributeMaxDynamicSharedMemorySize,
                         SMEM_BYTES);

    int nblk = (Nn + 127) / 128;

    // prep + init merged (grid covers the larger init range)
    prep_kernel<<<(int)(((size_t)Nn * 128 + 255) / 256), 256>>>(
        W_enc, Wq, bq, Wk, bk, Wv, bv, We, W_anti, b_anti, Nn);
    // fused enc + qq
    enc_qq_kernel<<<dim3(1, nblk), 256, SMEM_BYTES>>>(x, Nn, whi_p, wlo_p, b_enc);
    // edge pass: alpha/exp/fp16 vector scatter
    edge_kernel<<<(Ei + 7) / 8, 256>>>(src, dst, msg, last_update, t, w_time, b_time, Ei);
    // final fused CTAN GEMM
    final_gemm<<<dim3(1, nblk), 256, SMEM_BYTES>>>(Nn, whi_p, wlo_p, (float*)d_out);
}

// round 17
// speedup vs baseline: 3.3326x; 1.1061x over previous
#include <cuda_runtime.h>
#include <cuda_bf16.h>
#include <cuda_fp16.h>
#include <math.h>
#include <stdint.h>

#define NN_MAX 100000
#define EE_MAX 500000
#define MEMD 128
#define EPS 0.1f
#define GAM 0.1f

// weight-cat offsets (elements) in the bf16 hi/lo weight store, all [N,K] K-major
#define OFF_ENC 0          // [128,256]  W_enc
#define OFF_QQ 32768       // [256,128]  [M1|M2]: qk' rows 0..127, qW rows 128..255
#define OFF_FIN 65536      // [128,384]  [Aanti | Wv | We]  (bf16 hi/lo; h-chunk part used)
#define W_TOTAL 114688

#define LDT 72                          // padded SMEM row pitch in bf16 (144B)
#define TILE_ELEMS (128 * LDT)          // per buffer
#define SMEM_BYTES (4 * TILE_ELEMS * 2) // Ahi, Alo, Bhi, Blo = 73728 B

// ---------------- scratch (__device__ globals) ----------------
__device__ __nv_bfloat16 d_hhi[(size_t)NN_MAX * MEMD];
__device__ __nv_bfloat16 d_hlo[(size_t)NN_MAX * MEMD];
__device__ __nv_bfloat16 d_qqb[(size_t)NN_MAX * 256];   // [qk' | qW] bf16
__device__ float d_denom[NN_MAX];
__device__ __half d_aggh[(size_t)NN_MAX * 256];         // [sum w*h | sum w*attr] fp16
__device__ __nv_bfloat16 d_whi[W_TOTAL];
__device__ __nv_bfloat16 d_wlo[W_TOTAL];
__device__ __half d_wf16[128 * 256];                    // [Wv|We] f16, [n][k] K-major
__device__ float d_bqq[256];                            // [c1|c2]
__device__ float d_bfin[128];                           // b_anti + bv

// ---------------- PTX helpers --------------------------------------------------
__device__ __forceinline__ uint32_t smem_u32(const void* p) {
    uint32_t a;
    asm("{ .reg .u64 t; cvta.to.shared.u64 t, %1; cvt.u32.u64 %0, t; }" : "=r"(a) : "l"(p));
    return a;
}
__device__ __forceinline__ void ldm_x4(uint32_t* r, uint32_t addr) {
    asm volatile("ldmatrix.sync.aligned.m8n8.x4.shared.b16 {%0,%1,%2,%3}, [%4];"
                 : "=r"(r[0]), "=r"(r[1]), "=r"(r[2]), "=r"(r[3]) : "r"(addr));
}
__device__ __forceinline__ void mma_bf16(float* c, const uint32_t* a, const uint32_t* b) {
    asm volatile(
        "mma.sync.aligned.m16n8k16.row.col.f32.bf16.bf16.f32 "
        "{%0,%1,%2,%3}, {%4,%5,%6,%7}, {%8,%9}, {%0,%1,%2,%3};"
        : "+f"(c[0]), "+f"(c[1]), "+f"(c[2]), "+f"(c[3])
        : "r"(a[0]), "r"(a[1]), "r"(a[2]), "r"(a[3]), "r"(b[0]), "r"(b[1]));
}
__device__ __forceinline__ void mma_f16(float* c, const uint32_t* a, const uint32_t* b) {
    asm volatile(
        "mma.sync.aligned.m16n8k16.row.col.f32.f16.f16.f32 "
        "{%0,%1,%2,%3}, {%4,%5,%6,%7}, {%8,%9}, {%0,%1,%2,%3};"
        : "+f"(c[0]), "+f"(c[1]), "+f"(c[2]), "+f"(c[3])
        : "r"(a[0]), "r"(a[1]), "r"(a[2]), "r"(a[3]), "r"(b[0]), "r"(b[1]));
}
__device__ __forceinline__ void cp16(uint32_t saddr, const void* gaddr) {
    asm volatile("cp.async.ca.shared.global [%0], [%1], 16;" :: "r"(saddr), "l"(gaddr));
}
__device__ __forceinline__ void cp16z(uint32_t saddr, const void* gaddr, int srcsz) {
    asm volatile("cp.async.ca.shared.global [%0], [%1], 16, %2;"
                 :: "r"(saddr), "l"(gaddr), "r"(srcsz));
}
__device__ __forceinline__ void cp_commit_wait() {
    asm volatile("cp.async.commit_group;");
    asm volatile("cp.async.wait_group 0;");
}
__device__ __forceinline__ float tanh_fast(float x) {
    float r;
    asm("tanh.approx.f32 %0, %1;" : "=f"(r) : "f"(x));
    return r;
}

// ---------------- weight prep + per-call accumulator init (merged) -------------
__device__ __forceinline__ void split_store(int idx, float v) {
    __nv_bfloat16 hi = __float2bfloat16(v);
    __nv_bfloat16 lo = __float2bfloat16(v - __bfloat162float(hi));
    d_whi[idx] = hi;
    d_wlo[idx] = lo;
}
__global__ void prep_kernel(const float* __restrict__ W_enc,
                            const float* __restrict__ Wq, const float* __restrict__ bq,
                            const float* __restrict__ Wk, const float* __restrict__ bk,
                            const float* __restrict__ Wv, const float* __restrict__ bv,
                            const float* __restrict__ We, const float* __restrict__ W_anti,
                            const float* __restrict__ b_anti, int n_nodes) {
    size_t i = (size_t)blockIdx.x * blockDim.x + threadIdx.x;
    // per-call accumulator init
    if (i < (size_t)n_nodes * 128)
        reinterpret_cast<unsigned*>(d_aggh)[i] = 0u;      // 256 halves per node
    if (i < (size_t)n_nodes) d_denom[i] = 0.0f;
    // weight composition (graph replays recompute; deterministic)
    if (i < 32768) {
        split_store(OFF_ENC + (int)i, W_enc[i]);          // [128,256] direct
    } else if (i < 65536) {
        int j = (int)i - 32768;
        int jo = j / 128, k = j % 128;                    // out col jo, K index k
        float s = 0.0f;
        if (jo < 128) {
            for (int m = 0; m < 128; m++) s += Wk[m * 128 + jo] * Wq[m * 128 + k];
        } else {
            int j2 = jo - 128;
            for (int m = 0; m < 128; m++) s += We[m * 128 + j2] * Wq[m * 128 + k];
        }
        split_store(OFF_QQ + j, s);
    } else if (i < 114688) {
        int j = (int)i - 65536;
        int jo = j / 384, k = j % 384;
        float v;
        if (k < 128) {
            v = W_anti[jo * 128 + k] - W_anti[k * 128 + jo];
            if (jo == k) v -= GAM;
        } else if (k < 256) {
            v = Wv[jo * 128 + (k - 128)];
        } else {
            v = We[jo * 128 + (k - 256)];
        }
        split_store(OFF_FIN + j, v);
    } else if (i < 114944) {
        int j = (int)i - 114688;                          // c1|c2
        float s = 0.0f;
        if (j < 128) {
            for (int m = 0; m < 128; m++) s += bq[m] * Wk[m * 128 + j];
        } else {
            int j2 = j - 128;
            for (int m = 0; m < 128; m++) s += bq[m] * We[m * 128 + j2];
        }
        d_bqq[j] = s;
    } else if (i < 115072) {
        int j = (int)i - 114944;
        d_bfin[j] = b_anti[j] + bv[j];
    } else if (i < 147840) {
        int j = (int)i - 115072;                          // [Wv|We] f16 copy
        int n = j / 256, k = j % 256;
        float v = (k < 128) ? Wv[n * 128 + k] : We[n * 128 + (k - 128)];
        d_wf16[j] = __float2half(v);
    }
    // per-dst scalar alpha terms cancel in segment softmax - dropped.
}

// ---------------- fused enc + qq kernel ----------------------------------------
// Phase 1: h = x @ W_enc^T + b_enc (K=256, 3-MMA hi/lo). Writes hhi/hlo to gmem
//          and stages h-hi into the A smem buffers.
// Phase 2: qq = h @ [M1|M2]^T + [c1|c2] (K=128, 2-MMA, A-hi from smem),
//          two 128-col output halves sequentially, acc reused. bf16 out to qqb.
__global__ void __launch_bounds__(256, 2) enc_qq_kernel(
    const float* __restrict__ x, int M,
    const __nv_bfloat16* __restrict__ Wh, const __nv_bfloat16* __restrict__ Wl,
    const float* __restrict__ b_enc) {
    const int t = threadIdx.x;
    const int lane = t & 31, wid = t >> 5;
    const int wm = wid & 3, wn = wid >> 2;
    const size_t m0 = (size_t)blockIdx.y * 128;

    extern __shared__ __nv_bfloat16 smem[];
    uint32_t sbase = smem_u32(smem);
    const uint32_t oAhi = 0;
    const uint32_t oAlo = TILE_ELEMS * 2;
    const uint32_t oBhi = 2 * TILE_ELEMS * 2;
    const uint32_t oBlo = 3 * TILE_ELEMS * 2;

    float acc[2][8][4];
#pragma unroll
    for (int i = 0; i < 2; i++)
#pragma unroll
        for (int j = 0; j < 8; j++)
#pragma unroll
            for (int e = 0; e < 4; e++) acc[i][j][e] = 0.0f;

    const int tr = t >> 1;
    const int tcc = (t & 1) * 32;
    const size_t row = m0 + tr;
    const bool valid = row < (size_t)M;

    // ---- Phase 1 mainloop: K=256, 4 chunks ----
    const __nv_bfloat16* Bhp = Wh + OFF_ENC;   // [128,256]
    const __nv_bfloat16* Blp = Wl + OFF_ENC;
    for (int c = 0; c < 4; c++) {
        const int kc = c * 64;
        {
            const __nv_bfloat16* bh = Bhp + (size_t)tr * 256 + kc + tcc;
            const __nv_bfloat16* bl = Blp + (size_t)tr * 256 + kc + tcc;
#pragma unroll
            for (int g = 0; g < 4; g++) {
                uint32_t so = (tr * LDT + tcc + g * 8) * 2;
                cp16(sbase + oBhi + so, bh + g * 8);
                cp16(sbase + oBlo + so, bl + g * 8);
            }
        }
#pragma unroll
        for (int g = 0; g < 8; g++) {
            float4 v = make_float4(0.f, 0.f, 0.f, 0.f);
            if (valid)
                v = *reinterpret_cast<const float4*>(x + row * 256 + kc + tcc + g * 4);
            __nv_bfloat162 h0 = __floats2bfloat162_rn(v.x, v.y);
            __nv_bfloat162 h1 = __floats2bfloat162_rn(v.z, v.w);
            float2 f0 = __bfloat1622float2(h0);
            float2 f1 = __bfloat1622float2(h1);
            __nv_bfloat162 l0 = __floats2bfloat162_rn(v.x - f0.x, v.y - f0.y);
            __nv_bfloat162 l1 = __floats2bfloat162_rn(v.z - f1.x, v.w - f1.y);
            int idx = tr * LDT + tcc + g * 4;
            *reinterpret_cast<uint2*>(smem + idx) = make_uint2(
                *reinterpret_cast<unsigned*>(&h0), *reinterpret_cast<unsigned*>(&h1));
            *reinterpret_cast<uint2*>(smem + TILE_ELEMS + idx) = make_uint2(
                *reinterpret_cast<unsigned*>(&l0), *reinterpret_cast<unsigned*>(&l1));
        }
        cp_commit_wait();
        __syncthreads();
#pragma unroll
        for (int ks = 0; ks < 4; ks++) {
            const int k0 = ks * 16;
            uint32_t ah[2][4], al[2][4];
#pragma unroll
            for (int mi = 0; mi < 2; mi++) {
                uint32_t ao =
                    ((wm * 32 + mi * 16 + (lane & 15)) * LDT + k0 + ((lane >> 4) << 3)) * 2;
                ldm_x4(ah[mi], sbase + oAhi + ao);
                ldm_x4(al[mi], sbase + oAlo + ao);
            }
            uint32_t bhf[4][4], blf[4][4];
#pragma unroll
            for (int nj = 0; nj < 4; nj++) {
                int bn = wn * 64 + nj * 16 + (lane & 7) + ((lane >> 4) << 3);
                uint32_t bo = (bn * LDT + k0 + (((lane >> 3) & 1) << 3)) * 2;
                ldm_x4(bhf[nj], sbase + oBhi + bo);
                ldm_x4(blf[nj], sbase + oBlo + bo);
            }
#pragma unroll
            for (int mi = 0; mi < 2; mi++)
#pragma unroll
                for (int j = 0; j < 8; j++) {
                    const uint32_t* bh2 = &bhf[j >> 1][(j & 1) * 2];
                    const uint32_t* bl2 = &blf[j >> 1][(j & 1) * 2];
                    mma_bf16(acc[mi][j], ah[mi], bh2);
                    mma_bf16(acc[mi][j], ah[mi], bl2);
                    mma_bf16(acc[mi][j], al[mi], bh2);
                }
        }
        __syncthreads();
    }

    // ---- Phase 1 epilogue: h -> gmem hi/lo, h-hi -> A smem buffers ----
    // h cols [0,64) -> oAhi buffer, cols [64,128) -> oAlo buffer (qq K staging).
#pragma unroll
    for (int mi = 0; mi < 2; mi++) {
#pragma unroll
        for (int e = 0; e < 2; e++) {
            int rl = wm * 32 + mi * 16 + (lane >> 2) + e * 8;
            size_t r = m0 + rl;
#pragma unroll
            for (int j = 0; j < 8; j++) {
                int n = wn * 64 + j * 8 + (lane & 3) * 2;
                float v0 = acc[mi][j][e * 2 + 0] + b_enc[n];
                float v1 = acc[mi][j][e * 2 + 1] + b_enc[n + 1];
                __nv_bfloat162 hi2 = __floats2bfloat162_rn(v0, v1);
                float2 hf = __bfloat1622float2(hi2);
                __nv_bfloat162 lo2 = __floats2bfloat162_rn(v0 - hf.x, v1 - hf.y);
                if (r < (size_t)M) {
                    *reinterpret_cast<unsigned*>(d_hhi + r * MEMD + n) =
                        *reinterpret_cast<unsigned*>(&hi2);
                    *reinterpret_cast<unsigned*>(d_hlo + r * MEMD + n) =
                        *reinterpret_cast<unsigned*>(&lo2);
                }
                int idx = wn * TILE_ELEMS + rl * LDT + (n - wn * 64);
                *reinterpret_cast<unsigned*>(smem + idx) = *reinterpret_cast<unsigned*>(&hi2);
            }
        }
    }
    __syncthreads();

    // ---- Phase 2: qq, two output col-halves, K=128 (A-hi in smem) ----
    for (int ch = 0; ch < 2; ch++) {
        const int colq = ch * 128;
        const __nv_bfloat16* Bqh = Wh + OFF_QQ + (size_t)colq * 128;
        const __nv_bfloat16* Bql = Wl + OFF_QQ + (size_t)colq * 128;
#pragma unroll
        for (int i = 0; i < 2; i++)
#pragma unroll
            for (int j = 0; j < 8; j++)
#pragma unroll
                for (int e = 0; e < 4; e++) acc[i][j][e] = 0.0f;
        for (int c = 0; c < 2; c++) {
            const int kc = c * 64;
            {
                const __nv_bfloat16* bh = Bqh + (size_t)tr * 128 + kc + tcc;
                const __nv_bfloat16* bl = Bql + (size_t)tr * 128 + kc + tcc;
#pragma unroll
                for (int g = 0; g < 4; g++) {
                    uint32_t so = (tr * LDT + tcc + g * 8) * 2;
                    cp16(sbase + oBhi + so, bh + g * 8);
                    cp16(sbase + oBlo + so, bl + g * 8);
                }
            }
            cp_commit_wait();
            __syncthreads();
            const uint32_t oA = (c == 0) ? oAhi : oAlo;
#pragma unroll
            for (int ks = 0; ks < 4; ks++) {
                const int k0 = ks * 16;
                uint32_t ah[2][4];
#pragma unroll
                for (int mi = 0; mi < 2; mi++) {
                    uint32_t ao =
                        ((wm * 32 + mi * 16 + (lane & 15)) * LDT + k0 + ((lane >> 4) << 3)) * 2;
                    ldm_x4(ah[mi], sbase + oA + ao);
                }
                uint32_t bhf[4][4], blf[4][4];
#pragma unroll
                for (int nj = 0; nj < 4; nj++) {
                    int bn = wn * 64 + nj * 16 + (lane & 7) + ((lane >> 4) << 3);
                    uint32_t bo = (bn * LDT + k0 + (((lane >> 3) & 1) << 3)) * 2;
                    ldm_x4(bhf[nj], sbase + oBhi + bo);
                    ldm_x4(blf[nj], sbase + oBlo + bo);
                }
#pragma unroll
                for (int mi = 0; mi < 2; mi++)
#pragma unroll
                    for (int j = 0; j < 8; j++) {
                        mma_bf16(acc[mi][j], ah[mi], &bhf[j >> 1][(j & 1) * 2]);
                        mma_bf16(acc[mi][j], ah[mi], &blf[j >> 1][(j & 1) * 2]);
                    }
            }
            __syncthreads();
        }
        // qq epilogue: bf16 out
#pragma unroll
        for (int mi = 0; mi < 2; mi++) {
#pragma unroll
            for (int e = 0; e < 2; e++) {
                size_t r = m0 + wm * 32 + mi * 16 + (lane >> 2) + e * 8;
                if (r >= (size_t)M) continue;
#pragma unroll
                for (int j = 0; j < 8; j++) {
                    int n = wn * 64 + j * 8 + (lane & 3) * 2;
                    float v0 = acc[mi][j][e * 2 + 0] + d_bqq[colq + n];
                    float v1 = acc[mi][j][e * 2 + 1] + d_bqq[colq + n + 1];
                    __nv_bfloat162 hi2 = __floats2bfloat162_rn(v0, v1);
                    *reinterpret_cast<unsigned*>(d_qqb + r * 256 + colq + n) =
                        *reinterpret_cast<unsigned*>(&hi2);
                }
            }
        }
    }
}

// ---------------- final GEMM: out = tanh(h + eps*tanh(D + bfin)) ---------------
// D = rden*(agg@[Wv|We]^T) + h@Aanti^T.
// Phase A: 4 agg chunks, fp16 A direct cp.async + f16 weights, 1 MMA/frag.
// Then acc *= rden[r] (per-row scalar; exact by linearity).
// Phase B: 2 h chunks, bf16 hi/lo 3-MMA.
__global__ void __launch_bounds__(256, 2) final_gemm(
    int M, const __nv_bfloat16* __restrict__ Wh, const __nv_bfloat16* __restrict__ Wl,
    float* __restrict__ Cout) {
    const int t = threadIdx.x;
    const int lane = t & 31, wid = t >> 5;
    const int wm = wid & 3, wn = wid >> 2;
    const size_t m0 = (size_t)blockIdx.y * 128;

    extern __shared__ __nv_bfloat16 smem[];
    uint32_t sbase = smem_u32(smem);
    const uint32_t oAhi = 0;
    const uint32_t oAlo = TILE_ELEMS * 2;
    const uint32_t oBhi = 2 * TILE_ELEMS * 2;
    const uint32_t oBlo = 3 * TILE_ELEMS * 2;

    float acc[2][8][4];
#pragma unroll
    for (int i = 0; i < 2; i++)
#pragma unroll
        for (int j = 0; j < 8; j++)
#pragma unroll
            for (int e = 0; e < 4; e++) acc[i][j][e] = 0.0f;

    const int tr = t >> 1;
    const int tcc = (t & 1) * 32;
    const size_t row = m0 + tr;
    const bool valid = row < (size_t)M;

    // ---- Phase A: agg chunks (unnormalized), f16 x f16 ----
    for (int c = 0; c < 4; c++) {
        const int kc = c * 64;
        {
            const __half* bw = d_wf16 + (size_t)tr * 256 + kc + tcc;
#pragma unroll
            for (int g = 0; g < 4; g++) {
                uint32_t so = (tr * LDT + tcc + g * 8) * 2;
                cp16(sbase + oBhi + so, bw + g * 8);
            }
        }
        {
            const __half* ag = d_aggh + row * 256 + kc + tcc;
            int sz = valid ? 16 : 0;
#pragma unroll
            for (int g = 0; g < 4; g++) {
                uint32_t so = (tr * LDT + tcc + g * 8) * 2;
                cp16z(sbase + oAhi + so, ag + g * 8, sz);
            }
        }
        cp_commit_wait();
        __syncthreads();
#pragma unroll
        for (int ks = 0; ks < 4; ks++) {
            const int k0 = ks * 16;
            uint32_t ah[2][4];
#pragma unroll
            for (int mi = 0; mi < 2; mi++) {
                uint32_t ao =
                    ((wm * 32 + mi * 16 + (lane & 15)) * LDT + k0 + ((lane >> 4) << 3)) * 2;
                ldm_x4(ah[mi], sbase + oAhi + ao);
            }
            uint32_t bhf[4][4];
#pragma unroll
            for (int nj = 0; nj < 4; nj++) {
                int bn = wn * 64 + nj * 16 + (lane & 7) + ((lane >> 4) << 3);
                uint32_t bo = (bn * LDT + k0 + (((lane >> 3) & 1) << 3)) * 2;
                ldm_x4(bhf[nj], sbase + oBhi + bo);
            }
#pragma unroll
            for (int mi = 0; mi < 2; mi++)
#pragma unroll
                for (int j = 0; j < 8; j++)
                    mma_f16(acc[mi][j], ah[mi], &bhf[j >> 1][(j & 1) * 2]);
        }
        __syncthreads();
    }

    // ---- scale by per-row 1/denom (linearity; exact) ----
#pragma unroll
    for (int mi = 0; mi < 2; mi++) {
#pragma unroll
        for (int e = 0; e < 2; e++) {
            size_t r = m0 + wm * 32 + mi * 16 + (lane >> 2) + e * 8;
            float rd = 0.0f;
            if (r < (size_t)M) rd = 1.0f / (d_denom[r] + 1e-16f);
#pragma unroll
            for (int j = 0; j < 8; j++) {
                acc[mi][j][e * 2 + 0] *= rd;
                acc[mi][j][e * 2 + 1] *= rd;
            }
        }
    }

    // ---- Phase B: h chunks, bf16 hi/lo 3-MMA ----
    const __nv_bfloat16* Bhp = Wh + OFF_FIN;   // [128,384]; K 0..127 = Aanti
    const __nv_bfloat16* Blp = Wl + OFF_FIN;
    for (int c = 0; c < 2; c++) {
        const int kc = c * 64;
        {
            const __nv_bfloat16* bh = Bhp + (size_t)tr * 384 + kc + tcc;
            const __nv_bfloat16* bl = Blp + (size_t)tr * 384 + kc + tcc;
#pragma unroll
            for (int g = 0; g < 4; g++) {
                uint32_t so = (tr * LDT + tcc + g * 8) * 2;
                cp16(sbase + oBhi + so, bh + g * 8);
                cp16(sbase + oBlo + so, bl + g * 8);
            }
        }
        {
            const __nv_bfloat16* ah = d_hhi + row * 128 + kc + tcc;
            const __nv_bfloat16* al = d_hlo + row * 128 + kc + tcc;
            int sz = valid ? 16 : 0;
#pragma unroll
            for (int g = 0; g < 4; g++) {
                uint32_t so = (tr * LDT + tcc + g * 8) * 2;
                cp16z(sbase + oAhi + so, ah + g * 8, sz);
                cp16z(sbase + oAlo + so, al + g * 8, sz);
            }
        }
        cp_commit_wait();
        __syncthreads();
#pragma unroll
        for (int ks = 0; ks < 4; ks++) {
            const int k0 = ks * 16;
            uint32_t ah[2][4], al[2][4];
#pragma unroll
            for (int mi = 0; mi < 2; mi++) {
                uint32_t ao =
                    ((wm * 32 + mi * 16 + (lane & 15)) * LDT + k0 + ((lane >> 4) << 3)) * 2;
                ldm_x4(ah[mi], sbase + oAhi + ao);
                ldm_x4(al[mi], sbase + oAlo + ao);
            }
            uint32_t bhf[4][4], blf[4][4];
#pragma unroll
            for (int nj = 0; nj < 4; nj++) {
                int bn = wn * 64 + nj * 16 + (lane & 7) + ((lane >> 4) << 3);
                uint32_t bo = (bn * LDT + k0 + (((lane >> 3) & 1) << 3)) * 2;
                ldm_x4(bhf[nj], sbase + oBhi + bo);
                ldm_x4(blf[nj], sbase + oBlo + bo);
            }
#pragma unroll
            for (int mi = 0; mi < 2; mi++)
#pragma unroll
                for (int j = 0; j < 8; j++) {
                    const uint32_t* bh2 = &bhf[j >> 1][(j & 1) * 2];
                    const uint32_t* bl2 = &blf[j >> 1][(j & 1) * 2];
                    mma_bf16(acc[mi][j], ah[mi], bh2);
                    mma_bf16(acc[mi][j], ah[mi], bl2);
                    mma_bf16(acc[mi][j], al[mi], bh2);
                }
        }
        __syncthreads();
    }

    // ---- CTAN epilogue ----
#pragma unroll
    for (int mi = 0; mi < 2; mi++) {
#pragma unroll
        for (int e = 0; e < 2; e++) {
            size_t r = m0 + wm * 32 + mi * 16 + (lane >> 2) + e * 8;
            if (r >= (size_t)M) continue;
#pragma unroll
            for (int j = 0; j < 8; j++) {
                int n = wn * 64 + j * 8 + (lane & 3) * 2;
                float2 hi = __bfloat1622float2(
                    *reinterpret_cast<const __nv_bfloat162*>(d_hhi + r * MEMD + n));
                float2 lo = __bfloat1622float2(
                    *reinterpret_cast<const __nv_bfloat162*>(d_hlo + r * MEMD + n));
                float g0 = tanh_fast(acc[mi][j][e * 2 + 0] + d_bfin[n]);
                float g1 = tanh_fast(acc[mi][j][e * 2 + 1] + d_bfin[n + 1]);
                float v0 = tanhf(hi.x + lo.x + EPS * g0);
                float v1 = tanhf(hi.y + lo.y + EPS * g1);
                *reinterpret_cast<float2*>(Cout + r * MEMD + n) = make_float2(v0, v1);
            }
        }
    }
}

// ---------------- edge pass: alpha -> exp -> single fp16 vector scatter --------
// lane i owns elements [8i,8i+8) of the 256-wide [h | msg | timefeat] row.
// alpha = qq[dst].row; scatter ex*row as one red.v4.f16x2; ex scaled 2^-4
// (cancels in agg/denom). Per-dst scalar alpha terms cancel in softmax.
__global__ void edge_kernel(const int* __restrict__ src, const int* __restrict__ dst,
                            const float* __restrict__ msg,
                            const float* __restrict__ lu, const float* __restrict__ tar,
                            const float* __restrict__ wt, const float* __restrict__ bt,
                            int E) {
    int w = (int)(((size_t)blockIdx.x * blockDim.x + threadIdx.x) >> 5);
    int lane = threadIdx.x & 31;
    if (w >= E) return;
    int s = src[w], d = dst[w];
    uint4 qq4 = *reinterpret_cast<const uint4*>(d_qqb + (size_t)d * 256 + lane * 8);
    float q[8];
    {
        const __nv_bfloat162* qp = reinterpret_cast<const __nv_bfloat162*>(&qq4);
#pragma unroll
        for (int k = 0; k < 4; k++) {
            float2 f = __bfloat1622float2(qp[k]);
            q[2 * k] = f.x;
            q[2 * k + 1] = f.y;
        }
    }
    float o[8];
    if (lane < 16) {
        uint4 h4 = *reinterpret_cast<const uint4*>(d_hhi + (size_t)s * MEMD + lane * 8);
        const __nv_bfloat162* hp = reinterpret_cast<const __nv_bfloat162*>(&h4);
#pragma unroll
        for (int k = 0; k < 4; k++) {
            float2 f = __bfloat1622float2(hp[k]);
            o[2 * k] = f.x;
            o[2 * k + 1] = f.y;
        }
    } else if (lane < 24) {
        const float4* mp =
            reinterpret_cast<const float4*>(msg + (size_t)w * 64 + (lane - 16) * 8);
        float4 a = mp[0], b = mp[1];
        o[0] = a.x; o[1] = a.y; o[2] = a.z; o[3] = a.w;
        o[4] = b.x; o[5] = b.y; o[6] = b.z; o[7] = b.w;
    } else {
        float rel = fabsf(lu[s] - tar[w]);
        int j = (lane - 24) * 8;
#pragma unroll
        for (int k = 0; k < 8; k++)
            o[k] = __cosf(fmaf(rel, wt[j + k], bt[j + k]));
    }
    float p = 0.0f;
#pragma unroll
    for (int k = 0; k < 8; k++) p += q[k] * o[k];
#pragma unroll
    for (int off = 16; off; off >>= 1) p += __shfl_xor_sync(0xFFFFFFFFu, p, off);
    float ex = __expf(p * 0.08838834764831845f) * 0.0625f;  // 1/sqrt(128); 2^-4 scale
    __half2 p0 = __floats2half2_rn(ex * o[0], ex * o[1]);
    __half2 p1 = __floats2half2_rn(ex * o[2], ex * o[3]);
    __half2 p2 = __floats2half2_rn(ex * o[4], ex * o[5]);
    __half2 p3 = __floats2half2_rn(ex * o[6], ex * o[7]);
    __half* pa = d_aggh + (size_t)d * 256 + lane * 8;
    asm volatile("red.global.add.noftz.v4.f16x2 [%0], {%1,%2,%3,%4};"
                 :: "l"(pa), "r"(*reinterpret_cast<unsigned*>(&p0)),
                    "r"(*reinterpret_cast<unsigned*>(&p1)),
                    "r"(*reinterpret_cast<unsigned*>(&p2)),
                    "r"(*reinterpret_cast<unsigned*>(&p3))
                 : "memory");
    if (lane == 0) atomicAdd(&d_denom[d], ex);
}

// ---------------- launch ----------------
extern "C" void kernel_launch(void* const* d_in, const int* in_sizes, int n_in,
                              void* d_out, int out_size) {
    const float* x           = (const float*)d_in[0];
    const float* last_update = (const float*)d_in[1];
    const int*   edge_index  = (const int*)d_in[2];
    const float* t           = (const float*)d_in[3];
    const float* msg         = (const float*)d_in[4];
    const float* w_time      = (const float*)d_in[5];
    const float* b_time      = (const float*)d_in[6];
    const float* W_enc       = (const float*)d_in[7];
    const float* b_enc       = (const float*)d_in[8];
    const float* Wq          = (const float*)d_in[9];
    const float* bq          = (const float*)d_in[10];
    const float* Wk          = (const float*)d_in[11];
    const float* bk          = (const float*)d_in[12];
    const float* Wv          = (const float*)d_in[13];
    const float* bv          = (const float*)d_in[14];
    const float* We          = (const float*)d_in[15];
    const float* W_anti      = (const float*)d_in[16];
    const float* b_anti      = (const float*)d_in[17];

    int Nn = in_sizes[1];
    int Ei = in_sizes[3];
    const int* src = edge_index;
    const int* dst = edge_index + Ei;

    __nv_bfloat16 *whi_p, *wlo_p;
    cudaGetSymbolAddress((void**)&whi_p, d_whi);
    cudaGetSymbolAddress((void**)&wlo_p, d_wlo);

    cudaFuncSetAttribute(enc_qq_kernel, cudaFuncAttributeMaxDynamicSharedMemorySize,
                         SMEM_BYTES);
    cudaFuncSetAttribute(final_gemm, cudaFuncAttributeMaxDynamicSharedMemorySize,
                         SMEM_BYTES);

    int nblk = (Nn + 127) / 128;

    // prep + init merged (grid covers the larger init range)
    prep_kernel<<<(int)(((size_t)Nn * 128 + 255) / 256), 256>>>(
        W_enc, Wq, bq, Wk, bk, Wv, bv, We, W_anti, b_anti, Nn);
    // fused enc + qq
    enc_qq_kernel<<<dim3(1, nblk), 256, SMEM_BYTES>>>(x, Nn, whi_p, wlo_p, b_enc);
    // edge pass: alpha/exp/fp16 vector scatter
    edge_kernel<<<(Ei + 7) / 8, 256>>>(src, dst, msg, last_update, t, w_time, b_time, Ei);
    // final fused CTAN GEMM (agg phase f16, deferred rden scaling)
    final_gemm<<<dim3(1, nblk), 256, SMEM_BYTES>>>(Nn, whi_p, wlo_p, (float*)d_out);
}